// round 1
// baseline (speedup 1.0000x reference)
#include <cuda_runtime.h>
#include <math.h>

#define Bn 4
#define Cc 256
#define C8 32
#define Hh 64
#define Ww 64
#define HW 4096

// ---------------- scratch (device globals; no allocation allowed) ----------------
__device__ float g_x  [Bn*Cc*HW];   // after 3x3 conv
__device__ float g_tmp[Bn*Cc*HW];   // depthwise horizontal intermediate
__device__ float g_sum[Bn*Cc*HW];   // x + x1 + x2 + x3
__device__ float g_t  [Bn*C8*HW];   // projected out1  [b, 32, hw]
__device__ float g_attn1[Bn*C8*C8];
__device__ float g_out2[Bn*C8*HW];
__device__ float g_out3[Bn*C8*HW];
__device__ float g_ts  [Bn*HW*C8];  // t transposed    [b, hw, 32]
__device__ float g_q2n [Bn*HW*C8];  // l2-normalized ts

// ---------------- 3x3 conv 256->256, pad 1 ----------------
// grid: (4 h-tiles, 64 co-groups of 4, 4 batch); block 256
// each thread: 4 co x 4 cols, one row. weights for the 4 co held in registers.
__global__ void __launch_bounds__(256) conv3x3_k(
    const float* __restrict__ x, const float* __restrict__ w,
    const float* __restrict__ bias)
{
    const int ht  = blockIdx.x;      // 16-row tile
    const int cog = blockIdx.y;      // group of 4 output channels
    const int b   = blockIdx.z;

    __shared__ float sIn[18*68];
    __shared__ float sW[36];

    const int tid = threadIdx.x;
    const int ty  = tid >> 4;        // 0..15  (output row within tile)
    const int tx  = tid & 15;        // cols tx*4 .. tx*4+3
    const int h0  = ht * 16;

    float acc[4][4];
#pragma unroll
    for (int o = 0; o < 4; o++) {
        float bv = bias[cog*4 + o];
#pragma unroll
        for (int j = 0; j < 4; j++) acc[o][j] = bv;
    }

    for (int ci = 0; ci < Cc; ci++) {
        const float* xin = x + ((size_t)(b*Cc + ci)) * HW;
        // stage 18 x 66 input tile (rows h0-1..h0+16, cols -1..64)
        for (int idx = tid; idx < 18*66; idx += 256) {
            int r = idx / 66, c = idx - r*66;
            int gh = h0 + r - 1, gw = c - 1;
            float v = 0.f;
            if (gh >= 0 && gh < Hh && gw >= 0 && gw < Ww) v = xin[gh*Ww + gw];
            sIn[r*68 + c] = v;
        }
        if (tid < 36) {
            int o = tid / 9, kk = tid - o*9;
            sW[tid] = w[((size_t)(cog*4 + o)*Cc + ci)*9 + kk];
        }
        __syncthreads();

        float wr[4][9];
#pragma unroll
        for (int o = 0; o < 4; o++)
#pragma unroll
            for (int kk = 0; kk < 9; kk++) wr[o][kk] = sW[o*9 + kk];

#pragma unroll
        for (int kh = 0; kh < 3; kh++) {
            float in6[6];
            const float* rp = &sIn[(ty + kh)*68 + tx*4];
#pragma unroll
            for (int m = 0; m < 6; m++) in6[m] = rp[m];
#pragma unroll
            for (int o = 0; o < 4; o++)
#pragma unroll
                for (int j = 0; j < 4; j++)
#pragma unroll
                    for (int kw = 0; kw < 3; kw++)
                        acc[o][j] += wr[o][kh*3 + kw] * in6[j + kw];
        }
        __syncthreads();
    }

#pragma unroll
    for (int o = 0; o < 4; o++)
#pragma unroll
        for (int j = 0; j < 4; j++)
            g_x[((size_t)(b*Cc + cog*4 + o))*HW + (h0 + ty)*Ww + tx*4 + j] = acc[o][j];
}

// ---------------- depthwise horizontal (1 x K), pad (0, PAD) ----------------
template<int K, int PAD>
__global__ void __launch_bounds__(256) dwh_k(
    const float* __restrict__ in, const float* __restrict__ wk,
    const float* __restrict__ bias, float* __restrict__ out)
{
    int idx = blockIdx.x * 256 + threadIdx.x;       // over Bn*Cc*HW
    int w = idx & (Ww - 1);
    int c = (idx >> 12) & (Cc - 1);
    const float* row = in + (idx - w);
    float s = bias[c];
#pragma unroll
    for (int k = 0; k < K; k++) {
        int ww = w + k - PAD;
        if (ww >= 0 && ww < Ww) s += row[ww] * wk[c*K + k];
    }
    out[idx] = s;
}

// ---------------- depthwise vertical (K x 1), pad (PAD, 0); write or accumulate ----------------
template<int K, int PAD, int MODE>   // MODE 0: out = base + v ; MODE 1: out += v
__global__ void __launch_bounds__(256) dwv_k(
    const float* __restrict__ in, const float* __restrict__ wk,
    const float* __restrict__ bias, const float* __restrict__ base,
    float* __restrict__ out)
{
    int idx = blockIdx.x * 256 + threadIdx.x;
    int w = idx & (Ww - 1);
    int h = (idx >> 6) & (Hh - 1);
    int c = (idx >> 12) & (Cc - 1);
    const float* plane = in + (idx & ~(HW - 1));
    float s = bias[c];
#pragma unroll
    for (int k = 0; k < K; k++) {
        int hh = h + k - PAD;
        if (hh >= 0 && hh < Hh) s += plane[hh*Ww + w] * wk[c*K + k];
    }
    if (MODE) out[idx] += s;
    else      out[idx] = base[idx] + s;
}

// ---------------- 1x1 projection 256 -> 32 : g_t = w_proj @ g_sum + b ----------------
// grid 64 blocks x 256 threads; thread = one (b, pixel)
__global__ void __launch_bounds__(256) proj_k(
    const float* __restrict__ w_proj, const float* __restrict__ b_proj)
{
    __shared__ float ws[Cc*C8];   // transposed: ws[c*32+o] = w_proj[o*256+c]
    __shared__ float bs[C8];
    int tid = threadIdx.x;
    for (int idx = tid; idx < Cc*C8; idx += 256) {
        int o = idx >> 8, c = idx & 255;
        ws[c*C8 + o] = w_proj[o*Cc + c];
    }
    if (tid < C8) bs[tid] = b_proj[tid];
    __syncthreads();

    int g = blockIdx.x * 256 + tid;         // 0..16383
    int b = g >> 12, k = g & (HW - 1);
    float acc[C8];
#pragma unroll
    for (int o = 0; o < C8; o++) acc[o] = bs[o];

    const float* src = g_sum + (size_t)b*Cc*HW + k;
    for (int c = 0; c < Cc; c++) {
        float v = src[(size_t)c*HW];
        const float4* wv = (const float4*)(ws + c*C8);
#pragma unroll
        for (int d = 0; d < 8; d++) {
            float4 ww = wv[d];
            acc[d*4+0] += ww.x * v;
            acc[d*4+1] += ww.y * v;
            acc[d*4+2] += ww.z * v;
            acc[d*4+3] += ww.w * v;
        }
    }
    float* dst = g_t + (size_t)b*C8*HW + k;
#pragma unroll
    for (int o = 0; o < C8; o++) dst[(size_t)o*HW] = acc[o];
}

// ---------------- channel attention: gram + softmax -> g_attn1 ----------------
// grid 4 (batch), block 1024; thread (i,j) computes dot(t_i, t_j)
__global__ void __launch_bounds__(1024) chattn_k()
{
    int b = blockIdx.x;
    int tid = threadIdx.x;
    int i = tid >> 5, j = tid & 31;

    __shared__ float st[32*129];
    __shared__ float G[32*32];
    __shared__ float ninv[32];

    const float* tb = g_t + (size_t)b*C8*HW;
    float dot = 0.f;
    for (int kt = 0; kt < 32; kt++) {
        for (int idx = tid; idx < 32*128; idx += 1024) {
            int c = idx >> 7, x = idx & 127;
            st[c*129 + x] = tb[(size_t)c*HW + kt*128 + x];
        }
        __syncthreads();
#pragma unroll 8
        for (int x = 0; x < 128; x++)
            dot += st[i*129 + x] * st[j*129 + x];
        __syncthreads();
    }
    G[i*32 + j] = dot;
    if (i == j) ninv[i] = 1.f / fmaxf(sqrtf(dot), 1e-12f);
    __syncthreads();

    if (tid < 32) {
        int r = tid;
        float ir = ninv[r];
        float row[32];
        float s = 0.f;
#pragma unroll
        for (int jj = 0; jj < 32; jj++) {
            float a = G[r*32 + jj] * ir * ninv[jj];   // in [-1, 1]
            float p = expf(a - 1.f);
            row[jj] = p; s += p;
        }
        float is = 1.f / s;
        float* dst = g_attn1 + b*C8*C8 + r*32;
#pragma unroll
        for (int jj = 0; jj < 32; jj++) dst[jj] = row[jj] * is;
    }
}

// ---------------- out2 = attn1 @ t ----------------
// grid (32, 4), block 128; thread = one pixel column
__global__ void __launch_bounds__(128) chout_k()
{
    __shared__ float A[C8*C8];
    int tid = threadIdx.x;
    int b = blockIdx.y;
    for (int idx = tid; idx < C8*C8; idx += 128) A[idx] = g_attn1[b*C8*C8 + idx];
    __syncthreads();

    int k = blockIdx.x * 128 + tid;
    const float* tb = g_t + (size_t)b*C8*HW + k;
    float tv[C8];
#pragma unroll
    for (int j = 0; j < C8; j++) tv[j] = tb[(size_t)j*HW];

    float* dst = g_out2 + (size_t)b*C8*HW + k;
#pragma unroll
    for (int i = 0; i < C8; i++) {
        float s = 0.f;
#pragma unroll
        for (int j = 0; j < C8; j++) s += A[i*32 + j] * tv[j];
        dst[(size_t)i*HW] = s;
    }
}

// ---------------- transpose + l2-normalize -> g_ts, g_q2n ----------------
__global__ void __launch_bounds__(128) tnorm_k()
{
    int g = blockIdx.x * 128 + threadIdx.x;   // b*4096 + k
    int b = g >> 12, k = g & (HW - 1);
    const float* src = g_t + (size_t)b*C8*HW + k;
    float v[C8]; float ss = 0.f;
#pragma unroll
    for (int c = 0; c < C8; c++) { v[c] = src[(size_t)c*HW]; ss += v[c]*v[c]; }
    float inv = 1.f / fmaxf(sqrtf(ss), 1e-12f);
    float4* tsp = (float4*)(g_ts  + (size_t)g*C8);
    float4* qp  = (float4*)(g_q2n + (size_t)g*C8);
#pragma unroll
    for (int d = 0; d < 8; d++) {
        tsp[d] = make_float4(v[d*4+0], v[d*4+1], v[d*4+2], v[d*4+3]);
        qp[d]  = make_float4(v[d*4+0]*inv, v[d*4+1]*inv, v[d*4+2]*inv, v[d*4+3]*inv);
    }
}

// ---------------- spatial attention, single-pass softmax (logits <= 1) ----------------
// grid (32 q-tiles, 4 batch), block 128; thread = one query row
__global__ void __launch_bounds__(128) spattn_k()
{
    __shared__ float4 sK[8*128];   // [d4][row] layout: conflict-free stores, broadcast reads
    __shared__ float4 sV[8*128];

    int tid = threadIdx.x;
    int b = blockIdx.y;
    int qrow = blockIdx.x * 128 + tid;

    float q[C8];
    {
        const float4* qp = (const float4*)(g_q2n + ((size_t)b*HW + qrow)*C8);
#pragma unroll
        for (int d = 0; d < 8; d++) {
            float4 t4 = qp[d];
            q[d*4+0]=t4.x; q[d*4+1]=t4.y; q[d*4+2]=t4.z; q[d*4+3]=t4.w;
        }
    }

    float acc[C8];
#pragma unroll
    for (int d = 0; d < C8; d++) acc[d] = 0.f;
    float l = 0.f;

    for (int kt = 0; kt < 32; kt++) {
        __syncthreads();
        int krow = kt * 128 + tid;
        const float4* kp = (const float4*)(g_q2n + ((size_t)b*HW + krow)*C8);
        const float4* vp = (const float4*)(g_ts  + ((size_t)b*HW + krow)*C8);
#pragma unroll
        for (int d = 0; d < 8; d++) { sK[d*128 + tid] = kp[d]; sV[d*128 + tid] = vp[d]; }
        __syncthreads();

#pragma unroll 2
        for (int j = 0; j < 128; j++) {
            float s = 0.f;
#pragma unroll
            for (int d = 0; d < 8; d++) {
                float4 kk = sK[d*128 + j];
                s += q[d*4+0]*kk.x + q[d*4+1]*kk.y + q[d*4+2]*kk.z + q[d*4+3]*kk.w;
            }
            float p = __expf(s - 1.f);   // logits in [-1,1]: exact softmax, no running max
            l += p;
#pragma unroll
            for (int d = 0; d < 8; d++) {
                float4 vv = sV[d*128 + j];
                acc[d*4+0] += p*vv.x; acc[d*4+1] += p*vv.y;
                acc[d*4+2] += p*vv.z; acc[d*4+3] += p*vv.w;
            }
        }
    }

    float inv = 1.f / l;
    float* dst = g_out3 + (size_t)b*C8*HW + qrow;
#pragma unroll
    for (int d = 0; d < C8; d++) dst[(size_t)d*HW] = acc[d] * inv;
}

// ---------------- final: out5 = w3 @ cat(out2,out3) + b3 + t ; out = w4 @ out5 + b4 ----------------
__global__ void __launch_bounds__(128) final_k(
    const float* __restrict__ w3, const float* __restrict__ b3,
    const float* __restrict__ w4, const float* __restrict__ b4,
    float* __restrict__ out)
{
    __shared__ float sw3[64*32];    // transposed: sw3[j*32+o] = w3[o*64+j]
    __shared__ float sw4[Cc*C8];    // original [co][o]
    __shared__ float sb3[C8];
    __shared__ float sb4[Cc];

    int tid = threadIdx.x;
    for (int idx = tid; idx < 64*32; idx += 128) {
        int j = idx >> 5, o = idx & 31;
        sw3[j*32 + o] = w3[o*64 + j];
    }
    for (int idx = tid; idx < Cc*C8; idx += 128) sw4[idx] = w4[idx];
    if (tid < C8) sb3[tid] = b3[tid];
    for (int idx = tid; idx < Cc; idx += 128) sb4[idx] = b4[idx];
    __syncthreads();

    int g = blockIdx.x * 128 + tid;
    int b = g >> 12, k = g & (HW - 1);

    float cat[64];
    {
        const float* o2 = g_out2 + (size_t)b*C8*HW + k;
        const float* o3 = g_out3 + (size_t)b*C8*HW + k;
#pragma unroll
        for (int c = 0; c < C8; c++) cat[c]      = o2[(size_t)c*HW];
#pragma unroll
        for (int c = 0; c < C8; c++) cat[32 + c] = o3[(size_t)c*HW];
    }

    float o5[C8];
    {
        const float* tb = g_t + (size_t)b*C8*HW + k;
#pragma unroll
        for (int o = 0; o < C8; o++) o5[o] = sb3[o] + tb[(size_t)o*HW];
    }
#pragma unroll 4
    for (int j = 0; j < 64; j++) {
        float v = cat[j];
        const float4* wv = (const float4*)(sw3 + j*32);
#pragma unroll
        for (int d = 0; d < 8; d++) {
            float4 ww = wv[d];
            o5[d*4+0] += ww.x*v; o5[d*4+1] += ww.y*v;
            o5[d*4+2] += ww.z*v; o5[d*4+3] += ww.w*v;
        }
    }

    float* dst = out + (size_t)b*Cc*HW + k;
    for (int co = 0; co < Cc; co++) {
        const float4* wr = (const float4*)(sw4 + co*C8);
        float s = sb4[co];
#pragma unroll
        for (int d = 0; d < 8; d++) {
            float4 ww = wr[d];
            s += ww.x*o5[d*4+0] + ww.y*o5[d*4+1] + ww.z*o5[d*4+2] + ww.w*o5[d*4+3];
        }
        dst[(size_t)co*HW] = s;
    }
}

// ---------------- launch ----------------
extern "C" void kernel_launch(void* const* d_in, const int* in_sizes, int n_in,
                              void* d_out, int out_size)
{
    const float* x      = (const float*)d_in[0];
    const float* w_conv = (const float*)d_in[1];
    const float* b_conv = (const float*)d_in[2];
    const float* w01 = (const float*)d_in[3];
    const float* b01 = (const float*)d_in[4];
    const float* w02 = (const float*)d_in[5];
    const float* b02 = (const float*)d_in[6];
    const float* w11 = (const float*)d_in[7];
    const float* b11 = (const float*)d_in[8];
    const float* w12 = (const float*)d_in[9];
    const float* b12 = (const float*)d_in[10];
    const float* w21 = (const float*)d_in[11];
    const float* b21 = (const float*)d_in[12];
    const float* w22 = (const float*)d_in[13];
    const float* b22 = (const float*)d_in[14];
    const float* w_proj = (const float*)d_in[15];
    const float* b_proj = (const float*)d_in[16];
    const float* w3 = (const float*)d_in[17];
    const float* b3 = (const float*)d_in[18];
    const float* w4 = (const float*)d_in[19];
    const float* b4 = (const float*)d_in[20];
    float* out = (float*)d_out;

    float *px, *ptmp, *psum;
    cudaGetSymbolAddress((void**)&px,   g_x);
    cudaGetSymbolAddress((void**)&ptmp, g_tmp);
    cudaGetSymbolAddress((void**)&psum, g_sum);

    conv3x3_k<<<dim3(4, 64, 4), 256>>>(x, w_conv, b_conv);

    const int NB = Bn*Cc*HW / 256;   // 16384
    dwh_k<7,3>     <<<NB, 256>>>(px,   w01, b01, ptmp);
    dwv_k<7,3,0>   <<<NB, 256>>>(ptmp, w02, b02, px, psum);
    dwh_k<11,5>    <<<NB, 256>>>(px,   w11, b11, ptmp);
    dwv_k<11,5,1>  <<<NB, 256>>>(ptmp, w12, b12, px, psum);
    dwh_k<21,10>   <<<NB, 256>>>(px,   w21, b21, ptmp);
    dwv_k<21,10,1> <<<NB, 256>>>(ptmp, w22, b22, px, psum);

    proj_k  <<<64, 256>>>(w_proj, b_proj);
    chattn_k<<<4, 1024>>>();
    chout_k <<<dim3(32, 4), 128>>>();
    tnorm_k <<<128, 128>>>();
    spattn_k<<<dim3(32, 4), 128>>>();
    final_k <<<128, 128>>>(w3, b3, w4, b4, out);
}

// round 2
// speedup vs baseline: 1.6103x; 1.6103x over previous
#include <cuda_runtime.h>
#include <math.h>

#define Bn 4
#define Cc 256
#define C8 32
#define Hh 64
#define Ww 64
#define HW 4096

typedef unsigned long long u64;

__device__ __forceinline__ u64 ffma2(u64 a, u64 b, u64 c){
    u64 d; asm("fma.rn.f32x2 %0, %1, %2, %3;" : "=l"(d) : "l"(a), "l"(b), "l"(c)); return d;
}
__device__ __forceinline__ u64 pack2(float lo, float hi){
    u64 d; asm("mov.b64 %0, {%1, %2};" : "=l"(d) : "f"(lo), "f"(hi)); return d;
}
__device__ __forceinline__ float2 unpack2(u64 v){
    float lo, hi; asm("mov.b64 {%0, %1}, %2;" : "=f"(lo), "=f"(hi) : "l"(v));
    return make_float2(lo, hi);
}

// ---------------- scratch ----------------
__device__ float g_x  [Bn*Cc*HW];   // after 3x3 conv
__device__ float g_sum[Bn*Cc*HW];   // x + x1 + x2 + x3
__device__ float g_t  [Bn*C8*HW];   // projected out1 [b, 32, hw]
__device__ float g_attn1[Bn*C8*C8];
__device__ float g_out2[Bn*C8*HW];
__device__ float g_out3[Bn*C8*HW];
__device__ float g_ts  [Bn*HW*C8];
__device__ float g_q2n [Bn*HW*C8];
__device__ float g_p3 [Bn*4*HW*C8]; // split-k partial acc
__device__ float g_pl [Bn*4*HW];    // split-k partial l

// ================= 3x3 conv 256->256 pad 1, f32x2, double-buffered =================
// grid (2 h-tiles of 32, 32 co-groups of 8, 4 b); block 256
// thread: ty=tid>>3 (row), tx=tid&7 (8 cols as 4 f32x2 pairs), 8 output channels
__global__ void __launch_bounds__(256, 2) conv3x3_k(
    const float* __restrict__ x, const float* __restrict__ w,
    const float* __restrict__ bias)
{
    __shared__ float  sIn[2][34*68];
    __shared__ float2 sW [2][72];

    const int ht = blockIdx.x, cog = blockIdx.y, b = blockIdx.z;
    const int tid = threadIdx.x;
    const int ty = tid >> 3, tx = tid & 7;
    const int h0 = ht * 32;

    // staging descriptors (fixed across ci)
    int goff[9], soff[9];
    bool vld[9], act[9];
    const float* xbase = x + (size_t)b*Cc*HW;
#pragma unroll
    for (int s = 0; s < 9; s++) {
        int idx = tid + s*256;
        bool a = idx < 34*66;
        int r = idx / 66, c = idx - r*66;
        int gh = h0 + r - 1, gw = c - 1;
        act[s] = a;
        vld[s] = a && gh >= 0 && gh < Hh && gw >= 0 && gw < Ww;
        goff[s] = vld[s] ? (gh*Ww + gw) : 0;
        soff[s] = a ? (r*68 + c) : 0;
    }
    const int wo = tid / 9, wk = tid - wo*9;   // weight staging role (tid<72)

    // prologue: stage ci=0
#pragma unroll
    for (int s = 0; s < 9; s++)
        if (act[s]) sIn[0][soff[s]] = vld[s] ? __ldg(xbase + goff[s]) : 0.f;
    if (tid < 72) {
        float wv = w[((size_t)(cog*8 + wo)*Cc + 0)*9 + wk];
        sW[0][tid] = make_float2(wv, wv);
    }
    __syncthreads();

    u64 acc[8][4];
#pragma unroll
    for (int o = 0; o < 8; o++) {
        float bv = bias[cog*8 + o];
        u64 bp = pack2(bv, bv);
#pragma unroll
        for (int p = 0; p < 4; p++) acc[o][p] = bp;
    }

    for (int ci = 0; ci < Cc; ci++) {
        const int cur = ci & 1;

        // prefetch next plane into regs
        float pref[9]; float wpre = 0.f;
        if (ci < Cc-1) {
            const float* xp = xbase + (size_t)(ci+1)*HW;
#pragma unroll
            for (int s = 0; s < 9; s++) pref[s] = vld[s] ? __ldg(xp + goff[s]) : 0.f;
            if (tid < 72) wpre = w[((size_t)(cog*8 + wo)*Cc + (ci+1))*9 + wk];
        }

        const u64* wp = (const u64*)sW[cur];
#pragma unroll
        for (int kh = 0; kh < 3; kh++) {
            const float2* rp = (const float2*)(sIn[cur] + (ty + kh)*68 + tx*8);
            float2 p0 = rp[0], p1 = rp[1], p2 = rp[2], p3 = rp[3], p4 = rp[4];
            u64 e0 = pack2(p0.x, p0.y), e1 = pack2(p1.x, p1.y);
            u64 e2 = pack2(p2.x, p2.y), e3 = pack2(p3.x, p3.y);
            u64 e4 = pack2(p4.x, p4.y);
            u64 s0 = pack2(p0.y, p1.x), s1 = pack2(p1.y, p2.x);
            u64 s2 = pack2(p2.y, p3.x), s3 = pack2(p3.y, p4.x);
#pragma unroll
            for (int o = 0; o < 8; o++) {
                u64 w0 = wp[o*9 + kh*3 + 0];
                u64 w1 = wp[o*9 + kh*3 + 1];
                u64 w2 = wp[o*9 + kh*3 + 2];
                acc[o][0] = ffma2(w0, e0, acc[o][0]);
                acc[o][1] = ffma2(w0, e1, acc[o][1]);
                acc[o][2] = ffma2(w0, e2, acc[o][2]);
                acc[o][3] = ffma2(w0, e3, acc[o][3]);
                acc[o][0] = ffma2(w1, s0, acc[o][0]);
                acc[o][1] = ffma2(w1, s1, acc[o][1]);
                acc[o][2] = ffma2(w1, s2, acc[o][2]);
                acc[o][3] = ffma2(w1, s3, acc[o][3]);
                acc[o][0] = ffma2(w2, e1, acc[o][0]);
                acc[o][1] = ffma2(w2, e2, acc[o][1]);
                acc[o][2] = ffma2(w2, e3, acc[o][2]);
                acc[o][3] = ffma2(w2, e4, acc[o][3]);
            }
        }

        if (ci < Cc-1) {
            const int nxt = cur ^ 1;
#pragma unroll
            for (int s = 0; s < 9; s++)
                if (act[s]) sIn[nxt][soff[s]] = pref[s];
            if (tid < 72) sW[nxt][tid] = make_float2(wpre, wpre);
        }
        __syncthreads();
    }

    float* outp = g_x + ((size_t)(b*Cc + cog*8))*HW + (h0 + ty)*Ww + tx*8;
#pragma unroll
    for (int o = 0; o < 8; o++) {
        float2* dp = (float2*)(outp + (size_t)o*HW);
#pragma unroll
        for (int p = 0; p < 4; p++) dp[p] = unpack2(acc[o][p]);
    }
}

// ================= fused depthwise: all 3 separable scales + residual =================
template<int K>
__device__ __forceinline__ void dw_scale(
    const float* xs, float* hb, float out[16],
    const float* __restrict__ wh_c, const float* __restrict__ wv_c,
    float bh, float bv, int w, int h0)
{
    constexpr int P = K/2;
    float whr[K];
#pragma unroll
    for (int k = 0; k < K; k++) whr[k] = __ldg(wh_c + k);
#pragma unroll
    for (int i = 0; i < 16; i++) {
        int h = h0 + i; float s = bh;
#pragma unroll
        for (int k = 0; k < K; k++) {
            int ww = w + k - P;
            if (ww >= 0 && ww < Ww) s += whr[k] * xs[h*Ww + ww];
        }
        hb[h*Ww + w] = s;
    }
    __syncthreads();
    float wvr[K];
#pragma unroll
    for (int k = 0; k < K; k++) wvr[k] = __ldg(wv_c + k);
#pragma unroll
    for (int i = 0; i < 16; i++) {
        int h = h0 + i; float s = bv;
#pragma unroll
        for (int k = 0; k < K; k++) {
            int hh = h + k - P;
            if (hh >= 0 && hh < Hh) s += wvr[k] * hb[hh*Ww + w];
        }
        out[i] += s;
    }
    __syncthreads();
}

__global__ void __launch_bounds__(256) dwfused_k(
    const float* __restrict__ w01, const float* __restrict__ b01,
    const float* __restrict__ w02, const float* __restrict__ b02,
    const float* __restrict__ w11, const float* __restrict__ b11,
    const float* __restrict__ w12, const float* __restrict__ b12,
    const float* __restrict__ w21, const float* __restrict__ b21,
    const float* __restrict__ w22, const float* __restrict__ b22)
{
    __shared__ float xs[HW];
    __shared__ float hb[HW];
    const int plane = blockIdx.x;         // b*256 + c
    const int c = plane & (Cc-1);
    const int tid = threadIdx.x;
    const float* src = g_x + (size_t)plane*HW;

#pragma unroll
    for (int s = 0; s < 4; s++)
        ((float4*)xs)[tid + s*256] = ((const float4*)src)[tid + s*256];
    __syncthreads();

    const int w  = tid & 63;
    const int h0 = (tid >> 6) * 16;

    float out[16];
#pragma unroll
    for (int i = 0; i < 16; i++) out[i] = xs[(h0+i)*Ww + w];

    dw_scale<7> (xs, hb, out, w01 + c*7,  w02 + c*7,  __ldg(b01+c), __ldg(b02+c), w, h0);
    dw_scale<11>(xs, hb, out, w11 + c*11, w12 + c*11, __ldg(b11+c), __ldg(b12+c), w, h0);
    dw_scale<21>(xs, hb, out, w21 + c*21, w22 + c*21, __ldg(b21+c), __ldg(b22+c), w, h0);

    float* dst = g_sum + (size_t)plane*HW;
#pragma unroll
    for (int i = 0; i < 16; i++) dst[(h0+i)*Ww + w] = out[i];
}

// ================= 1x1 proj 256 -> 32 (f32x2) =================
__global__ void __launch_bounds__(128) proj_k(
    const float* __restrict__ w_proj, const float* __restrict__ b_proj)
{
    __shared__ float ws[Cc*C8];   // ws[c*32+o] = w_proj[o*256+c]
    const int tid = threadIdx.x;
    for (int idx = tid; idx < Cc*C8; idx += 128) {
        int o = idx >> 8, c = idx & 255;
        ws[c*C8 + o] = w_proj[o*Cc + c];
    }
    __syncthreads();

    const int g = blockIdx.x * 128 + tid;
    const int b = g >> 12, k = g & (HW-1);

    u64 acc[16];
#pragma unroll
    for (int d = 0; d < 16; d++) acc[d] = pack2(b_proj[2*d], b_proj[2*d+1]);

    const float* src = g_sum + (size_t)b*Cc*HW + k;
#pragma unroll 4
    for (int c = 0; c < Cc; c++) {
        float v = __ldg(src + (size_t)c*HW);
        u64 vp = pack2(v, v);
        const u64* wrow = (const u64*)(ws + c*C8);
#pragma unroll
        for (int d = 0; d < 16; d++) acc[d] = ffma2(vp, wrow[d], acc[d]);
    }
    float* dst = g_t + (size_t)b*C8*HW + k;
#pragma unroll
    for (int d = 0; d < 16; d++) {
        float2 v = unpack2(acc[d]);
        dst[(size_t)(2*d)*HW]   = v.x;
        dst[(size_t)(2*d+1)*HW] = v.y;
    }
}

// ================= channel attention gram + softmax =================
__global__ void __launch_bounds__(1024) chattn_k()
{
    int b = blockIdx.x;
    int tid = threadIdx.x;
    int i = tid >> 5, j = tid & 31;

    __shared__ float st[32*129];
    __shared__ float G[32*32];
    __shared__ float ninv[32];

    const float* tb = g_t + (size_t)b*C8*HW;
    float dot = 0.f;
    for (int kt = 0; kt < 32; kt++) {
        for (int idx = tid; idx < 32*128; idx += 1024) {
            int c = idx >> 7, x = idx & 127;
            st[c*129 + x] = tb[(size_t)c*HW + kt*128 + x];
        }
        __syncthreads();
#pragma unroll 8
        for (int x = 0; x < 128; x++)
            dot += st[i*129 + x] * st[j*129 + x];
        __syncthreads();
    }
    G[i*32 + j] = dot;
    if (i == j) ninv[i] = 1.f / fmaxf(sqrtf(dot), 1e-12f);
    __syncthreads();

    if (tid < 32) {
        int r = tid;
        float ir = ninv[r];
        float row[32]; float s = 0.f;
#pragma unroll
        for (int jj = 0; jj < 32; jj++) {
            float a = G[r*32 + jj] * ir * ninv[jj];
            float p = expf(a - 1.f);
            row[jj] = p; s += p;
        }
        float is = 1.f / s;
        float* dst = g_attn1 + b*C8*C8 + r*32;
#pragma unroll
        for (int jj = 0; jj < 32; jj++) dst[jj] = row[jj] * is;
    }
}

// ================= out2 = attn1 @ t =================
__global__ void __launch_bounds__(128) chout_k()
{
    __shared__ float A[C8*C8];
    int tid = threadIdx.x;
    int b = blockIdx.y;
    for (int idx = tid; idx < C8*C8; idx += 128) A[idx] = g_attn1[b*C8*C8 + idx];
    __syncthreads();

    int k = blockIdx.x * 128 + tid;
    const float* tb = g_t + (size_t)b*C8*HW + k;
    float tv[C8];
#pragma unroll
    for (int j = 0; j < C8; j++) tv[j] = tb[(size_t)j*HW];

    float* dst = g_out2 + (size_t)b*C8*HW + k;
#pragma unroll
    for (int i = 0; i < C8; i++) {
        float s = 0.f;
#pragma unroll
        for (int j = 0; j < C8; j++) s += A[i*32 + j] * tv[j];
        dst[(size_t)i*HW] = s;
    }
}

// ================= transpose + l2norm =================
__global__ void __launch_bounds__(128) tnorm_k()
{
    int g = blockIdx.x * 128 + threadIdx.x;
    int b = g >> 12, k = g & (HW-1);
    const float* src = g_t + (size_t)b*C8*HW + k;
    float v[C8]; float ss = 0.f;
#pragma unroll
    for (int c = 0; c < C8; c++) { v[c] = src[(size_t)c*HW]; ss += v[c]*v[c]; }
    float inv = 1.f / fmaxf(sqrtf(ss), 1e-12f);
    float4* tsp = (float4*)(g_ts  + (size_t)g*C8);
    float4* qp  = (float4*)(g_q2n + (size_t)g*C8);
#pragma unroll
    for (int d = 0; d < 8; d++) {
        tsp[d] = make_float4(v[d*4+0], v[d*4+1], v[d*4+2], v[d*4+3]);
        qp[d]  = make_float4(v[d*4+0]*inv, v[d*4+1]*inv, v[d*4+2]*inv, v[d*4+3]*inv);
    }
}

// ================= spatial attention: split-K x4, f32x2, single-pass softmax =================
// grid (16 q-tiles of 256, 4 k-splits, 4 b); block 256
__global__ void __launch_bounds__(256, 2) spattn_k()
{
    __shared__ u64 sK[16*128];
    __shared__ u64 sV[16*128];

    const int tid = threadIdx.x;
    const int qt = blockIdx.x, ks = blockIdx.y, b = blockIdx.z;
    const int q = qt*256 + tid;

    u64 qv[16];
    {
        const float4* qp = (const float4*)(g_q2n + ((size_t)b*HW + q)*C8);
#pragma unroll
        for (int d = 0; d < 8; d++) {
            float4 t = qp[d];
            qv[2*d]   = pack2(t.x, t.y);
            qv[2*d+1] = pack2(t.z, t.w);
        }
    }
    const u64 zero = pack2(0.f, 0.f);
    u64 acc[16];
#pragma unroll
    for (int d = 0; d < 16; d++) acc[d] = zero;
    float l = 0.f;

    for (int kt = 0; kt < 8; kt++) {
        __syncthreads();
        {
            int r = tid & 127;
            const float* src = (tid < 128) ? g_q2n : g_ts;
            u64* dst = (tid < 128) ? sK : sV;
            const float4* p = (const float4*)(src + ((size_t)b*HW + ks*1024 + kt*128 + r)*C8);
#pragma unroll
            for (int d = 0; d < 8; d++) {
                float4 t = p[d];
                dst[(2*d)*128 + r]   = pack2(t.x, t.y);
                dst[(2*d+1)*128 + r] = pack2(t.z, t.w);
            }
        }
        __syncthreads();

#pragma unroll 2
        for (int j = 0; j < 128; j++) {
            u64 s2 = zero;
#pragma unroll
            for (int d = 0; d < 16; d++) s2 = ffma2(qv[d], sK[d*128 + j], s2);
            float2 sf = unpack2(s2);
            float p = __expf(sf.x + sf.y - 1.f);   // logits in [-1,1]: exact softmax
            l += p;
            u64 pp = pack2(p, p);
#pragma unroll
            for (int d = 0; d < 16; d++) acc[d] = ffma2(pp, sV[d*128 + j], acc[d]);
        }
    }

    float2* pa = (float2*)(g_p3 + ((size_t)(b*4 + ks)*HW + q)*C8);
#pragma unroll
    for (int d = 0; d < 16; d++) pa[d] = unpack2(acc[d]);
    g_pl[(size_t)(b*4 + ks)*HW + q] = l;
}

// ================= combine split-K partials -> out3 =================
__global__ void __launch_bounds__(256) combine_k()
{
    int g = blockIdx.x * 256 + threadIdx.x;    // 16384
    int b = g >> 12, q = g & (HW-1);
    float l = 0.f;
#pragma unroll
    for (int ks = 0; ks < 4; ks++) l += g_pl[(size_t)(b*4 + ks)*HW + q];
    float inv = 1.f / l;

    float a[C8];
#pragma unroll
    for (int c = 0; c < C8; c++) a[c] = 0.f;
#pragma unroll
    for (int ks = 0; ks < 4; ks++) {
        const float4* pa = (const float4*)(g_p3 + ((size_t)(b*4 + ks)*HW + q)*C8);
#pragma unroll
        for (int d = 0; d < 8; d++) {
            float4 v = pa[d];
            a[d*4+0] += v.x; a[d*4+1] += v.y; a[d*4+2] += v.z; a[d*4+3] += v.w;
        }
    }
    float* dst = g_out3 + (size_t)b*C8*HW + q;
#pragma unroll
    for (int c = 0; c < C8; c++) dst[(size_t)c*HW] = a[c] * inv;
}

// ================= final: out5 = w3 @ cat(out2,out3) + b3 + t ; out = w4 @ out5 + b4 =================
__global__ void __launch_bounds__(128) final_k(
    const float* __restrict__ w3, const float* __restrict__ b3,
    const float* __restrict__ w4, const float* __restrict__ b4,
    float* __restrict__ out)
{
    __shared__ float sw3[64*32];   // sw3[j*32+o] = w3[o*64+j]
    __shared__ float sw4[Cc*C8];   // [co][o]
    __shared__ float sb4[Cc];

    const int tid = threadIdx.x;
    for (int idx = tid; idx < 64*32; idx += 128) {
        int j = idx >> 5, o = idx & 31;
        sw3[j*32 + o] = w3[o*64 + j];
    }
    for (int idx = tid; idx < Cc*C8; idx += 128) sw4[idx] = w4[idx];
    for (int idx = tid; idx < Cc; idx += 128) sb4[idx] = b4[idx];
    __syncthreads();

    const int g = blockIdx.x * 128 + tid;
    const int b = g >> 12, k = g & (HW-1);

    u64 o5[16];
    {
        const float* tb = g_t + (size_t)b*C8*HW + k;
#pragma unroll
        for (int d = 0; d < 16; d++)
            o5[d] = pack2(b3[2*d] + tb[(size_t)(2*d)*HW],
                          b3[2*d+1] + tb[(size_t)(2*d+1)*HW]);
    }
    {
        const float* o2 = g_out2 + (size_t)b*C8*HW + k;
#pragma unroll 4
        for (int j = 0; j < 32; j++) {
            float v = __ldg(o2 + (size_t)j*HW);
            u64 vp = pack2(v, v);
            const u64* wr = (const u64*)(sw3 + j*32);
#pragma unroll
            for (int d = 0; d < 16; d++) o5[d] = ffma2(vp, wr[d], o5[d]);
        }
        const float* o3 = g_out3 + (size_t)b*C8*HW + k;
#pragma unroll 4
        for (int j = 0; j < 32; j++) {
            float v = __ldg(o3 + (size_t)j*HW);
            u64 vp = pack2(v, v);
            const u64* wr = (const u64*)(sw3 + (32+j)*32);
#pragma unroll
            for (int d = 0; d < 16; d++) o5[d] = ffma2(vp, wr[d], o5[d]);
        }
    }

    float* dst = out + (size_t)b*Cc*HW + k;
#pragma unroll 2
    for (int co = 0; co < Cc; co += 2) {
        const u64* w0 = (const u64*)(sw4 + co*C8);
        const u64* w1 = (const u64*)(sw4 + (co+1)*C8);
        u64 s0 = pack2(0.f, 0.f), s1 = pack2(0.f, 0.f);
#pragma unroll
        for (int d = 0; d < 16; d++) {
            s0 = ffma2(w0[d], o5[d], s0);
            s1 = ffma2(w1[d], o5[d], s1);
        }
        float2 f0 = unpack2(s0), f1 = unpack2(s1);
        dst[(size_t)co*HW]     = f0.x + f0.y + sb4[co];
        dst[(size_t)(co+1)*HW] = f1.x + f1.y + sb4[co+1];
    }
}

// ================= launch =================
extern "C" void kernel_launch(void* const* d_in, const int* in_sizes, int n_in,
                              void* d_out, int out_size)
{
    const float* x      = (const float*)d_in[0];
    const float* w_conv = (const float*)d_in[1];
    const float* b_conv = (const float*)d_in[2];
    const float* w01 = (const float*)d_in[3];
    const float* b01 = (const float*)d_in[4];
    const float* w02 = (const float*)d_in[5];
    const float* b02 = (const float*)d_in[6];
    const float* w11 = (const float*)d_in[7];
    const float* b11 = (const float*)d_in[8];
    const float* w12 = (const float*)d_in[9];
    const float* b12 = (const float*)d_in[10];
    const float* w21 = (const float*)d_in[11];
    const float* b21 = (const float*)d_in[12];
    const float* w22 = (const float*)d_in[13];
    const float* b22 = (const float*)d_in[14];
    const float* w_proj = (const float*)d_in[15];
    const float* b_proj = (const float*)d_in[16];
    const float* w3 = (const float*)d_in[17];
    const float* b3 = (const float*)d_in[18];
    const float* w4 = (const float*)d_in[19];
    const float* b4 = (const float*)d_in[20];
    float* out = (float*)d_out;

    conv3x3_k<<<dim3(2, 32, 4), 256>>>(x, w_conv, b_conv);
    dwfused_k<<<Bn*Cc, 256>>>(w01, b01, w02, b02, w11, b11, w12, b12, w21, b21, w22, b22);
    proj_k   <<<128, 128>>>(w_proj, b_proj);
    chattn_k <<<4, 1024>>>();
    chout_k  <<<dim3(32, 4), 128>>>();
    tnorm_k  <<<128, 128>>>();
    spattn_k <<<dim3(16, 4, 4), 256>>>();
    combine_k<<<64, 256>>>();
    final_k  <<<128, 128>>>(w3, b3, w4, b4, out);
}

// round 3
// speedup vs baseline: 1.8476x; 1.1474x over previous
#include <cuda_runtime.h>
#include <math.h>

#define Bn 4
#define Cc 256
#define C8 32
#define Hh 64
#define Ww 64
#define HW 4096

typedef unsigned long long u64;

__device__ __forceinline__ u64 ffma2(u64 a, u64 b, u64 c){
    u64 d; asm("fma.rn.f32x2 %0, %1, %2, %3;" : "=l"(d) : "l"(a), "l"(b), "l"(c)); return d;
}
__device__ __forceinline__ u64 pack2(float lo, float hi){
    u64 d; asm("mov.b64 %0, {%1, %2};" : "=l"(d) : "f"(lo), "f"(hi)); return d;
}
__device__ __forceinline__ float2 unpack2(u64 v){
    float lo, hi; asm("mov.b64 {%0, %1}, %2;" : "=f"(lo), "=f"(hi) : "l"(v));
    return make_float2(lo, hi);
}

// ---------------- scratch ----------------
__device__ float g_x  [Bn*Cc*HW];
__device__ float g_sum[Bn*Cc*HW];
__device__ float g_t  [Bn*C8*HW];     // [b, 32, hw]
__device__ float g_attn1[Bn*C8*C8];
__device__ float g_out3[Bn*C8*HW];
__device__ float g_q2n [Bn*HW*C8];    // normalized rows [b, hw, 32]
__device__ float g_norm[Bn*HW];       // row norms
__device__ float g_pgram[Bn*32*C8*C8];
__device__ float g_p3 [Bn*4*HW*C8];
__device__ float g_pl [Bn*4*HW];

// ================= 3x3 conv 256->256 pad 1, f32x2, double-buffered =================
__global__ void __launch_bounds__(256, 2) conv3x3_k(
    const float* __restrict__ x, const float* __restrict__ w,
    const float* __restrict__ bias)
{
    __shared__ float  sIn[2][34*68];
    __shared__ float2 sW [2][72];

    const int ht = blockIdx.x, cog = blockIdx.y, b = blockIdx.z;
    const int tid = threadIdx.x;
    const int ty = tid >> 3, tx = tid & 7;
    const int h0 = ht * 32;

    int goff[9], soff[9];
    bool vld[9], act[9];
    const float* xbase = x + (size_t)b*Cc*HW;
#pragma unroll
    for (int s = 0; s < 9; s++) {
        int idx = tid + s*256;
        bool a = idx < 34*66;
        int r = idx / 66, c = idx - r*66;
        int gh = h0 + r - 1, gw = c - 1;
        act[s] = a;
        vld[s] = a && gh >= 0 && gh < Hh && gw >= 0 && gw < Ww;
        goff[s] = vld[s] ? (gh*Ww + gw) : 0;
        soff[s] = a ? (r*68 + c) : 0;
    }
    const int wo = tid / 9, wk = tid - wo*9;

#pragma unroll
    for (int s = 0; s < 9; s++)
        if (act[s]) sIn[0][soff[s]] = vld[s] ? __ldg(xbase + goff[s]) : 0.f;
    if (tid < 72) {
        float wv = w[((size_t)(cog*8 + wo)*Cc + 0)*9 + wk];
        sW[0][tid] = make_float2(wv, wv);
    }
    __syncthreads();

    u64 acc[8][4];
#pragma unroll
    for (int o = 0; o < 8; o++) {
        float bv = bias[cog*8 + o];
        u64 bp = pack2(bv, bv);
#pragma unroll
        for (int p = 0; p < 4; p++) acc[o][p] = bp;
    }

    for (int ci = 0; ci < Cc; ci++) {
        const int cur = ci & 1;

        float pref[9]; float wpre = 0.f;
        if (ci < Cc-1) {
            const float* xp = xbase + (size_t)(ci+1)*HW;
#pragma unroll
            for (int s = 0; s < 9; s++) pref[s] = vld[s] ? __ldg(xp + goff[s]) : 0.f;
            if (tid < 72) wpre = w[((size_t)(cog*8 + wo)*Cc + (ci+1))*9 + wk];
        }

        const u64* wp = (const u64*)sW[cur];
#pragma unroll
        for (int kh = 0; kh < 3; kh++) {
            const float2* rp = (const float2*)(sIn[cur] + (ty + kh)*68 + tx*8);
            float2 p0 = rp[0], p1 = rp[1], p2 = rp[2], p3 = rp[3], p4 = rp[4];
            u64 e0 = pack2(p0.x, p0.y), e1 = pack2(p1.x, p1.y);
            u64 e2 = pack2(p2.x, p2.y), e3 = pack2(p3.x, p3.y);
            u64 e4 = pack2(p4.x, p4.y);
            u64 s0 = pack2(p0.y, p1.x), s1 = pack2(p1.y, p2.x);
            u64 s2 = pack2(p2.y, p3.x), s3 = pack2(p3.y, p4.x);
#pragma unroll
            for (int o = 0; o < 8; o++) {
                u64 w0 = wp[o*9 + kh*3 + 0];
                u64 w1 = wp[o*9 + kh*3 + 1];
                u64 w2 = wp[o*9 + kh*3 + 2];
                acc[o][0] = ffma2(w0, e0, acc[o][0]);
                acc[o][1] = ffma2(w0, e1, acc[o][1]);
                acc[o][2] = ffma2(w0, e2, acc[o][2]);
                acc[o][3] = ffma2(w0, e3, acc[o][3]);
                acc[o][0] = ffma2(w1, s0, acc[o][0]);
                acc[o][1] = ffma2(w1, s1, acc[o][1]);
                acc[o][2] = ffma2(w1, s2, acc[o][2]);
                acc[o][3] = ffma2(w1, s3, acc[o][3]);
                acc[o][0] = ffma2(w2, e1, acc[o][0]);
                acc[o][1] = ffma2(w2, e2, acc[o][1]);
                acc[o][2] = ffma2(w2, e3, acc[o][2]);
                acc[o][3] = ffma2(w2, e4, acc[o][3]);
            }
        }

        if (ci < Cc-1) {
            const int nxt = cur ^ 1;
#pragma unroll
            for (int s = 0; s < 9; s++)
                if (act[s]) sIn[nxt][soff[s]] = pref[s];
            if (tid < 72) sW[nxt][tid] = make_float2(wpre, wpre);
        }
        __syncthreads();
    }

    float* outp = g_x + ((size_t)(b*Cc + cog*8))*HW + (h0 + ty)*Ww + tx*8;
#pragma unroll
    for (int o = 0; o < 8; o++) {
        float2* dp = (float2*)(outp + (size_t)o*HW);
#pragma unroll
        for (int p = 0; p < 4; p++) dp[p] = unpack2(acc[o][p]);
    }
}

// ================= fused depthwise =================
template<int K>
__device__ __forceinline__ void dw_scale(
    const float* xs, float* hb, float out[16],
    const float* __restrict__ wh_c, const float* __restrict__ wv_c,
    float bh, float bv, int w, int h0)
{
    constexpr int P = K/2;
    float whr[K];
#pragma unroll
    for (int k = 0; k < K; k++) whr[k] = __ldg(wh_c + k);
#pragma unroll
    for (int i = 0; i < 16; i++) {
        int h = h0 + i; float s = bh;
#pragma unroll
        for (int k = 0; k < K; k++) {
            int ww = w + k - P;
            if (ww >= 0 && ww < Ww) s += whr[k] * xs[h*Ww + ww];
        }
        hb[h*Ww + w] = s;
    }
    __syncthreads();
    float wvr[K];
#pragma unroll
    for (int k = 0; k < K; k++) wvr[k] = __ldg(wv_c + k);
#pragma unroll
    for (int i = 0; i < 16; i++) {
        int h = h0 + i; float s = bv;
#pragma unroll
        for (int k = 0; k < K; k++) {
            int hh = h + k - P;
            if (hh >= 0 && hh < Hh) s += wvr[k] * hb[hh*Ww + w];
        }
        out[i] += s;
    }
    __syncthreads();
}

__global__ void __launch_bounds__(256) dwfused_k(
    const float* __restrict__ w01, const float* __restrict__ b01,
    const float* __restrict__ w02, const float* __restrict__ b02,
    const float* __restrict__ w11, const float* __restrict__ b11,
    const float* __restrict__ w12, const float* __restrict__ b12,
    const float* __restrict__ w21, const float* __restrict__ b21,
    const float* __restrict__ w22, const float* __restrict__ b22)
{
    __shared__ float xs[HW];
    __shared__ float hb[HW];
    const int plane = blockIdx.x;
    const int c = plane & (Cc-1);
    const int tid = threadIdx.x;
    const float* src = g_x + (size_t)plane*HW;

#pragma unroll
    for (int s = 0; s < 4; s++)
        ((float4*)xs)[tid + s*256] = ((const float4*)src)[tid + s*256];
    __syncthreads();

    const int w  = tid & 63;
    const int h0 = (tid >> 6) * 16;

    float out[16];
#pragma unroll
    for (int i = 0; i < 16; i++) out[i] = xs[(h0+i)*Ww + w];

    dw_scale<7> (xs, hb, out, w01 + c*7,  w02 + c*7,  __ldg(b01+c), __ldg(b02+c), w, h0);
    dw_scale<11>(xs, hb, out, w11 + c*11, w12 + c*11, __ldg(b11+c), __ldg(b12+c), w, h0);
    dw_scale<21>(xs, hb, out, w21 + c*21, w22 + c*21, __ldg(b21+c), __ldg(b22+c), w, h0);

    float* dst = g_sum + (size_t)plane*HW;
#pragma unroll
    for (int i = 0; i < 16; i++) dst[(h0+i)*Ww + w] = out[i];
}

// ================= 1x1 proj 256 -> 32 =================
__global__ void __launch_bounds__(128) proj_k(
    const float* __restrict__ w_proj, const float* __restrict__ b_proj)
{
    __shared__ float ws[Cc*C8];
    const int tid = threadIdx.x;
    for (int idx = tid; idx < Cc*C8; idx += 128) {
        int o = idx >> 8, c = idx & 255;
        ws[c*C8 + o] = w_proj[o*Cc + c];
    }
    __syncthreads();

    const int g = blockIdx.x * 128 + tid;
    const int b = g >> 12, k = g & (HW-1);

    u64 acc[16];
#pragma unroll
    for (int d = 0; d < 16; d++) acc[d] = pack2(b_proj[2*d], b_proj[2*d+1]);

    const float* src = g_sum + (size_t)b*Cc*HW + k;
#pragma unroll 4
    for (int c = 0; c < Cc; c++) {
        float v = __ldg(src + (size_t)c*HW);
        u64 vp = pack2(v, v);
        const u64* wrow = (const u64*)(ws + c*C8);
#pragma unroll
        for (int d = 0; d < 16; d++) acc[d] = ffma2(vp, wrow[d], acc[d]);
    }
    float* dst = g_t + (size_t)b*C8*HW + k;
#pragma unroll
    for (int d = 0; d < 16; d++) {
        float2 v = unpack2(acc[d]);
        dst[(size_t)(2*d)*HW]   = v.x;
        dst[(size_t)(2*d+1)*HW] = v.y;
    }
}

// ================= gram partials: 32x32 over 128-pixel slabs =================
// grid (32 slabs, 4 b), block 256; thread -> (i, j0..j0+3)
__global__ void __launch_bounds__(256) gram_k()
{
    __shared__ float st[32*129];
    const int slab = blockIdx.x, b = blockIdx.y;
    const int tid = threadIdx.x;
    const float* tb = g_t + (size_t)b*C8*HW + slab*128;
    for (int idx = tid; idx < 32*128; idx += 256) {
        int c = idx >> 7, x = idx & 127;
        st[c*129 + x] = tb[(size_t)c*HW + x];
    }
    __syncthreads();

    const int i  = tid >> 3;
    const int j0 = (tid & 7) * 4;
    const float* ri = st + i*129;
    const float* r0 = st + (j0+0)*129;
    const float* r1 = st + (j0+1)*129;
    const float* r2 = st + (j0+2)*129;
    const float* r3 = st + (j0+3)*129;
    float s0=0.f, s1=0.f, s2=0.f, s3=0.f;
#pragma unroll 8
    for (int x = 0; x < 128; x++) {
        float a = ri[x];
        s0 += a*r0[x]; s1 += a*r1[x]; s2 += a*r2[x]; s3 += a*r3[x];
    }
    float* dst = g_pgram + (((size_t)b*32 + slab) << 10) + i*32 + j0;
    dst[0]=s0; dst[1]=s1; dst[2]=s2; dst[3]=s3;
}

// ================= reduce gram + softmax -> attn1 =================
__global__ void __launch_bounds__(1024) chsoft_k()
{
    const int b = blockIdx.x;
    const int tid = threadIdx.x;
    __shared__ float G[1024];
    __shared__ float ninv[32];

    float g = 0.f;
#pragma unroll
    for (int s = 0; s < 32; s++)
        g += g_pgram[(((size_t)b*32 + s) << 10) + tid];
    G[tid] = g;
    if ((tid >> 5) == (tid & 31)) ninv[tid & 31] = 1.f / fmaxf(sqrtf(g), 1e-12f);
    __syncthreads();

    if (tid < 32) {
        int r = tid;
        float ir = ninv[r];
        float row[32]; float s = 0.f;
#pragma unroll
        for (int jj = 0; jj < 32; jj++) {
            float a = G[r*32 + jj] * ir * ninv[jj];
            float p = expf(a - 1.f);
            row[jj] = p; s += p;
        }
        float is = 1.f / s;
        float* dst = g_attn1 + b*C8*C8 + r*32;
#pragma unroll
        for (int jj = 0; jj < 32; jj++) dst[jj] = row[jj] * is;
    }
}

// ================= transpose + l2norm: q2n + norms =================
__global__ void __launch_bounds__(128) tnorm_k()
{
    int g = blockIdx.x * 128 + threadIdx.x;
    int b = g >> 12, k = g & (HW-1);
    const float* src = g_t + (size_t)b*C8*HW + k;
    float v[C8]; float ss = 0.f;
#pragma unroll
    for (int c = 0; c < C8; c++) { v[c] = src[(size_t)c*HW]; ss += v[c]*v[c]; }
    float n = sqrtf(ss);
    float inv = 1.f / fmaxf(n, 1e-12f);
    g_norm[g] = ss > 0.f ? n : 0.f;   // v = n * (v*inv) holds exactly for n>=eps; for tiny n keep v/eps * eps'... see below
    // NOTE: reference does v / max(n, eps); ts = v. We reconstruct ts as norm_used * q2n
    // where q2n = v/max(n,eps). To make norm_used * q2n == v exactly-enough, store
    // norm_used = n when n >= eps else n (q2n = v/eps then, and n*q2n = v*(n/eps) ~ 0 anyway, |v| <= n < 1e-12).
    g_norm[g] = n;
    float4* qp  = (float4*)(g_q2n + (size_t)g*C8);
#pragma unroll
    for (int d = 0; d < 8; d++)
        qp[d] = make_float4(v[d*4+0]*inv, v[d*4+1]*inv, v[d*4+2]*inv, v[d*4+3]*inv);
}

// ================= spatial attention: split-K x4, V folded into K =================
__global__ void __launch_bounds__(256, 2) spattn_k()
{
    __shared__ u64  sK[16*128];
    __shared__ float sN[128];

    const int tid = threadIdx.x;
    const int qt = blockIdx.x, ks = blockIdx.y, b = blockIdx.z;
    const int q = qt*256 + tid;

    u64 qv[16];
    {
        const float4* qp = (const float4*)(g_q2n + ((size_t)b*HW + q)*C8);
#pragma unroll
        for (int d = 0; d < 8; d++) {
            float4 t = qp[d];
            qv[2*d]   = pack2(t.x, t.y);
            qv[2*d+1] = pack2(t.z, t.w);
        }
    }
    const u64 zero = pack2(0.f, 0.f);
    u64 acc[16];
#pragma unroll
    for (int d = 0; d < 16; d++) acc[d] = zero;
    float l = 0.f;

    for (int kt = 0; kt < 8; kt++) {
        __syncthreads();
        if (tid < 128) {
            int r = tid;
            const float4* p = (const float4*)(g_q2n + ((size_t)b*HW + ks*1024 + kt*128 + r)*C8);
#pragma unroll
            for (int d = 0; d < 8; d++) {
                float4 t = p[d];
                sK[(2*d)*128 + r]   = pack2(t.x, t.y);
                sK[(2*d+1)*128 + r] = pack2(t.z, t.w);
            }
        } else {
            int r = tid - 128;
            sN[r] = g_norm[(size_t)b*HW + ks*1024 + kt*128 + r];
        }
        __syncthreads();

#pragma unroll 2
        for (int j = 0; j < 128; j++) {
            u64 kk[16];
            u64 s2 = zero;
#pragma unroll
            for (int d = 0; d < 16; d++) {
                kk[d] = sK[d*128 + j];
                s2 = ffma2(qv[d], kk[d], s2);
            }
            float2 sf = unpack2(s2);
            float p = __expf(sf.x + sf.y - 1.f);
            l += p;
            float pn = p * sN[j];
            u64 pp = pack2(pn, pn);
#pragma unroll
            for (int d = 0; d < 16; d++) acc[d] = ffma2(pp, kk[d], acc[d]);
        }
    }

    float2* pa = (float2*)(g_p3 + ((size_t)(b*4 + ks)*HW + q)*C8);
#pragma unroll
    for (int d = 0; d < 16; d++) pa[d] = unpack2(acc[d]);
    g_pl[(size_t)(b*4 + ks)*HW + q] = l;
}

// ================= combine split-K =================
__global__ void __launch_bounds__(256) combine_k()
{
    int g = blockIdx.x * 256 + threadIdx.x;
    int b = g >> 12, q = g & (HW-1);
    float l = 0.f;
#pragma unroll
    for (int ks = 0; ks < 4; ks++) l += g_pl[(size_t)(b*4 + ks)*HW + q];
    float inv = 1.f / l;

    float a[C8];
#pragma unroll
    for (int c = 0; c < C8; c++) a[c] = 0.f;
#pragma unroll
    for (int ks = 0; ks < 4; ks++) {
        const float4* pa = (const float4*)(g_p3 + ((size_t)(b*4 + ks)*HW + q)*C8);
#pragma unroll
        for (int d = 0; d < 8; d++) {
            float4 v = pa[d];
            a[d*4+0] += v.x; a[d*4+1] += v.y; a[d*4+2] += v.z; a[d*4+3] += v.w;
        }
    }
    float* dst = g_out3 + (size_t)b*C8*HW + q;
#pragma unroll
    for (int c = 0; c < C8; c++) dst[(size_t)c*HW] = a[c] * inv;
}

// ================= final: fused chout + 1x1s =================
// out2_i = sum_j A[i][j] t[j];  o5 = b3 + t + w3 @ cat(out2, out3);  out = w4 @ o5 + b4
__global__ void __launch_bounds__(128) final_k(
    const float* __restrict__ w3, const float* __restrict__ b3,
    const float* __restrict__ w4, const float* __restrict__ b4,
    float* __restrict__ out)
{
    __shared__ float sw3[64*32];   // sw3[j*32+o] = w3[o*64+j]
    __shared__ float sw4[Cc*C8];
    __shared__ float sb4[Cc];
    __shared__ float sA[C8*C8];

    const int tid = threadIdx.x;
    const int g = blockIdx.x * 128 + tid;
    const int b = g >> 12, k = g & (HW-1);

    for (int idx = tid; idx < 64*32; idx += 128) {
        int j = idx >> 5, o = idx & 31;
        sw3[j*32 + o] = w3[o*64 + j];
    }
    for (int idx = tid; idx < Cc*C8; idx += 128) sw4[idx] = w4[idx];
    for (int idx = tid; idx < Cc; idx += 128) sb4[idx] = b4[idx];
    for (int idx = tid; idx < C8*C8; idx += 128) sA[idx] = g_attn1[b*C8*C8 + idx];
    __syncthreads();

    // load t values for this pixel
    float tv[C8];
    {
        const float* tb = g_t + (size_t)b*C8*HW + k;
#pragma unroll
        for (int c = 0; c < C8; c++) tv[c] = tb[(size_t)c*HW];
    }
    u64 tvp[16];
#pragma unroll
    for (int d = 0; d < 16; d++) tvp[d] = pack2(tv[2*d], tv[2*d+1]);

    // out2 = A @ tv
    float out2[C8];
#pragma unroll
    for (int i = 0; i < C8; i++) {
        const u64* ar = (const u64*)(sA + i*32);
        u64 s2 = pack2(0.f, 0.f);
#pragma unroll
        for (int d = 0; d < 16; d++) s2 = ffma2(ar[d], tvp[d], s2);
        float2 f = unpack2(s2);
        out2[i] = f.x + f.y;
    }

    // o5 = b3 + t
    u64 o5[16];
#pragma unroll
    for (int d = 0; d < 16; d++)
        o5[d] = pack2(b3[2*d] + tv[2*d], b3[2*d+1] + tv[2*d+1]);

    // o5 += w3[:, 0:32] @ out2
#pragma unroll 4
    for (int j = 0; j < 32; j++) {
        u64 vp = pack2(out2[j], out2[j]);
        const u64* wr = (const u64*)(sw3 + j*32);
#pragma unroll
        for (int d = 0; d < 16; d++) o5[d] = ffma2(vp, wr[d], o5[d]);
    }
    // o5 += w3[:, 32:64] @ out3
    {
        const float* o3 = g_out3 + (size_t)b*C8*HW + k;
#pragma unroll 4
        for (int j = 0; j < 32; j++) {
            float v = __ldg(o3 + (size_t)j*HW);
            u64 vp = pack2(v, v);
            const u64* wr = (const u64*)(sw3 + (32+j)*32);
#pragma unroll
            for (int d = 0; d < 16; d++) o5[d] = ffma2(vp, wr[d], o5[d]);
        }
    }

    float* dst = out + (size_t)b*Cc*HW + k;
#pragma unroll 2
    for (int co = 0; co < Cc; co += 2) {
        const u64* w0 = (const u64*)(sw4 + co*C8);
        const u64* w1 = (const u64*)(sw4 + (co+1)*C8);
        u64 s0 = pack2(0.f, 0.f), s1 = pack2(0.f, 0.f);
#pragma unroll
        for (int d = 0; d < 16; d++) {
            s0 = ffma2(w0[d], o5[d], s0);
            s1 = ffma2(w1[d], o5[d], s1);
        }
        float2 f0 = unpack2(s0), f1 = unpack2(s1);
        dst[(size_t)co*HW]     = f0.x + f0.y + sb4[co];
        dst[(size_t)(co+1)*HW] = f1.x + f1.y + sb4[co+1];
    }
}

// ================= launch =================
extern "C" void kernel_launch(void* const* d_in, const int* in_sizes, int n_in,
                              void* d_out, int out_size)
{
    const float* x      = (const float*)d_in[0];
    const float* w_conv = (const float*)d_in[1];
    const float* b_conv = (const float*)d_in[2];
    const float* w01 = (const float*)d_in[3];
    const float* b01 = (const float*)d_in[4];
    const float* w02 = (const float*)d_in[5];
    const float* b02 = (const float*)d_in[6];
    const float* w11 = (const float*)d_in[7];
    const float* b11 = (const float*)d_in[8];
    const float* w12 = (const float*)d_in[9];
    const float* b12 = (const float*)d_in[10];
    const float* w21 = (const float*)d_in[11];
    const float* b21 = (const float*)d_in[12];
    const float* w22 = (const float*)d_in[13];
    const float* b22 = (const float*)d_in[14];
    const float* w_proj = (const float*)d_in[15];
    const float* b_proj = (const float*)d_in[16];
    const float* w3 = (const float*)d_in[17];
    const float* b3 = (const float*)d_in[18];
    const float* w4 = (const float*)d_in[19];
    const float* b4 = (const float*)d_in[20];
    float* out = (float*)d_out;

    conv3x3_k<<<dim3(2, 32, 4), 256>>>(x, w_conv, b_conv);
    dwfused_k<<<Bn*Cc, 256>>>(w01, b01, w02, b02, w11, b11, w12, b12, w21, b21, w22, b22);
    proj_k   <<<128, 128>>>(w_proj, b_proj);
    gram_k   <<<dim3(32, 4), 256>>>();
    chsoft_k <<<4, 1024>>>();
    tnorm_k  <<<128, 128>>>();
    spattn_k <<<dim3(16, 4, 4), 256>>>();
    combine_k<<<64, 256>>>();
    final_k  <<<128, 128>>>(w3, b3, w4, b4, out);
}

// round 4
// speedup vs baseline: 2.6065x; 1.4107x over previous
#include <cuda_runtime.h>
#include <math.h>
#include <stdint.h>

#define Bn 4
#define Cc 256
#define C8 32
#define Hh 64
#define Ww 64
#define HW 4096

typedef unsigned long long u64;

__device__ __forceinline__ u64 ffma2(u64 a, u64 b, u64 c){
    u64 d; asm("fma.rn.f32x2 %0, %1, %2, %3;" : "=l"(d) : "l"(a), "l"(b), "l"(c)); return d;
}
__device__ __forceinline__ u64 pack2(float lo, float hi){
    u64 d; asm("mov.b64 %0, {%1, %2};" : "=l"(d) : "f"(lo), "f"(hi)); return d;
}
__device__ __forceinline__ float2 unpack2(u64 v){
    float lo, hi; asm("mov.b64 {%0, %1}, %2;" : "=f"(lo), "=f"(hi) : "l"(v));
    return make_float2(lo, hi);
}
__device__ __forceinline__ uint32_t cvt_tf32(float v){
    uint32_t r; asm("cvt.rna.tf32.f32 %0, %1;" : "=r"(r) : "f"(v)); return r;
}
__device__ __forceinline__ void mma_tf32(float4& d, const uint32_t a0, const uint32_t a1,
                                         const uint32_t a2, const uint32_t a3,
                                         const uint32_t b0, const uint32_t b1){
    asm volatile(
      "mma.sync.aligned.m16n8k8.row.col.f32.tf32.tf32.f32 "
      "{%0,%1,%2,%3}, {%4,%5,%6,%7}, {%8,%9}, {%0,%1,%2,%3};"
      : "+f"(d.x), "+f"(d.y), "+f"(d.z), "+f"(d.w)
      : "r"(a0), "r"(a1), "r"(a2), "r"(a3), "r"(b0), "r"(b1));
}

// ---------------- scratch ----------------
__device__ float g_x  [Bn*Cc*HW];
__device__ float g_sum[Bn*Cc*HW];
__device__ float g_t  [Bn*C8*HW];
__device__ float g_attn1[Bn*C8*C8];
__device__ float g_out3[Bn*C8*HW];
__device__ float g_q2n [Bn*HW*C8];
__device__ float g_norm[Bn*HW];
__device__ float g_pgram[Bn*32*C8*C8];
__device__ float g_p3 [Bn*4*HW*C8];
__device__ float g_pl [Bn*4*HW];
__device__ uint32_t g_wh[9*Cc*Cc];   // w transposed [tap][ci][co], tf32 hi
__device__ uint32_t g_wl[9*Cc*Cc];   // tf32 lo

// ================= weight prep: OIHW -> [tap][ci][co] hi/lo tf32 =================
__global__ void __launch_bounds__(256) wprep_k(const float* __restrict__ w)
{
    int idx = blockIdx.x * 256 + threadIdx.x;      // 9*256*256 = 589824
    int co  = idx & 255;
    int ci  = (idx >> 8) & 255;
    int tap = idx >> 16;
    float v = w[((size_t)co*Cc + ci)*9 + tap];
    uint32_t hi = cvt_tf32(v);
    float lo = v - __uint_as_float(hi);
    g_wh[idx] = hi;
    g_wl[idx] = cvt_tf32(lo);
}

// ================= 3x3 conv via m16n8k8 tf32 MMA, 3xTF32 split =================
// grid (32 pb, 2 cog, 4 b), block 256 (8 warps)
// CTA tile: 128 co x 128 px (2 image rows). K = 9 taps x 16-ci chunks.
#define CIB 16
#define SX_STRIDE 273          // per-ci stride for X strip (4 rows x 68, padded)
#define SW_STRIDE 136          // per-ci stride for W tile (128 co, padded)
#define SX_ELEMS (CIB*SX_STRIDE)
#define SW_ELEMS (CIB*SW_STRIDE)

__global__ void __launch_bounds__(256, 2) convmma_k(
    const float* __restrict__ x, const float* __restrict__ bias)
{
    extern __shared__ float smem[];
    float* sXh = smem;
    float* sXl = sXh + SX_ELEMS;
    float* sWh = sXl + SX_ELEMS;
    float* sWl = sWh + SW_ELEMS;

    const int pb = blockIdx.x, cog = blockIdx.y, b = blockIdx.z;
    const int tid  = threadIdx.x;
    const int wid  = tid >> 5, lane = tid & 31;
    const int wm   = wid >> 1, wn = wid & 1;     // warp: co group(32) x px group(64)
    const int gid  = lane >> 2, tig = lane & 3;
    const int h0   = pb * 2;

    float4 acc[2][8];
#pragma unroll
    for (int mt = 0; mt < 2; mt++)
#pragma unroll
        for (int nt = 0; nt < 8; nt++) acc[mt][nt] = make_float4(0.f,0.f,0.f,0.f);

    for (int cib = 0; cib < Cc/CIB; cib++) {
        __syncthreads();
        // ---- stage X strip: 16 ci x 4 rows (h0-1..h0+2) x 66 cols (-1..64), hi/lo
        for (int e = tid; e < CIB*4*66; e += 256) {
            int ci = e / 264;
            int rem = e - ci*264;
            int r = rem / 66;
            int c = rem - r*66;
            int gh = h0 - 1 + r, gw = c - 1;
            float v = 0.f;
            if (gh >= 0 && gh < Hh && gw >= 0 && gw < Ww)
                v = __ldg(x + ((size_t)(b*Cc + cib*CIB + ci))*HW + gh*Ww + gw);
            uint32_t hi = cvt_tf32(v);
            float lo = v - __uint_as_float(hi);
            sXh[ci*SX_STRIDE + r*68 + c] = __uint_as_float(hi);
            sXl[ci*SX_STRIDE + r*68 + c] = __uint_as_float(cvt_tf32(lo));
        }

        for (int tap = 0; tap < 9; tap++) {
            __syncthreads();
            // ---- stage W tile: [ci 16][co 128] from pre-transposed layout
            {
                const uint32_t* srcH = g_wh + (size_t)tap*Cc*Cc + (size_t)(cib*CIB)*Cc + cog*128;
                const uint32_t* srcL = g_wl + (size_t)tap*Cc*Cc + (size_t)(cib*CIB)*Cc + cog*128;
#pragma unroll
                for (int i = 0; i < 8; i++) {
                    int e = tid + i*256;           // 2048 elems
                    int ci = e >> 7, co = e & 127;
                    sWh[ci*SW_STRIDE + co] = __uint_as_float(srcH[(size_t)ci*Cc + co]);
                    sWl[ci*SW_STRIDE + co] = __uint_as_float(srcL[(size_t)ci*Cc + co]);
                }
            }
            __syncthreads();

            const int dh = tap/3 - 1, dw = tap%3 - 1;
            const int bcol = (wn + 1 + dh)*68 + 1 + dw + gid;  // B addr base (row fixed per warp)

#pragma unroll
            for (int kstep = 0; kstep < 2; kstep++) {
                const int kb = kstep*8;
                // A fragments
                uint32_t ah[2][4], al[2][4];
#pragma unroll
                for (int mt = 0; mt < 2; mt++) {
                    int cb = wm*32 + mt*16 + gid;
                    const uint32_t* wh = (const uint32_t*)sWh;
                    const uint32_t* wl = (const uint32_t*)sWl;
                    int r0 = (kb + tig)*SW_STRIDE, r1 = (kb + tig + 4)*SW_STRIDE;
                    ah[mt][0] = wh[r0 + cb];     ah[mt][1] = wh[r0 + cb + 8];
                    ah[mt][2] = wh[r1 + cb];     ah[mt][3] = wh[r1 + cb + 8];
                    al[mt][0] = wl[r0 + cb];     al[mt][1] = wl[r0 + cb + 8];
                    al[mt][2] = wl[r1 + cb];     al[mt][3] = wl[r1 + cb + 8];
                }
                const uint32_t* bh = (const uint32_t*)sXh + (kb + tig)*SX_STRIDE + bcol;
                const uint32_t* bl = (const uint32_t*)sXl + (kb + tig)*SX_STRIDE + bcol;
#pragma unroll
                for (int nt = 0; nt < 8; nt++) {
                    uint32_t bh0 = bh[nt*8], bh1 = bh[4*SX_STRIDE + nt*8];
                    uint32_t bl0 = bl[nt*8], bl1 = bl[4*SX_STRIDE + nt*8];
#pragma unroll
                    for (int mt = 0; mt < 2; mt++) {
                        mma_tf32(acc[mt][nt], ah[mt][0],ah[mt][1],ah[mt][2],ah[mt][3], bh0, bh1);
                        mma_tf32(acc[mt][nt], ah[mt][0],ah[mt][1],ah[mt][2],ah[mt][3], bl0, bl1);
                        mma_tf32(acc[mt][nt], al[mt][0],al[mt][1],al[mt][2],al[mt][3], bh0, bh1);
                    }
                }
            }
        }
    }

    // ---- epilogue: add bias, store to g_x
#pragma unroll
    for (int mt = 0; mt < 2; mt++) {
        int co0 = cog*128 + wm*32 + mt*16 + gid;
        float b0 = __ldg(bias + co0);
        float b1 = __ldg(bias + co0 + 8);
#pragma unroll
        for (int nt = 0; nt < 8; nt++) {
            int px = pb*128 + wn*64 + nt*8 + 2*tig;
            float2* d0 = (float2*)(g_x + ((size_t)(b*Cc + co0))*HW + px);
            float2* d1 = (float2*)(g_x + ((size_t)(b*Cc + co0 + 8))*HW + px);
            float4 a = acc[mt][nt];
            *d0 = make_float2(a.x + b0, a.y + b0);
            *d1 = make_float2(a.z + b1, a.w + b1);
        }
    }
}

// ================= fused depthwise =================
template<int K>
__device__ __forceinline__ void dw_scale(
    const float* xs, float* hb, float out[16],
    const float* __restrict__ wh_c, const float* __restrict__ wv_c,
    float bh, float bv, int w, int h0)
{
    constexpr int P = K/2;
    float whr[K];
#pragma unroll
    for (int k = 0; k < K; k++) whr[k] = __ldg(wh_c + k);
#pragma unroll
    for (int i = 0; i < 16; i++) {
        int h = h0 + i; float s = bh;
#pragma unroll
        for (int k = 0; k < K; k++) {
            int ww = w + k - P;
            if (ww >= 0 && ww < Ww) s += whr[k] * xs[h*Ww + ww];
        }
        hb[h*Ww + w] = s;
    }
    __syncthreads();
    float wvr[K];
#pragma unroll
    for (int k = 0; k < K; k++) wvr[k] = __ldg(wv_c + k);
#pragma unroll
    for (int i = 0; i < 16; i++) {
        int h = h0 + i; float s = bv;
#pragma unroll
        for (int k = 0; k < K; k++) {
            int hh = h + k - P;
            if (hh >= 0 && hh < Hh) s += wvr[k] * hb[hh*Ww + w];
        }
        out[i] += s;
    }
    __syncthreads();
}

__global__ void __launch_bounds__(256) dwfused_k(
    const float* __restrict__ w01, const float* __restrict__ b01,
    const float* __restrict__ w02, const float* __restrict__ b02,
    const float* __restrict__ w11, const float* __restrict__ b11,
    const float* __restrict__ w12, const float* __restrict__ b12,
    const float* __restrict__ w21, const float* __restrict__ b21,
    const float* __restrict__ w22, const float* __restrict__ b22)
{
    __shared__ float xs[HW];
    __shared__ float hb[HW];
    const int plane = blockIdx.x;
    const int c = plane & (Cc-1);
    const int tid = threadIdx.x;
    const float* src = g_x + (size_t)plane*HW;

#pragma unroll
    for (int s = 0; s < 4; s++)
        ((float4*)xs)[tid + s*256] = ((const float4*)src)[tid + s*256];
    __syncthreads();

    const int w  = tid & 63;
    const int h0 = (tid >> 6) * 16;

    float out[16];
#pragma unroll
    for (int i = 0; i < 16; i++) out[i] = xs[(h0+i)*Ww + w];

    dw_scale<7> (xs, hb, out, w01 + c*7,  w02 + c*7,  __ldg(b01+c), __ldg(b02+c), w, h0);
    dw_scale<11>(xs, hb, out, w11 + c*11, w12 + c*11, __ldg(b11+c), __ldg(b12+c), w, h0);
    dw_scale<21>(xs, hb, out, w21 + c*21, w22 + c*21, __ldg(b21+c), __ldg(b22+c), w, h0);

    float* dst = g_sum + (size_t)plane*HW;
#pragma unroll
    for (int i = 0; i < 16; i++) dst[(h0+i)*Ww + w] = out[i];
}

// ================= 1x1 proj 256 -> 32 =================
__global__ void __launch_bounds__(128) proj_k(
    const float* __restrict__ w_proj, const float* __restrict__ b_proj)
{
    __shared__ float ws[Cc*C8];
    const int tid = threadIdx.x;
    for (int idx = tid; idx < Cc*C8; idx += 128) {
        int o = idx >> 8, c = idx & 255;
        ws[c*C8 + o] = w_proj[o*Cc + c];
    }
    __syncthreads();

    const int g = blockIdx.x * 128 + tid;
    const int b = g >> 12, k = g & (HW-1);

    u64 acc[16];
#pragma unroll
    for (int d = 0; d < 16; d++) acc[d] = pack2(b_proj[2*d], b_proj[2*d+1]);

    const float* src = g_sum + (size_t)b*Cc*HW + k;
#pragma unroll 4
    for (int c = 0; c < Cc; c++) {
        float v = __ldg(src + (size_t)c*HW);
        u64 vp = pack2(v, v);
        const u64* wrow = (const u64*)(ws + c*C8);
#pragma unroll
        for (int d = 0; d < 16; d++) acc[d] = ffma2(vp, wrow[d], acc[d]);
    }
    float* dst = g_t + (size_t)b*C8*HW + k;
#pragma unroll
    for (int d = 0; d < 16; d++) {
        float2 v = unpack2(acc[d]);
        dst[(size_t)(2*d)*HW]   = v.x;
        dst[(size_t)(2*d+1)*HW] = v.y;
    }
}

// ================= gram partials =================
__global__ void __launch_bounds__(256) gram_k()
{
    __shared__ float st[32*129];
    const int slab = blockIdx.x, b = blockIdx.y;
    const int tid = threadIdx.x;
    const float* tb = g_t + (size_t)b*C8*HW + slab*128;
    for (int idx = tid; idx < 32*128; idx += 256) {
        int c = idx >> 7, x = idx & 127;
        st[c*129 + x] = tb[(size_t)c*HW + x];
    }
    __syncthreads();

    const int i  = tid >> 3;
    const int j0 = (tid & 7) * 4;
    const float* ri = st + i*129;
    const float* r0 = st + (j0+0)*129;
    const float* r1 = st + (j0+1)*129;
    const float* r2 = st + (j0+2)*129;
    const float* r3 = st + (j0+3)*129;
    float s0=0.f, s1=0.f, s2=0.f, s3=0.f;
#pragma unroll 8
    for (int x = 0; x < 128; x++) {
        float a = ri[x];
        s0 += a*r0[x]; s1 += a*r1[x]; s2 += a*r2[x]; s3 += a*r3[x];
    }
    float* dst = g_pgram + (((size_t)b*32 + slab) << 10) + i*32 + j0;
    dst[0]=s0; dst[1]=s1; dst[2]=s2; dst[3]=s3;
}

// ================= reduce gram + softmax =================
__global__ void __launch_bounds__(1024) chsoft_k()
{
    const int b = blockIdx.x;
    const int tid = threadIdx.x;
    __shared__ float G[1024];
    __shared__ float ninv[32];

    float g = 0.f;
#pragma unroll
    for (int s = 0; s < 32; s++)
        g += g_pgram[(((size_t)b*32 + s) << 10) + tid];
    G[tid] = g;
    if ((tid >> 5) == (tid & 31)) ninv[tid & 31] = 1.f / fmaxf(sqrtf(g), 1e-12f);
    __syncthreads();

    if (tid < 32) {
        int r = tid;
        float ir = ninv[r];
        float row[32]; float s = 0.f;
#pragma unroll
        for (int jj = 0; jj < 32; jj++) {
            float a = G[r*32 + jj] * ir * ninv[jj];
            float p = expf(a - 1.f);
            row[jj] = p; s += p;
        }
        float is = 1.f / s;
        float* dst = g_attn1 + b*C8*C8 + r*32;
#pragma unroll
        for (int jj = 0; jj < 32; jj++) dst[jj] = row[jj] * is;
    }
}

// ================= transpose + l2norm =================
__global__ void __launch_bounds__(128) tnorm_k()
{
    int g = blockIdx.x * 128 + threadIdx.x;
    int b = g >> 12, k = g & (HW-1);
    const float* src = g_t + (size_t)b*C8*HW + k;
    float v[C8]; float ss = 0.f;
#pragma unroll
    for (int c = 0; c < C8; c++) { v[c] = src[(size_t)c*HW]; ss += v[c]*v[c]; }
    float n = sqrtf(ss);
    float inv = 1.f / fmaxf(n, 1e-12f);
    g_norm[g] = n;
    float4* qp  = (float4*)(g_q2n + (size_t)g*C8);
#pragma unroll
    for (int d = 0; d < 8; d++)
        qp[d] = make_float4(v[d*4+0]*inv, v[d*4+1]*inv, v[d*4+2]*inv, v[d*4+3]*inv);
}

// ================= spatial attention =================
__global__ void __launch_bounds__(256, 2) spattn_k()
{
    __shared__ u64  sK[16*128];
    __shared__ float sN[128];

    const int tid = threadIdx.x;
    const int qt = blockIdx.x, ks = blockIdx.y, b = blockIdx.z;
    const int q = qt*256 + tid;

    u64 qv[16];
    {
        const float4* qp = (const float4*)(g_q2n + ((size_t)b*HW + q)*C8);
#pragma unroll
        for (int d = 0; d < 8; d++) {
            float4 t = qp[d];
            qv[2*d]   = pack2(t.x, t.y);
            qv[2*d+1] = pack2(t.z, t.w);
        }
    }
    const u64 zero = pack2(0.f, 0.f);
    u64 acc[16];
#pragma unroll
    for (int d = 0; d < 16; d++) acc[d] = zero;
    float l = 0.f;

    for (int kt = 0; kt < 8; kt++) {
        __syncthreads();
        if (tid < 128) {
            int r = tid;
            const float4* p = (const float4*)(g_q2n + ((size_t)b*HW + ks*1024 + kt*128 + r)*C8);
#pragma unroll
            for (int d = 0; d < 8; d++) {
                float4 t = p[d];
                sK[(2*d)*128 + r]   = pack2(t.x, t.y);
                sK[(2*d+1)*128 + r] = pack2(t.z, t.w);
            }
        } else {
            int r = tid - 128;
            sN[r] = g_norm[(size_t)b*HW + ks*1024 + kt*128 + r];
        }
        __syncthreads();

#pragma unroll 2
        for (int j = 0; j < 128; j++) {
            u64 kk[16];
            u64 s2 = zero;
#pragma unroll
            for (int d = 0; d < 16; d++) {
                kk[d] = sK[d*128 + j];
                s2 = ffma2(qv[d], kk[d], s2);
            }
            float2 sf = unpack2(s2);
            float p = __expf(sf.x + sf.y - 1.f);
            l += p;
            float pn = p * sN[j];
            u64 pp = pack2(pn, pn);
#pragma unroll
            for (int d = 0; d < 16; d++) acc[d] = ffma2(pp, kk[d], acc[d]);
        }
    }

    float2* pa = (float2*)(g_p3 + ((size_t)(b*4 + ks)*HW + q)*C8);
#pragma unroll
    for (int d = 0; d < 16; d++) pa[d] = unpack2(acc[d]);
    g_pl[(size_t)(b*4 + ks)*HW + q] = l;
}

// ================= combine split-K =================
__global__ void __launch_bounds__(256) combine_k()
{
    int g = blockIdx.x * 256 + threadIdx.x;
    int b = g >> 12, q = g & (HW-1);
    float l = 0.f;
#pragma unroll
    for (int ks = 0; ks < 4; ks++) l += g_pl[(size_t)(b*4 + ks)*HW + q];
    float inv = 1.f / l;

    float a[C8];
#pragma unroll
    for (int c = 0; c < C8; c++) a[c] = 0.f;
#pragma unroll
    for (int ks = 0; ks < 4; ks++) {
        const float4* pa = (const float4*)(g_p3 + ((size_t)(b*4 + ks)*HW + q)*C8);
#pragma unroll
        for (int d = 0; d < 8; d++) {
            float4 v = pa[d];
            a[d*4+0] += v.x; a[d*4+1] += v.y; a[d*4+2] += v.z; a[d*4+3] += v.w;
        }
    }
    float* dst = g_out3 + (size_t)b*C8*HW + q;
#pragma unroll
    for (int c = 0; c < C8; c++) dst[(size_t)c*HW] = a[c] * inv;
}

// ================= final =================
__global__ void __launch_bounds__(128) final_k(
    const float* __restrict__ w3, const float* __restrict__ b3,
    const float* __restrict__ w4, const float* __restrict__ b4,
    float* __restrict__ out)
{
    __shared__ float sw3[64*32];
    __shared__ float sw4[Cc*C8];
    __shared__ float sb4[Cc];
    __shared__ float sA[C8*C8];

    const int tid = threadIdx.x;
    const int g = blockIdx.x * 128 + tid;
    const int b = g >> 12, k = g & (HW-1);

    for (int idx = tid; idx < 64*32; idx += 128) {
        int j = idx >> 5, o = idx & 31;
        sw3[j*32 + o] = w3[o*64 + j];
    }
    for (int idx = tid; idx < Cc*C8; idx += 128) sw4[idx] = w4[idx];
    for (int idx = tid; idx < Cc; idx += 128) sb4[idx] = b4[idx];
    for (int idx = tid; idx < C8*C8; idx += 128) sA[idx] = g_attn1[b*C8*C8 + idx];
    __syncthreads();

    float tv[C8];
    {
        const float* tb = g_t + (size_t)b*C8*HW + k;
#pragma unroll
        for (int c = 0; c < C8; c++) tv[c] = tb[(size_t)c*HW];
    }
    u64 tvp[16];
#pragma unroll
    for (int d = 0; d < 16; d++) tvp[d] = pack2(tv[2*d], tv[2*d+1]);

    float out2[C8];
#pragma unroll
    for (int i = 0; i < C8; i++) {
        const u64* ar = (const u64*)(sA + i*32);
        u64 s2 = pack2(0.f, 0.f);
#pragma unroll
        for (int d = 0; d < 16; d++) s2 = ffma2(ar[d], tvp[d], s2);
        float2 f = unpack2(s2);
        out2[i] = f.x + f.y;
    }

    u64 o5[16];
#pragma unroll
    for (int d = 0; d < 16; d++)
        o5[d] = pack2(b3[2*d] + tv[2*d], b3[2*d+1] + tv[2*d+1]);

#pragma unroll 4
    for (int j = 0; j < 32; j++) {
        u64 vp = pack2(out2[j], out2[j]);
        const u64* wr = (const u64*)(sw3 + j*32);
#pragma unroll
        for (int d = 0; d < 16; d++) o5[d] = ffma2(vp, wr[d], o5[d]);
    }
    {
        const float* o3 = g_out3 + (size_t)b*C8*HW + k;
#pragma unroll 4
        for (int j = 0; j < 32; j++) {
            float v = __ldg(o3 + (size_t)j*HW);
            u64 vp = pack2(v, v);
            const u64* wr = (const u64*)(sw3 + (32+j)*32);
#pragma unroll
            for (int d = 0; d < 16; d++) o5[d] = ffma2(vp, wr[d], o5[d]);
        }
    }

    float* dst = out + (size_t)b*Cc*HW + k;
#pragma unroll 2
    for (int co = 0; co < Cc; co += 2) {
        const u64* w0 = (const u64*)(sw4 + co*C8);
        const u64* w1 = (const u64*)(sw4 + (co+1)*C8);
        u64 s0 = pack2(0.f, 0.f), s1 = pack2(0.f, 0.f);
#pragma unroll
        for (int d = 0; d < 16; d++) {
            s0 = ffma2(w0[d], o5[d], s0);
            s1 = ffma2(w1[d], o5[d], s1);
        }
        float2 f0 = unpack2(s0), f1 = unpack2(s1);
        dst[(size_t)co*HW]     = f0.x + f0.y + sb4[co];
        dst[(size_t)(co+1)*HW] = f1.x + f1.y + sb4[co+1];
    }
}

// ================= launch =================
extern "C" void kernel_launch(void* const* d_in, const int* in_sizes, int n_in,
                              void* d_out, int out_size)
{
    const float* x      = (const float*)d_in[0];
    const float* w_conv = (const float*)d_in[1];
    const float* b_conv = (const float*)d_in[2];
    const float* w01 = (const float*)d_in[3];
    const float* b01 = (const float*)d_in[4];
    const float* w02 = (const float*)d_in[5];
    const float* b02 = (const float*)d_in[6];
    const float* w11 = (const float*)d_in[7];
    const float* b11 = (const float*)d_in[8];
    const float* w12 = (const float*)d_in[9];
    const float* b12 = (const float*)d_in[10];
    const float* w21 = (const float*)d_in[11];
    const float* b21 = (const float*)d_in[12];
    const float* w22 = (const float*)d_in[13];
    const float* b22 = (const float*)d_in[14];
    const float* w_proj = (const float*)d_in[15];
    const float* b_proj = (const float*)d_in[16];
    const float* w3 = (const float*)d_in[17];
    const float* b3 = (const float*)d_in[18];
    const float* w4 = (const float*)d_in[19];
    const float* b4 = (const float*)d_in[20];
    float* out = (float*)d_out;

    const int convSmem = (2*SX_ELEMS + 2*SW_ELEMS) * (int)sizeof(float);
    static bool attrSet = false;
    if (!attrSet) {
        cudaFuncSetAttribute(convmma_k, cudaFuncAttributeMaxDynamicSharedMemorySize, convSmem);
        attrSet = true;
    }

    wprep_k  <<<9*Cc*Cc/256, 256>>>(w_conv);
    convmma_k<<<dim3(32, 2, 4), 256, convSmem>>>(x, b_conv);
    dwfused_k<<<Bn*Cc, 256>>>(w01, b01, w02, b02, w11, b11, w12, b12, w21, b21, w22, b22);
    proj_k   <<<128, 128>>>(w_proj, b_proj);
    gram_k   <<<dim3(32, 4), 256>>>();
    chsoft_k <<<4, 1024>>>();
    tnorm_k  <<<128, 128>>>();
    spattn_k <<<dim3(16, 4, 4), 256>>>();
    combine_k<<<64, 256>>>();
    final_k  <<<128, 128>>>(w3, b3, w4, b4, out);
}

// round 5
// speedup vs baseline: 2.6970x; 1.0347x over previous
#include <cuda_runtime.h>
#include <math.h>
#include <stdint.h>

#define Bn 4
#define Cc 256
#define C8 32
#define Hh 64
#define Ww 64
#define HW 4096

typedef unsigned long long u64;

__device__ __forceinline__ u64 ffma2(u64 a, u64 b, u64 c){
    u64 d; asm("fma.rn.f32x2 %0, %1, %2, %3;" : "=l"(d) : "l"(a), "l"(b), "l"(c)); return d;
}
__device__ __forceinline__ u64 pack2(float lo, float hi){
    u64 d; asm("mov.b64 %0, {%1, %2};" : "=l"(d) : "f"(lo), "f"(hi)); return d;
}
__device__ __forceinline__ float2 unpack2(u64 v){
    float lo, hi; asm("mov.b64 {%0, %1}, %2;" : "=f"(lo), "=f"(hi) : "l"(v));
    return make_float2(lo, hi);
}
__device__ __forceinline__ uint32_t cvt_tf32(float v){
    uint32_t r; asm("cvt.rna.tf32.f32 %0, %1;" : "=r"(r) : "f"(v)); return r;
}
__device__ __forceinline__ void mma_tf32(float4& d, const uint32_t a0, const uint32_t a1,
                                         const uint32_t a2, const uint32_t a3,
                                         const uint32_t b0, const uint32_t b1){
    asm volatile(
      "mma.sync.aligned.m16n8k8.row.col.f32.tf32.tf32.f32 "
      "{%0,%1,%2,%3}, {%4,%5,%6,%7}, {%8,%9}, {%0,%1,%2,%3};"
      : "+f"(d.x), "+f"(d.y), "+f"(d.z), "+f"(d.w)
      : "r"(a0), "r"(a1), "r"(a2), "r"(a3), "r"(b0), "r"(b1));
}

// ---------------- scratch ----------------
__device__ float g_x  [Bn*Cc*HW];
__device__ float g_sum[Bn*Cc*HW];
__device__ float g_t  [Bn*C8*HW];
__device__ float g_attn1[Bn*C8*C8];
__device__ float g_q2n [Bn*HW*C8];
__device__ float g_norm[Bn*HW];
__device__ float g_pgram[Bn*32*C8*C8];
__device__ float g_p3 [Bn*4*HW*C8];
__device__ float g_pl [Bn*4*HW];
__device__ uint32_t g_wh[9*Cc*Cc];
__device__ uint32_t g_wl[9*Cc*Cc];

// ================= weight prep =================
__global__ void __launch_bounds__(256) wprep_k(const float* __restrict__ w)
{
    int idx = blockIdx.x * 256 + threadIdx.x;
    int co  = idx & 255;
    int ci  = (idx >> 8) & 255;
    int tap = idx >> 16;
    float v = w[((size_t)co*Cc + ci)*9 + tap];
    uint32_t hi = cvt_tf32(v);
    float lo = v - __uint_as_float(hi);
    g_wh[idx] = hi;
    g_wl[idx] = cvt_tf32(lo);
}

// ================= 3x3 conv via tf32 MMA =================
#define CIB 16
#define SX_STRIDE 273
#define SW_STRIDE 136
#define SX_ELEMS (CIB*SX_STRIDE)
#define SW_ELEMS (CIB*SW_STRIDE)

__global__ void __launch_bounds__(256, 2) convmma_k(
    const float* __restrict__ x, const float* __restrict__ bias)
{
    extern __shared__ float smem[];
    float* sXh = smem;
    float* sXl = sXh + SX_ELEMS;
    float* sWh = sXl + SX_ELEMS;
    float* sWl = sWh + SW_ELEMS;

    const int pb = blockIdx.x, cog = blockIdx.y, b = blockIdx.z;
    const int tid  = threadIdx.x;
    const int wid  = tid >> 5, lane = tid & 31;
    const int wm   = wid >> 1, wn = wid & 1;
    const int gid  = lane >> 2, tig = lane & 3;
    const int h0   = pb * 2;

    float4 acc[2][8];
#pragma unroll
    for (int mt = 0; mt < 2; mt++)
#pragma unroll
        for (int nt = 0; nt < 8; nt++) acc[mt][nt] = make_float4(0.f,0.f,0.f,0.f);

    for (int cib = 0; cib < Cc/CIB; cib++) {
        __syncthreads();
        for (int e = tid; e < CIB*4*66; e += 256) {
            int ci = e / 264;
            int rem = e - ci*264;
            int r = rem / 66;
            int c = rem - r*66;
            int gh = h0 - 1 + r, gw = c - 1;
            float v = 0.f;
            if (gh >= 0 && gh < Hh && gw >= 0 && gw < Ww)
                v = __ldg(x + ((size_t)(b*Cc + cib*CIB + ci))*HW + gh*Ww + gw);
            uint32_t hi = cvt_tf32(v);
            float lo = v - __uint_as_float(hi);
            sXh[ci*SX_STRIDE + r*68 + c] = __uint_as_float(hi);
            sXl[ci*SX_STRIDE + r*68 + c] = __uint_as_float(cvt_tf32(lo));
        }

        for (int tap = 0; tap < 9; tap++) {
            __syncthreads();
            {
                const uint32_t* srcH = g_wh + (size_t)tap*Cc*Cc + (size_t)(cib*CIB)*Cc + cog*128;
                const uint32_t* srcL = g_wl + (size_t)tap*Cc*Cc + (size_t)(cib*CIB)*Cc + cog*128;
#pragma unroll
                for (int i = 0; i < 8; i++) {
                    int e = tid + i*256;
                    int ci = e >> 7, co = e & 127;
                    sWh[ci*SW_STRIDE + co] = __uint_as_float(srcH[(size_t)ci*Cc + co]);
                    sWl[ci*SW_STRIDE + co] = __uint_as_float(srcL[(size_t)ci*Cc + co]);
                }
            }
            __syncthreads();

            const int dh = tap/3 - 1, dw = tap%3 - 1;
            const int bcol = (wn + 1 + dh)*68 + 1 + dw + gid;

#pragma unroll
            for (int kstep = 0; kstep < 2; kstep++) {
                const int kb = kstep*8;
                uint32_t ah[2][4], al[2][4];
#pragma unroll
                for (int mt = 0; mt < 2; mt++) {
                    int cb = wm*32 + mt*16 + gid;
                    const uint32_t* wh = (const uint32_t*)sWh;
                    const uint32_t* wl = (const uint32_t*)sWl;
                    int r0 = (kb + tig)*SW_STRIDE, r1 = (kb + tig + 4)*SW_STRIDE;
                    ah[mt][0] = wh[r0 + cb];     ah[mt][1] = wh[r0 + cb + 8];
                    ah[mt][2] = wh[r1 + cb];     ah[mt][3] = wh[r1 + cb + 8];
                    al[mt][0] = wl[r0 + cb];     al[mt][1] = wl[r0 + cb + 8];
                    al[mt][2] = wl[r1 + cb];     al[mt][3] = wl[r1 + cb + 8];
                }
                const uint32_t* bh = (const uint32_t*)sXh + (kb + tig)*SX_STRIDE + bcol;
                const uint32_t* bl = (const uint32_t*)sXl + (kb + tig)*SX_STRIDE + bcol;
#pragma unroll
                for (int nt = 0; nt < 8; nt++) {
                    uint32_t bh0 = bh[nt*8], bh1 = bh[4*SX_STRIDE + nt*8];
                    uint32_t bl0 = bl[nt*8], bl1 = bl[4*SX_STRIDE + nt*8];
#pragma unroll
                    for (int mt = 0; mt < 2; mt++) {
                        mma_tf32(acc[mt][nt], ah[mt][0],ah[mt][1],ah[mt][2],ah[mt][3], bh0, bh1);
                        mma_tf32(acc[mt][nt], ah[mt][0],ah[mt][1],ah[mt][2],ah[mt][3], bl0, bl1);
                        mma_tf32(acc[mt][nt], al[mt][0],al[mt][1],al[mt][2],al[mt][3], bh0, bh1);
                    }
                }
            }
        }
    }

#pragma unroll
    for (int mt = 0; mt < 2; mt++) {
        int co0 = cog*128 + wm*32 + mt*16 + gid;
        float b0 = __ldg(bias + co0);
        float b1 = __ldg(bias + co0 + 8);
#pragma unroll
        for (int nt = 0; nt < 8; nt++) {
            int px = pb*128 + wn*64 + nt*8 + 2*tig;
            float2* d0 = (float2*)(g_x + ((size_t)(b*Cc + co0))*HW + px);
            float2* d1 = (float2*)(g_x + ((size_t)(b*Cc + co0 + 8))*HW + px);
            float4 a = acc[mt][nt];
            *d0 = make_float2(a.x + b0, a.y + b0);
            *d1 = make_float2(a.z + b1, a.w + b1);
        }
    }
}

// ================= fused depthwise =================
template<int K>
__device__ __forceinline__ void dw_scale(
    const float* xs, float* hb, float out[16],
    const float* __restrict__ wh_c, const float* __restrict__ wv_c,
    float bh, float bv, int w, int h0)
{
    constexpr int P = K/2;
    float whr[K];
#pragma unroll
    for (int k = 0; k < K; k++) whr[k] = __ldg(wh_c + k);
#pragma unroll
    for (int i = 0; i < 16; i++) {
        int h = h0 + i; float s = bh;
#pragma unroll
        for (int k = 0; k < K; k++) {
            int ww = w + k - P;
            if (ww >= 0 && ww < Ww) s += whr[k] * xs[h*Ww + ww];
        }
        hb[h*Ww + w] = s;
    }
    __syncthreads();
    float wvr[K];
#pragma unroll
    for (int k = 0; k < K; k++) wvr[k] = __ldg(wv_c + k);
#pragma unroll
    for (int i = 0; i < 16; i++) {
        int h = h0 + i; float s = bv;
#pragma unroll
        for (int k = 0; k < K; k++) {
            int hh = h + k - P;
            if (hh >= 0 && hh < Hh) s += wvr[k] * hb[hh*Ww + w];
        }
        out[i] += s;
    }
    __syncthreads();
}

__global__ void __launch_bounds__(256) dwfused_k(
    const float* __restrict__ w01, const float* __restrict__ b01,
    const float* __restrict__ w02, const float* __restrict__ b02,
    const float* __restrict__ w11, const float* __restrict__ b11,
    const float* __restrict__ w12, const float* __restrict__ b12,
    const float* __restrict__ w21, const float* __restrict__ b21,
    const float* __restrict__ w22, const float* __restrict__ b22)
{
    __shared__ float xs[HW];
    __shared__ float hb[HW];
    const int plane = blockIdx.x;
    const int c = plane & (Cc-1);
    const int tid = threadIdx.x;
    const float* src = g_x + (size_t)plane*HW;

#pragma unroll
    for (int s = 0; s < 4; s++)
        ((float4*)xs)[tid + s*256] = ((const float4*)src)[tid + s*256];
    __syncthreads();

    const int w  = tid & 63;
    const int h0 = (tid >> 6) * 16;

    float out[16];
#pragma unroll
    for (int i = 0; i < 16; i++) out[i] = xs[(h0+i)*Ww + w];

    dw_scale<7> (xs, hb, out, w01 + c*7,  w02 + c*7,  __ldg(b01+c), __ldg(b02+c), w, h0);
    dw_scale<11>(xs, hb, out, w11 + c*11, w12 + c*11, __ldg(b11+c), __ldg(b12+c), w, h0);
    dw_scale<21>(xs, hb, out, w21 + c*21, w22 + c*21, __ldg(b21+c), __ldg(b22+c), w, h0);

    float* dst = g_sum + (size_t)plane*HW;
#pragma unroll
    for (int i = 0; i < 16; i++) dst[(h0+i)*Ww + w] = out[i];
}

// ================= fused 1x1 proj + transpose + l2norm =================
// grid 256, block 256 = 64 px x 4 channel-slices of 64
__global__ void __launch_bounds__(256, 2) projnorm_k(
    const float* __restrict__ w_proj, const float* __restrict__ b_proj)
{
    __shared__ float ws[Cc*C8];        // ws[c*32+o] = w_proj[o*256+c]
    __shared__ float sred[4*64*33];    // [slice][px][o], padded
    __shared__ float st[64*33];

    const int tid = threadIdx.x;
    for (int idx = tid; idx < Cc*C8; idx += 256) {
        int o = idx >> 8, c = idx & 255;
        ws[c*C8 + o] = w_proj[o*Cc + c];
    }
    __syncthreads();

    const int px = tid & 63, slice = tid >> 6;
    const int g0 = blockIdx.x * 64;
    const int gp = g0 + px;
    const int b = gp >> 12, k = gp & (HW-1);

    u64 acc[16];
    const u64 zero = pack2(0.f, 0.f);
#pragma unroll
    for (int d = 0; d < 16; d++) acc[d] = zero;

    const float* src = g_sum + (size_t)b*Cc*HW + (size_t)slice*64*HW + k;
    const float* wsl = ws + slice*64*C8;
#pragma unroll 4
    for (int c = 0; c < 64; c++) {
        float v = __ldg(src + (size_t)c*HW);
        u64 vp = pack2(v, v);
        const u64* wrow = (const u64*)(wsl + c*C8);
#pragma unroll
        for (int d = 0; d < 16; d++) acc[d] = ffma2(vp, wrow[d], acc[d]);
    }
    float* srow = sred + (slice*64 + px)*33;
#pragma unroll
    for (int d = 0; d < 16; d++) {
        float2 v = unpack2(acc[d]);
        srow[2*d] = v.x; srow[2*d+1] = v.y;
    }
    __syncthreads();

    // reduce 4 slices + bias -> st
    for (int e = tid; e < 64*C8; e += 256) {
        int p = e >> 5, o = e & 31;
        float v = __ldg(b_proj + o)
                + sred[(0*64+p)*33 + o] + sred[(1*64+p)*33 + o]
                + sred[(2*64+p)*33 + o] + sred[(3*64+p)*33 + o];
        st[p*33 + o] = v;
    }
    __syncthreads();

    if (tid < 64) {
        int p = tid;
        int gpp = g0 + p;
        int bb = gpp >> 12, kk = gpp & (HW-1);
        float v[C8]; float ss = 0.f;
#pragma unroll
        for (int c = 0; c < C8; c++) { v[c] = st[p*33 + c]; ss += v[c]*v[c]; }
        float n = sqrtf(ss);
        float inv = 1.f / fmaxf(n, 1e-12f);
        g_norm[gpp] = n;
        float4* qp = (float4*)(g_q2n + (size_t)gpp*C8);
#pragma unroll
        for (int d = 0; d < 8; d++)
            qp[d] = make_float4(v[d*4+0]*inv, v[d*4+1]*inv, v[d*4+2]*inv, v[d*4+3]*inv);
        float* tb = g_t + (size_t)bb*C8*HW + kk;
#pragma unroll
        for (int c = 0; c < C8; c++) tb[(size_t)c*HW] = v[c];
    }
}

// ================= gram partials =================
__global__ void __launch_bounds__(256) gram_k()
{
    __shared__ float st[32*129];
    const int slab = blockIdx.x, b = blockIdx.y;
    const int tid = threadIdx.x;
    const float* tb = g_t + (size_t)b*C8*HW + slab*128;
    for (int idx = tid; idx < 32*128; idx += 256) {
        int c = idx >> 7, x = idx & 127;
        st[c*129 + x] = tb[(size_t)c*HW + x];
    }
    __syncthreads();

    const int i  = tid >> 3;
    const int j0 = (tid & 7) * 4;
    const float* ri = st + i*129;
    const float* r0 = st + (j0+0)*129;
    const float* r1 = st + (j0+1)*129;
    const float* r2 = st + (j0+2)*129;
    const float* r3 = st + (j0+3)*129;
    float s0=0.f, s1=0.f, s2=0.f, s3=0.f;
#pragma unroll 8
    for (int x = 0; x < 128; x++) {
        float a = ri[x];
        s0 += a*r0[x]; s1 += a*r1[x]; s2 += a*r2[x]; s3 += a*r3[x];
    }
    float* dst = g_pgram + (((size_t)b*32 + slab) << 10) + i*32 + j0;
    dst[0]=s0; dst[1]=s1; dst[2]=s2; dst[3]=s3;
}

// ================= reduce gram + softmax =================
__global__ void __launch_bounds__(1024) chsoft_k()
{
    const int b = blockIdx.x;
    const int tid = threadIdx.x;
    __shared__ float G[1024];
    __shared__ float ninv[32];

    float g = 0.f;
#pragma unroll
    for (int s = 0; s < 32; s++)
        g += g_pgram[(((size_t)b*32 + s) << 10) + tid];
    G[tid] = g;
    if ((tid >> 5) == (tid & 31)) ninv[tid & 31] = 1.f / fmaxf(sqrtf(g), 1e-12f);
    __syncthreads();

    if (tid < 32) {
        int r = tid;
        float ir = ninv[r];
        float row[32]; float s = 0.f;
#pragma unroll
        for (int jj = 0; jj < 32; jj++) {
            float a = G[r*32 + jj] * ir * ninv[jj];
            float p = expf(a - 1.f);
            row[jj] = p; s += p;
        }
        float is = 1.f / s;
        float* dst = g_attn1 + b*C8*C8 + r*32;
#pragma unroll
        for (int jj = 0; jj < 32; jj++) dst[jj] = row[jj] * is;
    }
}

// ================= spatial attention =================
__global__ void __launch_bounds__(256, 2) spattn_k()
{
    __shared__ u64  sK[16*128];
    __shared__ float sN[128];

    const int tid = threadIdx.x;
    const int qt = blockIdx.x, ks = blockIdx.y, b = blockIdx.z;
    const int q = qt*256 + tid;

    u64 qv[16];
    {
        const float4* qp = (const float4*)(g_q2n + ((size_t)b*HW + q)*C8);
#pragma unroll
        for (int d = 0; d < 8; d++) {
            float4 t = qp[d];
            qv[2*d]   = pack2(t.x, t.y);
            qv[2*d+1] = pack2(t.z, t.w);
        }
    }
    const u64 zero = pack2(0.f, 0.f);
    u64 acc[16];
#pragma unroll
    for (int d = 0; d < 16; d++) acc[d] = zero;
    float l = 0.f;

    for (int kt = 0; kt < 8; kt++) {
        __syncthreads();
        if (tid < 128) {
            int r = tid;
            const float4* p = (const float4*)(g_q2n + ((size_t)b*HW + ks*1024 + kt*128 + r)*C8);
#pragma unroll
            for (int d = 0; d < 8; d++) {
                float4 t = p[d];
                sK[(2*d)*128 + r]   = pack2(t.x, t.y);
                sK[(2*d+1)*128 + r] = pack2(t.z, t.w);
            }
        } else {
            int r = tid - 128;
            sN[r] = g_norm[(size_t)b*HW + ks*1024 + kt*128 + r];
        }
        __syncthreads();

#pragma unroll 2
        for (int j = 0; j < 128; j++) {
            u64 kk[16];
            u64 s2 = zero;
#pragma unroll
            for (int d = 0; d < 16; d++) {
                kk[d] = sK[d*128 + j];
                s2 = ffma2(qv[d], kk[d], s2);
            }
            float2 sf = unpack2(s2);
            float p = __expf(sf.x + sf.y - 1.f);
            l += p;
            float pn = p * sN[j];
            u64 pp = pack2(pn, pn);
#pragma unroll
            for (int d = 0; d < 16; d++) acc[d] = ffma2(pp, kk[d], acc[d]);
        }
    }

    float2* pa = (float2*)(g_p3 + ((size_t)(b*4 + ks)*HW + q)*C8);
#pragma unroll
    for (int d = 0; d < 16; d++) pa[d] = unpack2(acc[d]);
    g_pl[(size_t)(b*4 + ks)*HW + q] = l;
}

// ================= final: fused combine + chout + 1x1s =================
// grid 256, block 256 = 64 px x 4 co-slices of 64
__global__ void __launch_bounds__(256, 2) final_k(
    const float* __restrict__ w3, const float* __restrict__ b3,
    const float* __restrict__ w4, const float* __restrict__ b4,
    float* __restrict__ out)
{
    __shared__ float sw3[64*32];   // sw3[j*32+o] = w3[o*64+j]
    __shared__ float sw4[Cc*C8];
    __shared__ float sb4[Cc];
    __shared__ float sA[C8*C8];
    __shared__ float so3[64*33];

    const int tid = threadIdx.x;
    const int px = tid & 63, coh = tid >> 6;
    const int g0 = blockIdx.x * 64;
    const int gp = g0 + px;
    const int b = gp >> 12, k = gp & (HW-1);

    for (int idx = tid; idx < 64*32; idx += 256) {
        int j = idx >> 5, o = idx & 31;
        sw3[j*32 + o] = w3[o*64 + j];
    }
    for (int idx = tid; idx < Cc*C8; idx += 256) sw4[idx] = w4[idx];
    if (tid < Cc) sb4[tid] = b4[tid];
    for (int idx = tid; idx < C8*C8; idx += 256) sA[idx] = g_attn1[b*C8*C8 + idx];

    // combine split-K partials -> so3 (64 threads, one per pixel)
    if (coh == 0) {
        float l = 0.f;
#pragma unroll
        for (int ks = 0; ks < 4; ks++) l += g_pl[(size_t)(b*4 + ks)*HW + k];
        float inv = 1.f / l;
        float a[C8];
#pragma unroll
        for (int c = 0; c < C8; c++) a[c] = 0.f;
#pragma unroll
        for (int ks = 0; ks < 4; ks++) {
            const float4* pa = (const float4*)(g_p3 + ((size_t)(b*4 + ks)*HW + k)*C8);
#pragma unroll
            for (int d = 0; d < 8; d++) {
                float4 v = pa[d];
                a[d*4+0] += v.x; a[d*4+1] += v.y; a[d*4+2] += v.z; a[d*4+3] += v.w;
            }
        }
#pragma unroll
        for (int c = 0; c < C8; c++) so3[px*33 + c] = a[c] * inv;
    }
    __syncthreads();

    // load t for this pixel
    float tv[C8];
    {
        const float* tb = g_t + (size_t)b*C8*HW + k;
#pragma unroll
        for (int c = 0; c < C8; c++) tv[c] = tb[(size_t)c*HW];
    }
    u64 tvp[16];
#pragma unroll
    for (int d = 0; d < 16; d++) tvp[d] = pack2(tv[2*d], tv[2*d+1]);

    // out2 = A @ tv
    float out2[C8];
#pragma unroll
    for (int i = 0; i < C8; i++) {
        const u64* ar = (const u64*)(sA + i*32);
        u64 s2 = pack2(0.f, 0.f);
#pragma unroll
        for (int d = 0; d < 16; d++) s2 = ffma2(ar[d], tvp[d], s2);
        float2 f = unpack2(s2);
        out2[i] = f.x + f.y;
    }

    // o5 = b3 + t + w3 @ cat(out2, out3)
    u64 o5[16];
#pragma unroll
    for (int d = 0; d < 16; d++)
        o5[d] = pack2(__ldg(b3 + 2*d) + tv[2*d], __ldg(b3 + 2*d+1) + tv[2*d+1]);

#pragma unroll 4
    for (int j = 0; j < 32; j++) {
        u64 vp = pack2(out2[j], out2[j]);
        const u64* wr = (const u64*)(sw3 + j*32);
#pragma unroll
        for (int d = 0; d < 16; d++) o5[d] = ffma2(vp, wr[d], o5[d]);
    }
#pragma unroll 4
    for (int j = 0; j < 32; j++) {
        float v = so3[px*33 + j];
        u64 vp = pack2(v, v);
        const u64* wr = (const u64*)(sw3 + (32+j)*32);
#pragma unroll
        for (int d = 0; d < 16; d++) o5[d] = ffma2(vp, wr[d], o5[d]);
    }

    // out[co0..co0+64) for this pixel
    const int co0 = coh * 64;
    float* dst = out + (size_t)b*Cc*HW + (size_t)co0*HW + k;
#pragma unroll 2
    for (int cc = 0; cc < 64; cc += 2) {
        const u64* w0 = (const u64*)(sw4 + (co0+cc)*C8);
        const u64* w1 = (const u64*)(sw4 + (co0+cc+1)*C8);
        u64 s0 = pack2(0.f, 0.f), s1 = pack2(0.f, 0.f);
#pragma unroll
        for (int d = 0; d < 16; d++) {
            s0 = ffma2(w0[d], o5[d], s0);
            s1 = ffma2(w1[d], o5[d], s1);
        }
        float2 f0 = unpack2(s0), f1 = unpack2(s1);
        dst[(size_t)cc*HW]     = f0.x + f0.y + sb4[co0+cc];
        dst[(size_t)(cc+1)*HW] = f1.x + f1.y + sb4[co0+cc+1];
    }
}

// ================= launch =================
extern "C" void kernel_launch(void* const* d_in, const int* in_sizes, int n_in,
                              void* d_out, int out_size)
{
    const float* x      = (const float*)d_in[0];
    const float* w_conv = (const float*)d_in[1];
    const float* b_conv = (const float*)d_in[2];
    const float* w01 = (const float*)d_in[3];
    const float* b01 = (const float*)d_in[4];
    const float* w02 = (const float*)d_in[5];
    const float* b02 = (const float*)d_in[6];
    const float* w11 = (const float*)d_in[7];
    const float* b11 = (const float*)d_in[8];
    const float* w12 = (const float*)d_in[9];
    const float* b12 = (const float*)d_in[10];
    const float* w21 = (const float*)d_in[11];
    const float* b21 = (const float*)d_in[12];
    const float* w22 = (const float*)d_in[13];
    const float* b22 = (const float*)d_in[14];
    const float* w_proj = (const float*)d_in[15];
    const float* b_proj = (const float*)d_in[16];
    const float* w3 = (const float*)d_in[17];
    const float* b3 = (const float*)d_in[18];
    const float* w4 = (const float*)d_in[19];
    const float* b4 = (const float*)d_in[20];
    float* out = (float*)d_out;

    const int convSmem = (2*SX_ELEMS + 2*SW_ELEMS) * (int)sizeof(float);
    static bool attrSet = false;
    if (!attrSet) {
        cudaFuncSetAttribute(convmma_k, cudaFuncAttributeMaxDynamicSharedMemorySize, convSmem);
        attrSet = true;
    }

    wprep_k   <<<9*Cc*Cc/256, 256>>>(w_conv);
    convmma_k <<<dim3(32, 2, 4), 256, convSmem>>>(x, b_conv);
    dwfused_k <<<Bn*Cc, 256>>>(w01, b01, w02, b02, w11, b11, w12, b12, w21, b21, w22, b22);
    projnorm_k<<<256, 256>>>(w_proj, b_proj);
    gram_k    <<<dim3(32, 4), 256>>>();
    chsoft_k  <<<4, 1024>>>();
    spattn_k  <<<dim3(16, 4, 4), 256>>>();
    final_k   <<<256, 256>>>(w3, b3, w4, b4, out);
}

// round 6
// speedup vs baseline: 3.0441x; 1.1287x over previous
#include <cuda_runtime.h>
#include <math.h>
#include <stdint.h>

#define Bn 4
#define Cc 256
#define C8 32
#define Hh 64
#define Ww 64
#define HW 4096

typedef unsigned long long u64;

__device__ __forceinline__ u64 ffma2(u64 a, u64 b, u64 c){
    u64 d; asm("fma.rn.f32x2 %0, %1, %2, %3;" : "=l"(d) : "l"(a), "l"(b), "l"(c)); return d;
}
__device__ __forceinline__ u64 pack2(float lo, float hi){
    u64 d; asm("mov.b64 %0, {%1, %2};" : "=l"(d) : "f"(lo), "f"(hi)); return d;
}
__device__ __forceinline__ float2 unpack2(u64 v){
    float lo, hi; asm("mov.b64 {%0, %1}, %2;" : "=f"(lo), "=f"(hi) : "l"(v));
    return make_float2(lo, hi);
}
__device__ __forceinline__ uint32_t cvt_tf32(float v){
    uint32_t r; asm("cvt.rna.tf32.f32 %0, %1;" : "=r"(r) : "f"(v)); return r;
}
__device__ __forceinline__ void mma_tf32(float4& d, const uint32_t a0, const uint32_t a1,
                                         const uint32_t a2, const uint32_t a3,
                                         const uint32_t b0, const uint32_t b1){
    asm volatile(
      "mma.sync.aligned.m16n8k8.row.col.f32.tf32.tf32.f32 "
      "{%0,%1,%2,%3}, {%4,%5,%6,%7}, {%8,%9}, {%0,%1,%2,%3};"
      : "+f"(d.x), "+f"(d.y), "+f"(d.z), "+f"(d.w)
      : "r"(a0), "r"(a1), "r"(a2), "r"(a3), "r"(b0), "r"(b1));
}

// ---------------- scratch ----------------
__device__ float g_x  [Bn*Cc*HW];
__device__ float g_sum[Bn*Cc*HW];
__device__ float g_t  [Bn*C8*HW];
__device__ float g_attn1[Bn*C8*C8];
__device__ float g_out3[Bn*C8*HW];
__device__ float g_q2n [Bn*HW*C8];
__device__ float g_norm[Bn*HW];
__device__ float g_pgram[Bn*32*C8*C8];
__device__ uint32_t g_wh[9*Cc*Cc];
__device__ uint32_t g_wl[9*Cc*Cc];

// ================= weight prep =================
__global__ void __launch_bounds__(256) wprep_k(const float* __restrict__ w)
{
    int idx = blockIdx.x * 256 + threadIdx.x;
    int co  = idx & 255;
    int ci  = (idx >> 8) & 255;
    int tap = idx >> 16;
    float v = w[((size_t)co*Cc + ci)*9 + tap];
    uint32_t hi = cvt_tf32(v);
    float lo = v - __uint_as_float(hi);
    g_wh[idx] = hi;
    g_wl[idx] = cvt_tf32(lo);
}

// ================= 3x3 conv via tf32 MMA =================
#define CIB 16
#define SX_STRIDE 273
#define SW_STRIDE 136
#define SX_ELEMS (CIB*SX_STRIDE)
#define SW_ELEMS (CIB*SW_STRIDE)

__global__ void __launch_bounds__(256, 2) convmma_k(
    const float* __restrict__ x, const float* __restrict__ bias)
{
    extern __shared__ float smem[];
    float* sXh = smem;
    float* sXl = sXh + SX_ELEMS;
    float* sWh = sXl + SX_ELEMS;
    float* sWl = sWh + SW_ELEMS;

    const int pb = blockIdx.x, cog = blockIdx.y, b = blockIdx.z;
    const int tid  = threadIdx.x;
    const int wid  = tid >> 5, lane = tid & 31;
    const int wm   = wid >> 1, wn = wid & 1;
    const int gid  = lane >> 2, tig = lane & 3;
    const int h0   = pb * 2;

    float4 acc[2][8];
#pragma unroll
    for (int mt = 0; mt < 2; mt++)
#pragma unroll
        for (int nt = 0; nt < 8; nt++) acc[mt][nt] = make_float4(0.f,0.f,0.f,0.f);

    for (int cib = 0; cib < Cc/CIB; cib++) {
        __syncthreads();
        for (int e = tid; e < CIB*4*66; e += 256) {
            int ci = e / 264;
            int rem = e - ci*264;
            int r = rem / 66;
            int c = rem - r*66;
            int gh = h0 - 1 + r, gw = c - 1;
            float v = 0.f;
            if (gh >= 0 && gh < Hh && gw >= 0 && gw < Ww)
                v = __ldg(x + ((size_t)(b*Cc + cib*CIB + ci))*HW + gh*Ww + gw);
            uint32_t hi = cvt_tf32(v);
            float lo = v - __uint_as_float(hi);
            sXh[ci*SX_STRIDE + r*68 + c] = __uint_as_float(hi);
            sXl[ci*SX_STRIDE + r*68 + c] = __uint_as_float(cvt_tf32(lo));
        }

        for (int tap = 0; tap < 9; tap++) {
            __syncthreads();
            {
                const uint32_t* srcH = g_wh + (size_t)tap*Cc*Cc + (size_t)(cib*CIB)*Cc + cog*128;
                const uint32_t* srcL = g_wl + (size_t)tap*Cc*Cc + (size_t)(cib*CIB)*Cc + cog*128;
#pragma unroll
                for (int i = 0; i < 8; i++) {
                    int e = tid + i*256;
                    int ci = e >> 7, co = e & 127;
                    sWh[ci*SW_STRIDE + co] = __uint_as_float(srcH[(size_t)ci*Cc + co]);
                    sWl[ci*SW_STRIDE + co] = __uint_as_float(srcL[(size_t)ci*Cc + co]);
                }
            }
            __syncthreads();

            const int dh = tap/3 - 1, dw = tap%3 - 1;
            const int bcol = (wn + 1 + dh)*68 + 1 + dw + gid;

#pragma unroll
            for (int kstep = 0; kstep < 2; kstep++) {
                const int kb = kstep*8;
                uint32_t ah[2][4], al[2][4];
#pragma unroll
                for (int mt = 0; mt < 2; mt++) {
                    int cb = wm*32 + mt*16 + gid;
                    const uint32_t* wh = (const uint32_t*)sWh;
                    const uint32_t* wl = (const uint32_t*)sWl;
                    int r0 = (kb + tig)*SW_STRIDE, r1 = (kb + tig + 4)*SW_STRIDE;
                    ah[mt][0] = wh[r0 + cb];     ah[mt][1] = wh[r0 + cb + 8];
                    ah[mt][2] = wh[r1 + cb];     ah[mt][3] = wh[r1 + cb + 8];
                    al[mt][0] = wl[r0 + cb];     al[mt][1] = wl[r0 + cb + 8];
                    al[mt][2] = wl[r1 + cb];     al[mt][3] = wl[r1 + cb + 8];
                }
                const uint32_t* bh = (const uint32_t*)sXh + (kb + tig)*SX_STRIDE + bcol;
                const uint32_t* bl = (const uint32_t*)sXl + (kb + tig)*SX_STRIDE + bcol;
#pragma unroll
                for (int nt = 0; nt < 8; nt++) {
                    uint32_t bh0 = bh[nt*8], bh1 = bh[4*SX_STRIDE + nt*8];
                    uint32_t bl0 = bl[nt*8], bl1 = bl[4*SX_STRIDE + nt*8];
#pragma unroll
                    for (int mt = 0; mt < 2; mt++) {
                        mma_tf32(acc[mt][nt], ah[mt][0],ah[mt][1],ah[mt][2],ah[mt][3], bh0, bh1);
                        mma_tf32(acc[mt][nt], ah[mt][0],ah[mt][1],ah[mt][2],ah[mt][3], bl0, bl1);
                        mma_tf32(acc[mt][nt], al[mt][0],al[mt][1],al[mt][2],al[mt][3], bh0, bh1);
                    }
                }
            }
        }
    }

#pragma unroll
    for (int mt = 0; mt < 2; mt++) {
        int co0 = cog*128 + wm*32 + mt*16 + gid;
        float b0 = __ldg(bias + co0);
        float b1 = __ldg(bias + co0 + 8);
#pragma unroll
        for (int nt = 0; nt < 8; nt++) {
            int px = pb*128 + wn*64 + nt*8 + 2*tig;
            float2* d0 = (float2*)(g_x + ((size_t)(b*Cc + co0))*HW + px);
            float2* d1 = (float2*)(g_x + ((size_t)(b*Cc + co0 + 8))*HW + px);
            float4 a = acc[mt][nt];
            *d0 = make_float2(a.x + b0, a.y + b0);
            *d1 = make_float2(a.z + b1, a.w + b1);
        }
    }
}

// ================= fused depthwise =================
template<int K>
__device__ __forceinline__ void dw_scale(
    const float* xs, float* hb, float out[16],
    const float* __restrict__ wh_c, const float* __restrict__ wv_c,
    float bh, float bv, int w, int h0)
{
    constexpr int P = K/2;
    float whr[K];
#pragma unroll
    for (int k = 0; k < K; k++) whr[k] = __ldg(wh_c + k);
#pragma unroll
    for (int i = 0; i < 16; i++) {
        int h = h0 + i; float s = bh;
#pragma unroll
        for (int k = 0; k < K; k++) {
            int ww = w + k - P;
            if (ww >= 0 && ww < Ww) s += whr[k] * xs[h*Ww + ww];
        }
        hb[h*Ww + w] = s;
    }
    __syncthreads();
    float wvr[K];
#pragma unroll
    for (int k = 0; k < K; k++) wvr[k] = __ldg(wv_c + k);
#pragma unroll
    for (int i = 0; i < 16; i++) {
        int h = h0 + i; float s = bv;
#pragma unroll
        for (int k = 0; k < K; k++) {
            int hh = h + k - P;
            if (hh >= 0 && hh < Hh) s += wvr[k] * hb[hh*Ww + w];
        }
        out[i] += s;
    }
    __syncthreads();
}

__global__ void __launch_bounds__(256) dwfused_k(
    const float* __restrict__ w01, const float* __restrict__ b01,
    const float* __restrict__ w02, const float* __restrict__ b02,
    const float* __restrict__ w11, const float* __restrict__ b11,
    const float* __restrict__ w12, const float* __restrict__ b12,
    const float* __restrict__ w21, const float* __restrict__ b21,
    const float* __restrict__ w22, const float* __restrict__ b22)
{
    __shared__ float xs[HW];
    __shared__ float hb[HW];
    const int plane = blockIdx.x;
    const int c = plane & (Cc-1);
    const int tid = threadIdx.x;
    const float* src = g_x + (size_t)plane*HW;

#pragma unroll
    for (int s = 0; s < 4; s++)
        ((float4*)xs)[tid + s*256] = ((const float4*)src)[tid + s*256];
    __syncthreads();

    const int w  = tid & 63;
    const int h0 = (tid >> 6) * 16;

    float out[16];
#pragma unroll
    for (int i = 0; i < 16; i++) out[i] = xs[(h0+i)*Ww + w];

    dw_scale<7> (xs, hb, out, w01 + c*7,  w02 + c*7,  __ldg(b01+c), __ldg(b02+c), w, h0);
    dw_scale<11>(xs, hb, out, w11 + c*11, w12 + c*11, __ldg(b11+c), __ldg(b12+c), w, h0);
    dw_scale<21>(xs, hb, out, w21 + c*21, w22 + c*21, __ldg(b21+c), __ldg(b22+c), w, h0);

    float* dst = g_sum + (size_t)plane*HW;
#pragma unroll
    for (int i = 0; i < 16; i++) dst[(h0+i)*Ww + w] = out[i];
}

// ================= fused 1x1 proj + transpose + l2norm =================
__global__ void __launch_bounds__(256, 2) projnorm_k(
    const float* __restrict__ w_proj, const float* __restrict__ b_proj)
{
    __shared__ float ws[Cc*C8];
    __shared__ float sred[4*64*33];
    __shared__ float st[64*33];

    const int tid = threadIdx.x;
    for (int idx = tid; idx < Cc*C8; idx += 256) {
        int o = idx >> 8, c = idx & 255;
        ws[c*C8 + o] = w_proj[o*Cc + c];
    }
    __syncthreads();

    const int px = tid & 63, slice = tid >> 6;
    const int g0 = blockIdx.x * 64;
    const int gp = g0 + px;
    const int b = gp >> 12, k = gp & (HW-1);

    u64 acc[16];
    const u64 zero = pack2(0.f, 0.f);
#pragma unroll
    for (int d = 0; d < 16; d++) acc[d] = zero;

    const float* src = g_sum + (size_t)b*Cc*HW + (size_t)slice*64*HW + k;
    const float* wsl = ws + slice*64*C8;
#pragma unroll 4
    for (int c = 0; c < 64; c++) {
        float v = __ldg(src + (size_t)c*HW);
        u64 vp = pack2(v, v);
        const u64* wrow = (const u64*)(wsl + c*C8);
#pragma unroll
        for (int d = 0; d < 16; d++) acc[d] = ffma2(vp, wrow[d], acc[d]);
    }
    float* srow = sred + (slice*64 + px)*33;
#pragma unroll
    for (int d = 0; d < 16; d++) {
        float2 v = unpack2(acc[d]);
        srow[2*d] = v.x; srow[2*d+1] = v.y;
    }
    __syncthreads();

    for (int e = tid; e < 64*C8; e += 256) {
        int p = e >> 5, o = e & 31;
        float v = __ldg(b_proj + o)
                + sred[(0*64+p)*33 + o] + sred[(1*64+p)*33 + o]
                + sred[(2*64+p)*33 + o] + sred[(3*64+p)*33 + o];
        st[p*33 + o] = v;
    }
    __syncthreads();

    if (tid < 64) {
        int p = tid;
        int gpp = g0 + p;
        int bb = gpp >> 12, kk = gpp & (HW-1);
        float v[C8]; float ss = 0.f;
#pragma unroll
        for (int c = 0; c < C8; c++) { v[c] = st[p*33 + c]; ss += v[c]*v[c]; }
        float n = sqrtf(ss);
        float inv = 1.f / fmaxf(n, 1e-12f);
        g_norm[gpp] = n;
        float4* qp = (float4*)(g_q2n + (size_t)gpp*C8);
#pragma unroll
        for (int d = 0; d < 8; d++)
            qp[d] = make_float4(v[d*4+0]*inv, v[d*4+1]*inv, v[d*4+2]*inv, v[d*4+3]*inv);
        float* tb = g_t + (size_t)bb*C8*HW + kk;
#pragma unroll
        for (int c = 0; c < C8; c++) tb[(size_t)c*HW] = v[c];
    }
}

// ================= gram partials =================
__global__ void __launch_bounds__(256) gram_k()
{
    __shared__ float st[32*129];
    const int slab = blockIdx.x, b = blockIdx.y;
    const int tid = threadIdx.x;
    const float* tb = g_t + (size_t)b*C8*HW + slab*128;
    for (int idx = tid; idx < 32*128; idx += 256) {
        int c = idx >> 7, x = idx & 127;
        st[c*129 + x] = tb[(size_t)c*HW + x];
    }
    __syncthreads();

    const int i  = tid >> 3;
    const int j0 = (tid & 7) * 4;
    const float* ri = st + i*129;
    const float* r0 = st + (j0+0)*129;
    const float* r1 = st + (j0+1)*129;
    const float* r2 = st + (j0+2)*129;
    const float* r3 = st + (j0+3)*129;
    float s0=0.f, s1=0.f, s2=0.f, s3=0.f;
#pragma unroll 8
    for (int x = 0; x < 128; x++) {
        float a = ri[x];
        s0 += a*r0[x]; s1 += a*r1[x]; s2 += a*r2[x]; s3 += a*r3[x];
    }
    float* dst = g_pgram + (((size_t)b*32 + slab) << 10) + i*32 + j0;
    dst[0]=s0; dst[1]=s1; dst[2]=s2; dst[3]=s3;
}

// ================= reduce gram + softmax =================
__global__ void __launch_bounds__(1024) chsoft_k()
{
    const int b = blockIdx.x;
    const int tid = threadIdx.x;
    __shared__ float G[1024];
    __shared__ float ninv[32];

    float g = 0.f;
#pragma unroll
    for (int s = 0; s < 32; s++)
        g += g_pgram[(((size_t)b*32 + s) << 10) + tid];
    G[tid] = g;
    if ((tid >> 5) == (tid & 31)) ninv[tid & 31] = 1.f / fmaxf(sqrtf(g), 1e-12f);
    __syncthreads();

    if (tid < 32) {
        int r = tid;
        float ir = ninv[r];
        float row[32]; float s = 0.f;
#pragma unroll
        for (int jj = 0; jj < 32; jj++) {
            float a = G[r*32 + jj] * ir * ninv[jj];
            float p = expf(a - 1.f);
            row[jj] = p; s += p;
        }
        float is = 1.f / s;
        float* dst = g_attn1 + b*C8*C8 + r*32;
#pragma unroll
        for (int jj = 0; jj < 32; jj++) dst[jj] = row[jj] * is;
    }
}

// ================= flash spatial attention on tensor cores =================
// grid (32 q-tiles of 128, 4 b), block 256 (8 warps x 16 q-rows)
#define SP_KN 36     // [key][dim] stride
#define SP_KD 132    // [dim][key] stride
#define SP_P  133    // per-warp P stride

__global__ void __launch_bounds__(256, 1) spflash_k()
{
    extern __shared__ float sm[];
    float* sKnh = sm;                       // 128*36
    float* sKnl = sKnh + 128*SP_KN;
    float* sKdh = sKnl + 128*SP_KN;         // 32*132
    float* sKdl = sKdh + 32*SP_KD;
    float* sP   = sKdl + 32*SP_KD;          // 8*16*133
    float* sN   = sP + 8*16*SP_P;           // 128

    const int tid = threadIdx.x;
    const int w = tid >> 5, lane = tid & 31;
    const int gid = lane >> 2, tig = lane & 3;
    const int b = blockIdx.y;
    const int qb = blockIdx.x*128 + w*16;

    // Q A-fragments (hi/lo) held in registers for the whole kernel
    uint32_t qh[4][4], ql[4][4];
    {
        const float* Q = g_q2n + ((size_t)b*HW + qb)*C8;
#pragma unroll
        for (int ks = 0; ks < 4; ks++) {
            float f[4];
            f[0] = Q[(size_t)gid*32      + ks*8 + tig];
            f[1] = Q[(size_t)(gid+8)*32  + ks*8 + tig];
            f[2] = Q[(size_t)gid*32      + ks*8 + tig + 4];
            f[3] = Q[(size_t)(gid+8)*32  + ks*8 + tig + 4];
#pragma unroll
            for (int i = 0; i < 4; i++) {
                uint32_t hi = cvt_tf32(f[i]);
                qh[ks][i] = hi;
                ql[ks][i] = cvt_tf32(f[i] - __uint_as_float(hi));
            }
        }
    }

    float4 acc_o[4];
#pragma unroll
    for (int n = 0; n < 4; n++) acc_o[n] = make_float4(0.f,0.f,0.f,0.f);
    float l0 = 0.f, l1 = 0.f;
    float* sPw = sP + w*16*SP_P;

    for (int kt = 0; kt < 32; kt++) {
        __syncthreads();
        // ---- stage K tile (128 keys x 32 dims) in two layouts, hi/lo split
        {
            int key = tid & 127, dh = tid >> 7;           // dh=0: dims 0..15, dh=1: 16..31
            const float4* src = (const float4*)(g_q2n + ((size_t)b*HW + kt*128 + key)*C8 + dh*16);
#pragma unroll
            for (int q4 = 0; q4 < 4; q4++) {
                float4 v = src[q4];
                int dim = dh*16 + q4*4;
                float4 h4, l4;
                uint32_t u;
                u = cvt_tf32(v.x); h4.x = __uint_as_float(u); l4.x = __uint_as_float(cvt_tf32(v.x - h4.x));
                u = cvt_tf32(v.y); h4.y = __uint_as_float(u); l4.y = __uint_as_float(cvt_tf32(v.y - h4.y));
                u = cvt_tf32(v.z); h4.z = __uint_as_float(u); l4.z = __uint_as_float(cvt_tf32(v.z - h4.z));
                u = cvt_tf32(v.w); h4.w = __uint_as_float(u); l4.w = __uint_as_float(cvt_tf32(v.w - h4.w));
                *(float4*)(sKnh + key*SP_KN + dim) = h4;
                *(float4*)(sKnl + key*SP_KN + dim) = l4;
                sKdh[(dim+0)*SP_KD + key] = h4.x;  sKdl[(dim+0)*SP_KD + key] = l4.x;
                sKdh[(dim+1)*SP_KD + key] = h4.y;  sKdl[(dim+1)*SP_KD + key] = l4.y;
                sKdh[(dim+2)*SP_KD + key] = h4.z;  sKdl[(dim+2)*SP_KD + key] = l4.z;
                sKdh[(dim+3)*SP_KD + key] = h4.w;  sKdl[(dim+3)*SP_KD + key] = l4.w;
            }
            if (tid < 128) sN[tid] = g_norm[(size_t)b*HW + kt*128 + tid];
        }
        __syncthreads();

        // ---- S = Q @ K^T (3xTF32), exp, fold norm, store P to per-warp smem
#pragma unroll 4
        for (int nt = 0; nt < 16; nt++) {
            float4 s = make_float4(0.f,0.f,0.f,0.f);
#pragma unroll
            for (int ks = 0; ks < 4; ks++) {
                int off = (nt*8 + gid)*SP_KN + ks*8 + tig;
                uint32_t bh0 = __float_as_uint(sKnh[off]);
                uint32_t bh1 = __float_as_uint(sKnh[off + 4]);
                uint32_t bl0 = __float_as_uint(sKnl[off]);
                uint32_t bl1 = __float_as_uint(sKnl[off + 4]);
                mma_tf32(s, qh[ks][0],qh[ks][1],qh[ks][2],qh[ks][3], bh0, bh1);
                mma_tf32(s, qh[ks][0],qh[ks][1],qh[ks][2],qh[ks][3], bl0, bl1);
                mma_tf32(s, ql[ks][0],ql[ks][1],ql[ks][2],ql[ks][3], bh0, bh1);
            }
            float n0 = sN[nt*8 + 2*tig], n1 = sN[nt*8 + 2*tig + 1];
            float p0 = __expf(s.x - 1.f), p1 = __expf(s.y - 1.f);
            float p2 = __expf(s.z - 1.f), p3 = __expf(s.w - 1.f);
            l0 += p0 + p1;
            l1 += p2 + p3;
            sPw[(size_t)gid*SP_P     + nt*8 + 2*tig    ] = __uint_as_float(cvt_tf32(p0*n0));
            sPw[(size_t)gid*SP_P     + nt*8 + 2*tig + 1] = __uint_as_float(cvt_tf32(p1*n1));
            sPw[(size_t)(gid+8)*SP_P + nt*8 + 2*tig    ] = __uint_as_float(cvt_tf32(p2*n0));
            sPw[(size_t)(gid+8)*SP_P + nt*8 + 2*tig + 1] = __uint_as_float(cvt_tf32(p3*n1));
        }
        __syncwarp();

        // ---- O += P @ V  (V = diag(n)K folded into P; V hi+lo)
#pragma unroll 4
        for (int ks2 = 0; ks2 < 16; ks2++) {
            uint32_t a0 = __float_as_uint(sPw[(size_t)gid*SP_P     + ks2*8 + tig]);
            uint32_t a1 = __float_as_uint(sPw[(size_t)(gid+8)*SP_P + ks2*8 + tig]);
            uint32_t a2 = __float_as_uint(sPw[(size_t)gid*SP_P     + ks2*8 + tig + 4]);
            uint32_t a3 = __float_as_uint(sPw[(size_t)(gid+8)*SP_P + ks2*8 + tig + 4]);
#pragma unroll
            for (int nt2 = 0; nt2 < 4; nt2++) {
                int off = (nt2*8 + gid)*SP_KD + ks2*8 + tig;
                uint32_t vh0 = __float_as_uint(sKdh[off]);
                uint32_t vh1 = __float_as_uint(sKdh[off + 4]);
                uint32_t vl0 = __float_as_uint(sKdl[off]);
                uint32_t vl1 = __float_as_uint(sKdl[off + 4]);
                mma_tf32(acc_o[nt2], a0,a1,a2,a3, vh0, vh1);
                mma_tf32(acc_o[nt2], a0,a1,a2,a3, vl0, vl1);
            }
        }
    }

    // reduce l over the quad (lanes sharing gid)
    l0 += __shfl_xor_sync(0xffffffffu, l0, 1);
    l0 += __shfl_xor_sync(0xffffffffu, l0, 2);
    l1 += __shfl_xor_sync(0xffffffffu, l1, 1);
    l1 += __shfl_xor_sync(0xffffffffu, l1, 2);
    float i0 = 1.f / l0, i1 = 1.f / l1;

    int q0 = qb + gid, q1 = qb + gid + 8;
#pragma unroll
    for (int nt2 = 0; nt2 < 4; nt2++) {
        int d0 = nt2*8 + 2*tig, d1 = d0 + 1;
        g_out3[((size_t)b*C8 + d0)*HW + q0] = acc_o[nt2].x * i0;
        g_out3[((size_t)b*C8 + d1)*HW + q0] = acc_o[nt2].y * i0;
        g_out3[((size_t)b*C8 + d0)*HW + q1] = acc_o[nt2].z * i1;
        g_out3[((size_t)b*C8 + d1)*HW + q1] = acc_o[nt2].w * i1;
    }
}

// ================= final: fused chout + 1x1s =================
__global__ void __launch_bounds__(256, 2) final_k(
    const float* __restrict__ w3, const float* __restrict__ b3,
    const float* __restrict__ w4, const float* __restrict__ b4,
    float* __restrict__ out)
{
    __shared__ float sw3[64*32];
    __shared__ float sw4[Cc*C8];
    __shared__ float sb4[Cc];
    __shared__ float sA[C8*C8];
    __shared__ float so3[64*33];

    const int tid = threadIdx.x;
    const int px = tid & 63, coh = tid >> 6;
    const int g0 = blockIdx.x * 64;
    const int gp = g0 + px;
    const int b = gp >> 12, k = gp & (HW-1);

    for (int idx = tid; idx < 64*32; idx += 256) {
        int j = idx >> 5, o = idx & 31;
        sw3[j*32 + o] = w3[o*64 + j];
    }
    for (int idx = tid; idx < Cc*C8; idx += 256) sw4[idx] = w4[idx];
    if (tid < Cc) sb4[tid] = b4[tid];
    for (int idx = tid; idx < C8*C8; idx += 256) sA[idx] = g_attn1[b*C8*C8 + idx];

    if (coh == 0) {
        const float* o3 = g_out3 + (size_t)b*C8*HW + k;
#pragma unroll
        for (int c = 0; c < C8; c++) so3[px*33 + c] = __ldg(o3 + (size_t)c*HW);
    }
    __syncthreads();

    float tv[C8];
    {
        const float* tb = g_t + (size_t)b*C8*HW + k;
#pragma unroll
        for (int c = 0; c < C8; c++) tv[c] = tb[(size_t)c*HW];
    }
    u64 tvp[16];
#pragma unroll
    for (int d = 0; d < 16; d++) tvp[d] = pack2(tv[2*d], tv[2*d+1]);

    float out2[C8];
#pragma unroll
    for (int i = 0; i < C8; i++) {
        const u64* ar = (const u64*)(sA + i*32);
        u64 s2 = pack2(0.f, 0.f);
#pragma unroll
        for (int d = 0; d < 16; d++) s2 = ffma2(ar[d], tvp[d], s2);
        float2 f = unpack2(s2);
        out2[i] = f.x + f.y;
    }

    u64 o5[16];
#pragma unroll
    for (int d = 0; d < 16; d++)
        o5[d] = pack2(__ldg(b3 + 2*d) + tv[2*d], __ldg(b3 + 2*d+1) + tv[2*d+1]);

#pragma unroll 4
    for (int j = 0; j < 32; j++) {
        u64 vp = pack2(out2[j], out2[j]);
        const u64* wr = (const u64*)(sw3 + j*32);
#pragma unroll
        for (int d = 0; d < 16; d++) o5[d] = ffma2(vp, wr[d], o5[d]);
    }
#pragma unroll 4
    for (int j = 0; j < 32; j++) {
        float v = so3[px*33 + j];
        u64 vp = pack2(v, v);
        const u64* wr = (const u64*)(sw3 + (32+j)*32);
#pragma unroll
        for (int d = 0; d < 16; d++) o5[d] = ffma2(vp, wr[d], o5[d]);
    }

    const int co0 = coh * 64;
    float* dst = out + (size_t)b*Cc*HW + (size_t)co0*HW + k;
#pragma unroll 2
    for (int cc = 0; cc < 64; cc += 2) {
        const u64* w0 = (const u64*)(sw4 + (co0+cc)*C8);
        const u64* w1 = (const u64*)(sw4 + (co0+cc+1)*C8);
        u64 s0 = pack2(0.f, 0.f), s1 = pack2(0.f, 0.f);
#pragma unroll
        for (int d = 0; d < 16; d++) {
            s0 = ffma2(w0[d], o5[d], s0);
            s1 = ffma2(w1[d], o5[d], s1);
        }
        float2 f0 = unpack2(s0), f1 = unpack2(s1);
        dst[(size_t)cc*HW]     = f0.x + f0.y + sb4[co0+cc];
        dst[(size_t)(cc+1)*HW] = f1.x + f1.y + sb4[co0+cc+1];
    }
}

// ================= launch =================
extern "C" void kernel_launch(void* const* d_in, const int* in_sizes, int n_in,
                              void* d_out, int out_size)
{
    const float* x      = (const float*)d_in[0];
    const float* w_conv = (const float*)d_in[1];
    const float* b_conv = (const float*)d_in[2];
    const float* w01 = (const float*)d_in[3];
    const float* b01 = (const float*)d_in[4];
    const float* w02 = (const float*)d_in[5];
    const float* b02 = (const float*)d_in[6];
    const float* w11 = (const float*)d_in[7];
    const float* b11 = (const float*)d_in[8];
    const float* w12 = (const float*)d_in[9];
    const float* b12 = (const float*)d_in[10];
    const float* w21 = (const float*)d_in[11];
    const float* b21 = (const float*)d_in[12];
    const float* w22 = (const float*)d_in[13];
    const float* b22 = (const float*)d_in[14];
    const float* w_proj = (const float*)d_in[15];
    const float* b_proj = (const float*)d_in[16];
    const float* w3 = (const float*)d_in[17];
    const float* b3 = (const float*)d_in[18];
    const float* w4 = (const float*)d_in[19];
    const float* b4 = (const float*)d_in[20];
    float* out = (float*)d_out;

    const int convSmem = (2*SX_ELEMS + 2*SW_ELEMS) * (int)sizeof(float);
    const int spSmem   = (2*128*SP_KN + 2*32*SP_KD + 8*16*SP_P + 128) * (int)sizeof(float);
    static bool attrSet = false;
    if (!attrSet) {
        cudaFuncSetAttribute(convmma_k, cudaFuncAttributeMaxDynamicSharedMemorySize, convSmem);
        cudaFuncSetAttribute(spflash_k, cudaFuncAttributeMaxDynamicSharedMemorySize, spSmem);
        attrSet = true;
    }

    wprep_k   <<<9*Cc*Cc/256, 256>>>(w_conv);
    convmma_k <<<dim3(32, 2, 4), 256, convSmem>>>(x, b_conv);
    dwfused_k <<<Bn*Cc, 256>>>(w01, b01, w02, b02, w11, b11, w12, b12, w21, b21, w22, b22);
    projnorm_k<<<256, 256>>>(w_proj, b_proj);
    gram_k    <<<dim3(32, 4), 256>>>();
    chsoft_k  <<<4, 1024>>>();
    spflash_k <<<dim3(32, 4), 256, spSmem>>>();
    final_k   <<<256, 256>>>(w3, b3, w4, b4, out);
}

// round 7
// speedup vs baseline: 4.0782x; 1.3397x over previous
#include <cuda_runtime.h>
#include <cuda_bf16.h>
#include <math.h>
#include <stdint.h>

#define Bn 4
#define Cc 256
#define C8 32
#define Hh 64
#define Ww 64
#define HW 4096

typedef unsigned long long u64;

__device__ __forceinline__ u64 ffma2(u64 a, u64 b, u64 c){
    u64 d; asm("fma.rn.f32x2 %0, %1, %2, %3;" : "=l"(d) : "l"(a), "l"(b), "l"(c)); return d;
}
__device__ __forceinline__ u64 pack2(float lo, float hi){
    u64 d; asm("mov.b64 %0, {%1, %2};" : "=l"(d) : "f"(lo), "f"(hi)); return d;
}
__device__ __forceinline__ float2 unpack2(u64 v){
    float lo, hi; asm("mov.b64 {%0, %1}, %2;" : "=f"(lo), "=f"(hi) : "l"(v));
    return make_float2(lo, hi);
}
__device__ __forceinline__ uint32_t cvt_tf32(float v){
    uint32_t r; asm("cvt.rna.tf32.f32 %0, %1;" : "=r"(r) : "f"(v)); return r;
}
__device__ __forceinline__ void mma_tf32(float4& d, const uint32_t a0, const uint32_t a1,
                                         const uint32_t a2, const uint32_t a3,
                                         const uint32_t b0, const uint32_t b1){
    asm volatile(
      "mma.sync.aligned.m16n8k8.row.col.f32.tf32.tf32.f32 "
      "{%0,%1,%2,%3}, {%4,%5,%6,%7}, {%8,%9}, {%0,%1,%2,%3};"
      : "+f"(d.x), "+f"(d.y), "+f"(d.z), "+f"(d.w)
      : "r"(a0), "r"(a1), "r"(a2), "r"(a3), "r"(b0), "r"(b1));
}
__device__ __forceinline__ void mma_bf16(float4& d, const uint32_t a0, const uint32_t a1,
                                         const uint32_t a2, const uint32_t a3,
                                         const uint32_t b0, const uint32_t b1){
    asm volatile(
      "mma.sync.aligned.m16n8k16.row.col.f32.bf16.bf16.f32 "
      "{%0,%1,%2,%3}, {%4,%5,%6,%7}, {%8,%9}, {%0,%1,%2,%3};"
      : "+f"(d.x), "+f"(d.y), "+f"(d.z), "+f"(d.w)
      : "r"(a0), "r"(a1), "r"(a2), "r"(a3), "r"(b0), "r"(b1));
}
__device__ __forceinline__ uint32_t pkbf(__nv_bfloat16 a, __nv_bfloat16 b){
    __nv_bfloat162 t = __halves2bfloat162(a, b);
    return *reinterpret_cast<uint32_t*>(&t);
}

// ---------------- scratch ----------------
__device__ float g_x  [Bn*Cc*HW];
__device__ float g_sum[Bn*Cc*HW];
__device__ float g_t  [Bn*C8*HW];
__device__ float g_attn1[Bn*C8*C8];
__device__ float g_out3[Bn*C8*HW];
__device__ float g_q2n [Bn*HW*C8];
__device__ float g_norm[Bn*HW];
__device__ float g_pgram[Bn*32*C8*C8];
__device__ uint32_t g_wbh[9*128*Cc];   // [tap][ci2][co] bf16-pair hi
__device__ uint32_t g_wbl[9*128*Cc];   // bf16-pair lo

// ================= weight prep: bf16 hi/lo pairs, [tap][ci2][co] =================
__global__ void __launch_bounds__(256) wprep_k(const float* __restrict__ w)
{
    int idx = blockIdx.x * 256 + threadIdx.x;   // 9*128*256 = 294912
    int co  = idx & 255;
    int ci2 = (idx >> 8) & 127;
    int tap = idx >> 15;
    float v0 = w[((size_t)co*Cc + 2*ci2    )*9 + tap];
    float v1 = w[((size_t)co*Cc + 2*ci2 + 1)*9 + tap];
    __nv_bfloat16 h0 = __float2bfloat16_rn(v0), h1 = __float2bfloat16_rn(v1);
    __nv_bfloat16 l0 = __float2bfloat16_rn(v0 - __bfloat162float(h0));
    __nv_bfloat16 l1 = __float2bfloat16_rn(v1 - __bfloat162float(h1));
    g_wbh[idx] = pkbf(h0, h1);
    g_wbl[idx] = pkbf(l0, l1);
}

// ================= 3x3 conv via bf16 m16n8k16 MMA, 2-way split =================
// grid (32 pb, 2 cog, 4 b), block 256 (8 warps). CTA tile: 128 co x 128 px.
#define SXB 264            // u32 stride per ci2 for X strip (4 rows x 66)
#define SWB 136            // u32 stride per ci2 for W tile (128 co, padded)
#define SXB_ELEMS (8*SXB)  // 2112
#define SWB_ELEMS (8*SWB)  // 1088

__global__ void __launch_bounds__(256, 2) convmma_k(
    const float* __restrict__ x, const float* __restrict__ bias)
{
    extern __shared__ uint32_t smu[];
    uint32_t* sXh = smu;
    uint32_t* sXl = sXh + SXB_ELEMS;
    uint32_t* sWh = sXl + SXB_ELEMS;
    uint32_t* sWl = sWh + SWB_ELEMS;

    const int pb = blockIdx.x, cog = blockIdx.y, b = blockIdx.z;
    const int tid  = threadIdx.x;
    const int wid  = tid >> 5, lane = tid & 31;
    const int wm   = wid >> 1, wn = wid & 1;
    const int gid  = lane >> 2, tig = lane & 3;
    const int h0   = pb * 2;

    float4 acc[2][8];
#pragma unroll
    for (int mt = 0; mt < 2; mt++)
#pragma unroll
        for (int nt = 0; nt < 8; nt++) acc[mt][nt] = make_float4(0.f,0.f,0.f,0.f);

    for (int cib = 0; cib < Cc/16; cib++) {
        __syncthreads();
        // ---- stage X strip: 8 ci-pairs x 4 rows x 66 cols, bf16 hi/lo pairs
        for (int e = tid; e < 8*264; e += 256) {
            int ci2 = e / 264;
            int rem = e - ci2*264;
            int r = rem / 66;
            int c = rem - r*66;
            int gh = h0 - 1 + r, gw = c - 1;
            float v0 = 0.f, v1 = 0.f;
            if (gh >= 0 && gh < Hh && gw >= 0 && gw < Ww) {
                const float* p = x + ((size_t)(b*Cc + cib*16 + 2*ci2))*HW + gh*Ww + gw;
                v0 = __ldg(p);
                v1 = __ldg(p + HW);
            }
            __nv_bfloat16 h0b = __float2bfloat16_rn(v0), h1b = __float2bfloat16_rn(v1);
            __nv_bfloat16 l0b = __float2bfloat16_rn(v0 - __bfloat162float(h0b));
            __nv_bfloat16 l1b = __float2bfloat16_rn(v1 - __bfloat162float(h1b));
            sXh[e] = pkbf(h0b, h1b);
            sXl[e] = pkbf(l0b, l1b);
        }

        for (int tap = 0; tap < 9; tap++) {
            __syncthreads();
            // ---- stage W tile: [ci2 8][co 128] u32 pairs
            {
                const uint32_t* srcH = g_wbh + (size_t)tap*32768 + (size_t)(cib*8)*256 + cog*128;
                const uint32_t* srcL = g_wbl + (size_t)tap*32768 + (size_t)(cib*8)*256 + cog*128;
#pragma unroll
                for (int i = 0; i < 4; i++) {
                    int e = tid + i*256;          // 1024 entries
                    int ci2 = e >> 7, co = e & 127;
                    sWh[ci2*SWB + co] = srcH[(size_t)ci2*256 + co];
                    sWl[ci2*SWB + co] = srcL[(size_t)ci2*256 + co];
                }
            }
            __syncthreads();

            const int dh = tap/3 - 1, dw = tap%3 - 1;

            uint32_t ah[2][4], al[2][4];
#pragma unroll
            for (int mt = 0; mt < 2; mt++) {
                int cb = wm*32 + mt*16 + gid;
                ah[mt][0] = sWh[tig*SWB + cb];       ah[mt][1] = sWh[tig*SWB + cb + 8];
                ah[mt][2] = sWh[(tig+4)*SWB + cb];   ah[mt][3] = sWh[(tig+4)*SWB + cb + 8];
                al[mt][0] = sWl[tig*SWB + cb];       al[mt][1] = sWl[tig*SWB + cb + 8];
                al[mt][2] = sWl[(tig+4)*SWB + cb];   al[mt][3] = sWl[(tig+4)*SWB + cb + 8];
            }
            const int boff = tig*SXB + (wn + 1 + dh)*66 + 1 + dw + gid;
#pragma unroll
            for (int nt = 0; nt < 8; nt++) {
                uint32_t b0h = sXh[boff + nt*8], b1h = sXh[boff + nt*8 + 4*SXB];
                uint32_t b0l = sXl[boff + nt*8], b1l = sXl[boff + nt*8 + 4*SXB];
#pragma unroll
                for (int mt = 0; mt < 2; mt++) {
                    mma_bf16(acc[mt][nt], ah[mt][0],ah[mt][1],ah[mt][2],ah[mt][3], b0h, b1h);
                    mma_bf16(acc[mt][nt], ah[mt][0],ah[mt][1],ah[mt][2],ah[mt][3], b0l, b1l);
                    mma_bf16(acc[mt][nt], al[mt][0],al[mt][1],al[mt][2],al[mt][3], b0h, b1h);
                }
            }
        }
    }

#pragma unroll
    for (int mt = 0; mt < 2; mt++) {
        int co0 = cog*128 + wm*32 + mt*16 + gid;
        float b0 = __ldg(bias + co0);
        float b1 = __ldg(bias + co0 + 8);
#pragma unroll
        for (int nt = 0; nt < 8; nt++) {
            int px = pb*128 + wn*64 + nt*8 + 2*tig;
            float2* d0 = (float2*)(g_x + ((size_t)(b*Cc + co0))*HW + px);
            float2* d1 = (float2*)(g_x + ((size_t)(b*Cc + co0 + 8))*HW + px);
            float4 a = acc[mt][nt];
            *d0 = make_float2(a.x + b0, a.y + b0);
            *d1 = make_float2(a.z + b1, a.w + b1);
        }
    }
}

// ================= fused depthwise =================
template<int K>
__device__ __forceinline__ void dw_scale(
    const float* xs, float* hb, float out[16],
    const float* __restrict__ wh_c, const float* __restrict__ wv_c,
    float bh, float bv, int w, int h0)
{
    constexpr int P = K/2;
    float whr[K];
#pragma unroll
    for (int k = 0; k < K; k++) whr[k] = __ldg(wh_c + k);
#pragma unroll
    for (int i = 0; i < 16; i++) {
        int h = h0 + i; float s = bh;
#pragma unroll
        for (int k = 0; k < K; k++) {
            int ww = w + k - P;
            if (ww >= 0 && ww < Ww) s += whr[k] * xs[h*Ww + ww];
        }
        hb[h*Ww + w] = s;
    }
    __syncthreads();
    float wvr[K];
#pragma unroll
    for (int k = 0; k < K; k++) wvr[k] = __ldg(wv_c + k);
#pragma unroll
    for (int i = 0; i < 16; i++) {
        int h = h0 + i; float s = bv;
#pragma unroll
        for (int k = 0; k < K; k++) {
            int hh = h + k - P;
            if (hh >= 0 && hh < Hh) s += wvr[k] * hb[hh*Ww + w];
        }
        out[i] += s;
    }
    __syncthreads();
}

__global__ void __launch_bounds__(256) dwfused_k(
    const float* __restrict__ w01, const float* __restrict__ b01,
    const float* __restrict__ w02, const float* __restrict__ b02,
    const float* __restrict__ w11, const float* __restrict__ b11,
    const float* __restrict__ w12, const float* __restrict__ b12,
    const float* __restrict__ w21, const float* __restrict__ b21,
    const float* __restrict__ w22, const float* __restrict__ b22)
{
    __shared__ float xs[HW];
    __shared__ float hb[HW];
    const int plane = blockIdx.x;
    const int c = plane & (Cc-1);
    const int tid = threadIdx.x;
    const float* src = g_x + (size_t)plane*HW;

#pragma unroll
    for (int s = 0; s < 4; s++)
        ((float4*)xs)[tid + s*256] = ((const float4*)src)[tid + s*256];
    __syncthreads();

    const int w  = tid & 63;
    const int h0 = (tid >> 6) * 16;

    float out[16];
#pragma unroll
    for (int i = 0; i < 16; i++) out[i] = xs[(h0+i)*Ww + w];

    dw_scale<7> (xs, hb, out, w01 + c*7,  w02 + c*7,  __ldg(b01+c), __ldg(b02+c), w, h0);
    dw_scale<11>(xs, hb, out, w11 + c*11, w12 + c*11, __ldg(b11+c), __ldg(b12+c), w, h0);
    dw_scale<21>(xs, hb, out, w21 + c*21, w22 + c*21, __ldg(b21+c), __ldg(b22+c), w, h0);

    float* dst = g_sum + (size_t)plane*HW;
#pragma unroll
    for (int i = 0; i < 16; i++) dst[(h0+i)*Ww + w] = out[i];
}

// ================= fused 1x1 proj + transpose + l2norm =================
__global__ void __launch_bounds__(256, 2) projnorm_k(
    const float* __restrict__ w_proj, const float* __restrict__ b_proj)
{
    __shared__ float ws[Cc*C8];
    __shared__ float sred[4*64*33];
    __shared__ float st[64*33];

    const int tid = threadIdx.x;
    for (int idx = tid; idx < Cc*C8; idx += 256) {
        int o = idx >> 8, c = idx & 255;
        ws[c*C8 + o] = w_proj[o*Cc + c];
    }
    __syncthreads();

    const int px = tid & 63, slice = tid >> 6;
    const int g0 = blockIdx.x * 64;
    const int gp = g0 + px;
    const int b = gp >> 12, k = gp & (HW-1);

    u64 acc[16];
    const u64 zero = pack2(0.f, 0.f);
#pragma unroll
    for (int d = 0; d < 16; d++) acc[d] = zero;

    const float* src = g_sum + (size_t)b*Cc*HW + (size_t)slice*64*HW + k;
    const float* wsl = ws + slice*64*C8;
#pragma unroll 4
    for (int c = 0; c < 64; c++) {
        float v = __ldg(src + (size_t)c*HW);
        u64 vp = pack2(v, v);
        const u64* wrow = (const u64*)(wsl + c*C8);
#pragma unroll
        for (int d = 0; d < 16; d++) acc[d] = ffma2(vp, wrow[d], acc[d]);
    }
    float* srow = sred + (slice*64 + px)*33;
#pragma unroll
    for (int d = 0; d < 16; d++) {
        float2 v = unpack2(acc[d]);
        srow[2*d] = v.x; srow[2*d+1] = v.y;
    }
    __syncthreads();

    for (int e = tid; e < 64*C8; e += 256) {
        int p = e >> 5, o = e & 31;
        float v = __ldg(b_proj + o)
                + sred[(0*64+p)*33 + o] + sred[(1*64+p)*33 + o]
                + sred[(2*64+p)*33 + o] + sred[(3*64+p)*33 + o];
        st[p*33 + o] = v;
    }
    __syncthreads();

    if (tid < 64) {
        int p = tid;
        int gpp = g0 + p;
        int bb = gpp >> 12, kk = gpp & (HW-1);
        float v[C8]; float ss = 0.f;
#pragma unroll
        for (int c = 0; c < C8; c++) { v[c] = st[p*33 + c]; ss += v[c]*v[c]; }
        float n = sqrtf(ss);
        float inv = 1.f / fmaxf(n, 1e-12f);
        g_norm[gpp] = n;
        float4* qp = (float4*)(g_q2n + (size_t)gpp*C8);
#pragma unroll
        for (int d = 0; d < 8; d++)
            qp[d] = make_float4(v[d*4+0]*inv, v[d*4+1]*inv, v[d*4+2]*inv, v[d*4+3]*inv);
        float* tb = g_t + (size_t)bb*C8*HW + kk;
#pragma unroll
        for (int c = 0; c < C8; c++) tb[(size_t)c*HW] = v[c];
    }
}

// ================= gram partials =================
__global__ void __launch_bounds__(256) gram_k()
{
    __shared__ float st[32*129];
    const int slab = blockIdx.x, b = blockIdx.y;
    const int tid = threadIdx.x;
    const float* tb = g_t + (size_t)b*C8*HW + slab*128;
    for (int idx = tid; idx < 32*128; idx += 256) {
        int c = idx >> 7, x = idx & 127;
        st[c*129 + x] = tb[(size_t)c*HW + x];
    }
    __syncthreads();

    const int i  = tid >> 3;
    const int j0 = (tid & 7) * 4;
    const float* ri = st + i*129;
    const float* r0 = st + (j0+0)*129;
    const float* r1 = st + (j0+1)*129;
    const float* r2 = st + (j0+2)*129;
    const float* r3 = st + (j0+3)*129;
    float s0=0.f, s1=0.f, s2=0.f, s3=0.f;
#pragma unroll 8
    for (int x = 0; x < 128; x++) {
        float a = ri[x];
        s0 += a*r0[x]; s1 += a*r1[x]; s2 += a*r2[x]; s3 += a*r3[x];
    }
    float* dst = g_pgram + (((size_t)b*32 + slab) << 10) + i*32 + j0;
    dst[0]=s0; dst[1]=s1; dst[2]=s2; dst[3]=s3;
}

// ================= reduce gram + softmax =================
__global__ void __launch_bounds__(1024) chsoft_k()
{
    const int b = blockIdx.x;
    const int tid = threadIdx.x;
    __shared__ float G[1024];
    __shared__ float ninv[32];

    float g = 0.f;
#pragma unroll
    for (int s = 0; s < 32; s++)
        g += g_pgram[(((size_t)b*32 + s) << 10) + tid];
    G[tid] = g;
    if ((tid >> 5) == (tid & 31)) ninv[tid & 31] = 1.f / fmaxf(sqrtf(g), 1e-12f);
    __syncthreads();

    if (tid < 32) {
        int r = tid;
        float ir = ninv[r];
        float row[32]; float s = 0.f;
#pragma unroll
        for (int jj = 0; jj < 32; jj++) {
            float a = G[r*32 + jj] * ir * ninv[jj];
            float p = expf(a - 1.f);
            row[jj] = p; s += p;
        }
        float is = 1.f / s;
        float* dst = g_attn1 + b*C8*C8 + r*32;
#pragma unroll
        for (int jj = 0; jj < 32; jj++) dst[jj] = row[jj] * is;
    }
}

// ================= flash spatial attention on tensor cores (tf32) =================
#define SP_KN 36
#define SP_KD 132
#define SP_P  133

__global__ void __launch_bounds__(256, 1) spflash_k()
{
    extern __shared__ float sm[];
    float* sKnh = sm;
    float* sKnl = sKnh + 128*SP_KN;
    float* sKdh = sKnl + 128*SP_KN;
    float* sKdl = sKdh + 32*SP_KD;
    float* sP   = sKdl + 32*SP_KD;
    float* sN   = sP + 8*16*SP_P;

    const int tid = threadIdx.x;
    const int w = tid >> 5, lane = tid & 31;
    const int gid = lane >> 2, tig = lane & 3;
    const int b = blockIdx.y;
    const int qb = blockIdx.x*128 + w*16;

    uint32_t qh[4][4], ql[4][4];
    {
        const float* Q = g_q2n + ((size_t)b*HW + qb)*C8;
#pragma unroll
        for (int ks = 0; ks < 4; ks++) {
            float f[4];
            f[0] = Q[(size_t)gid*32      + ks*8 + tig];
            f[1] = Q[(size_t)(gid+8)*32  + ks*8 + tig];
            f[2] = Q[(size_t)gid*32      + ks*8 + tig + 4];
            f[3] = Q[(size_t)(gid+8)*32  + ks*8 + tig + 4];
#pragma unroll
            for (int i = 0; i < 4; i++) {
                uint32_t hi = cvt_tf32(f[i]);
                qh[ks][i] = hi;
                ql[ks][i] = cvt_tf32(f[i] - __uint_as_float(hi));
            }
        }
    }

    float4 acc_o[4];
#pragma unroll
    for (int n = 0; n < 4; n++) acc_o[n] = make_float4(0.f,0.f,0.f,0.f);
    float l0 = 0.f, l1 = 0.f;
    float* sPw = sP + w*16*SP_P;

    for (int kt = 0; kt < 32; kt++) {
        __syncthreads();
        {
            int key = tid & 127, dh = tid >> 7;
            const float4* src = (const float4*)(g_q2n + ((size_t)b*HW + kt*128 + key)*C8 + dh*16);
#pragma unroll
            for (int q4 = 0; q4 < 4; q4++) {
                float4 v = src[q4];
                int dim = dh*16 + q4*4;
                float4 h4, l4;
                uint32_t u;
                u = cvt_tf32(v.x); h4.x = __uint_as_float(u); l4.x = __uint_as_float(cvt_tf32(v.x - h4.x));
                u = cvt_tf32(v.y); h4.y = __uint_as_float(u); l4.y = __uint_as_float(cvt_tf32(v.y - h4.y));
                u = cvt_tf32(v.z); h4.z = __uint_as_float(u); l4.z = __uint_as_float(cvt_tf32(v.z - h4.z));
                u = cvt_tf32(v.w); h4.w = __uint_as_float(u); l4.w = __uint_as_float(cvt_tf32(v.w - h4.w));
                *(float4*)(sKnh + key*SP_KN + dim) = h4;
                *(float4*)(sKnl + key*SP_KN + dim) = l4;
                sKdh[(dim+0)*SP_KD + key] = h4.x;  sKdl[(dim+0)*SP_KD + key] = l4.x;
                sKdh[(dim+1)*SP_KD + key] = h4.y;  sKdl[(dim+1)*SP_KD + key] = l4.y;
                sKdh[(dim+2)*SP_KD + key] = h4.z;  sKdl[(dim+2)*SP_KD + key] = l4.z;
                sKdh[(dim+3)*SP_KD + key] = h4.w;  sKdl[(dim+3)*SP_KD + key] = l4.w;
            }
            if (tid < 128) sN[tid] = g_norm[(size_t)b*HW + kt*128 + tid];
        }
        __syncthreads();

#pragma unroll 4
        for (int nt = 0; nt < 16; nt++) {
            float4 s = make_float4(0.f,0.f,0.f,0.f);
#pragma unroll
            for (int ks = 0; ks < 4; ks++) {
                int off = (nt*8 + gid)*SP_KN + ks*8 + tig;
                uint32_t bh0 = __float_as_uint(sKnh[off]);
                uint32_t bh1 = __float_as_uint(sKnh[off + 4]);
                uint32_t bl0 = __float_as_uint(sKnl[off]);
                uint32_t bl1 = __float_as_uint(sKnl[off + 4]);
                mma_tf32(s, qh[ks][0],qh[ks][1],qh[ks][2],qh[ks][3], bh0, bh1);
                mma_tf32(s, qh[ks][0],qh[ks][1],qh[ks][2],qh[ks][3], bl0, bl1);
                mma_tf32(s, ql[ks][0],ql[ks][1],ql[ks][2],ql[ks][3], bh0, bh1);
            }
            float n0 = sN[nt*8 + 2*tig], n1 = sN[nt*8 + 2*tig + 1];
            float p0 = __expf(s.x - 1.f), p1 = __expf(s.y - 1.f);
            float p2 = __expf(s.z - 1.f), p3 = __expf(s.w - 1.f);
            l0 += p0 + p1;
            l1 += p2 + p3;
            sPw[(size_t)gid*SP_P     + nt*8 + 2*tig    ] = __uint_as_float(cvt_tf32(p0*n0));
            sPw[(size_t)gid*SP_P     + nt*8 + 2*tig + 1] = __uint_as_float(cvt_tf32(p1*n1));
            sPw[(size_t)(gid+8)*SP_P + nt*8 + 2*tig    ] = __uint_as_float(cvt_tf32(p2*n0));
            sPw[(size_t)(gid+8)*SP_P + nt*8 + 2*tig + 1] = __uint_as_float(cvt_tf32(p3*n1));
        }
        __syncwarp();

#pragma unroll 4
        for (int ks2 = 0; ks2 < 16; ks2++) {
            uint32_t a0 = __float_as_uint(sPw[(size_t)gid*SP_P     + ks2*8 + tig]);
            uint32_t a1 = __float_as_uint(sPw[(size_t)(gid+8)*SP_P + ks2*8 + tig]);
            uint32_t a2 = __float_as_uint(sPw[(size_t)gid*SP_P     + ks2*8 + tig + 4]);
            uint32_t a3 = __float_as_uint(sPw[(size_t)(gid+8)*SP_P + ks2*8 + tig + 4]);
#pragma unroll
            for (int nt2 = 0; nt2 < 4; nt2++) {
                int off = (nt2*8 + gid)*SP_KD + ks2*8 + tig;
                uint32_t vh0 = __float_as_uint(sKdh[off]);
                uint32_t vh1 = __float_as_uint(sKdh[off + 4]);
                uint32_t vl0 = __float_as_uint(sKdl[off]);
                uint32_t vl1 = __float_as_uint(sKdl[off + 4]);
                mma_tf32(acc_o[nt2], a0,a1,a2,a3, vh0, vh1);
                mma_tf32(acc_o[nt2], a0,a1,a2,a3, vl0, vl1);
            }
        }
    }

    l0 += __shfl_xor_sync(0xffffffffu, l0, 1);
    l0 += __shfl_xor_sync(0xffffffffu, l0, 2);
    l1 += __shfl_xor_sync(0xffffffffu, l1, 1);
    l1 += __shfl_xor_sync(0xffffffffu, l1, 2);
    float i0 = 1.f / l0, i1 = 1.f / l1;

    int q0 = qb + gid, q1 = qb + gid + 8;
#pragma unroll
    for (int nt2 = 0; nt2 < 4; nt2++) {
        int d0 = nt2*8 + 2*tig, d1 = d0 + 1;
        g_out3[((size_t)b*C8 + d0)*HW + q0] = acc_o[nt2].x * i0;
        g_out3[((size_t)b*C8 + d1)*HW + q0] = acc_o[nt2].y * i0;
        g_out3[((size_t)b*C8 + d0)*HW + q1] = acc_o[nt2].z * i1;
        g_out3[((size_t)b*C8 + d1)*HW + q1] = acc_o[nt2].w * i1;
    }
}

// ================= final: fused chout + 1x1s =================
__global__ void __launch_bounds__(256, 2) final_k(
    const float* __restrict__ w3, const float* __restrict__ b3,
    const float* __restrict__ w4, const float* __restrict__ b4,
    float* __restrict__ out)
{
    __shared__ float sw3[64*32];
    __shared__ float sw4[Cc*C8];
    __shared__ float sb4[Cc];
    __shared__ float sA[C8*C8];
    __shared__ float so3[64*33];

    const int tid = threadIdx.x;
    const int px = tid & 63, coh = tid >> 6;
    const int g0 = blockIdx.x * 64;
    const int gp = g0 + px;
    const int b = gp >> 12, k = gp & (HW-1);

    for (int idx = tid; idx < 64*32; idx += 256) {
        int j = idx >> 5, o = idx & 31;
        sw3[j*32 + o] = w3[o*64 + j];
    }
    for (int idx = tid; idx < Cc*C8; idx += 256) sw4[idx] = w4[idx];
    if (tid < Cc) sb4[tid] = b4[tid];
    for (int idx = tid; idx < C8*C8; idx += 256) sA[idx] = g_attn1[b*C8*C8 + idx];

    if (coh == 0) {
        const float* o3 = g_out3 + (size_t)b*C8*HW + k;
#pragma unroll
        for (int c = 0; c < C8; c++) so3[px*33 + c] = __ldg(o3 + (size_t)c*HW);
    }
    __syncthreads();

    float tv[C8];
    {
        const float* tb = g_t + (size_t)b*C8*HW + k;
#pragma unroll
        for (int c = 0; c < C8; c++) tv[c] = tb[(size_t)c*HW];
    }
    u64 tvp[16];
#pragma unroll
    for (int d = 0; d < 16; d++) tvp[d] = pack2(tv[2*d], tv[2*d+1]);

    float out2[C8];
#pragma unroll
    for (int i = 0; i < C8; i++) {
        const u64* ar = (const u64*)(sA + i*32);
        u64 s2 = pack2(0.f, 0.f);
#pragma unroll
        for (int d = 0; d < 16; d++) s2 = ffma2(ar[d], tvp[d], s2);
        float2 f = unpack2(s2);
        out2[i] = f.x + f.y;
    }

    u64 o5[16];
#pragma unroll
    for (int d = 0; d < 16; d++)
        o5[d] = pack2(__ldg(b3 + 2*d) + tv[2*d], __ldg(b3 + 2*d+1) + tv[2*d+1]);

#pragma unroll 4
    for (int j = 0; j < 32; j++) {
        u64 vp = pack2(out2[j], out2[j]);
        const u64* wr = (const u64*)(sw3 + j*32);
#pragma unroll
        for (int d = 0; d < 16; d++) o5[d] = ffma2(vp, wr[d], o5[d]);
    }
#pragma unroll 4
    for (int j = 0; j < 32; j++) {
        float v = so3[px*33 + j];
        u64 vp = pack2(v, v);
        const u64* wr = (const u64*)(sw3 + (32+j)*32);
#pragma unroll
        for (int d = 0; d < 16; d++) o5[d] = ffma2(vp, wr[d], o5[d]);
    }

    const int co0 = coh * 64;
    float* dst = out + (size_t)b*Cc*HW + (size_t)co0*HW + k;
#pragma unroll 2
    for (int cc = 0; cc < 64; cc += 2) {
        const u64* w0 = (const u64*)(sw4 + (co0+cc)*C8);
        const u64* w1 = (const u64*)(sw4 + (co0+cc+1)*C8);
        u64 s0 = pack2(0.f, 0.f), s1 = pack2(0.f, 0.f);
#pragma unroll
        for (int d = 0; d < 16; d++) {
            s0 = ffma2(w0[d], o5[d], s0);
            s1 = ffma2(w1[d], o5[d], s1);
        }
        float2 f0 = unpack2(s0), f1 = unpack2(s1);
        dst[(size_t)cc*HW]     = f0.x + f0.y + sb4[co0+cc];
        dst[(size_t)(cc+1)*HW] = f1.x + f1.y + sb4[co0+cc+1];
    }
}

// ================= launch =================
extern "C" void kernel_launch(void* const* d_in, const int* in_sizes, int n_in,
                              void* d_out, int out_size)
{
    const float* x      = (const float*)d_in[0];
    const float* w_conv = (const float*)d_in[1];
    const float* b_conv = (const float*)d_in[2];
    const float* w01 = (const float*)d_in[3];
    const float* b01 = (const float*)d_in[4];
    const float* w02 = (const float*)d_in[5];
    const float* b02 = (const float*)d_in[6];
    const float* w11 = (const float*)d_in[7];
    const float* b11 = (const float*)d_in[8];
    const float* w12 = (const float*)d_in[9];
    const float* b12 = (const float*)d_in[10];
    const float* w21 = (const float*)d_in[11];
    const float* b21 = (const float*)d_in[12];
    const float* w22 = (const float*)d_in[13];
    const float* b22 = (const float*)d_in[14];
    const float* w_proj = (const float*)d_in[15];
    const float* b_proj = (const float*)d_in[16];
    const float* w3 = (const float*)d_in[17];
    const float* b3 = (const float*)d_in[18];
    const float* w4 = (const float*)d_in[19];
    const float* b4 = (const float*)d_in[20];
    float* out = (float*)d_out;

    const int convSmem = (2*SXB_ELEMS + 2*SWB_ELEMS) * (int)sizeof(uint32_t);
    const int spSmem   = (2*128*SP_KN + 2*32*SP_KD + 8*16*SP_P + 128) * (int)sizeof(float);
    static bool attrSet = false;
    if (!attrSet) {
        cudaFuncSetAttribute(convmma_k, cudaFuncAttributeMaxDynamicSharedMemorySize, convSmem);
        cudaFuncSetAttribute(spflash_k, cudaFuncAttributeMaxDynamicSharedMemorySize, spSmem);
        attrSet = true;
    }

    wprep_k   <<<9*128*Cc/256, 256>>>(w_conv);
    convmma_k <<<dim3(32, 2, 4), 256, convSmem>>>(x, b_conv);
    dwfused_k <<<Bn*Cc, 256>>>(w01, b01, w02, b02, w11, b11, w12, b12, w21, b21, w22, b22);
    projnorm_k<<<256, 256>>>(w_proj, b_proj);
    gram_k    <<<dim3(32, 4), 256>>>();
    chsoft_k  <<<4, 1024>>>();
    spflash_k <<<dim3(32, 4), 256, spSmem>>>();
    final_k   <<<256, 256>>>(w3, b3, w4, b4, out);
}

// round 8
// speedup vs baseline: 4.7129x; 1.1556x over previous
#include <cuda_runtime.h>
#include <cuda_bf16.h>
#include <math.h>
#include <stdint.h>

#define Bn 4
#define Cc 256
#define C8 32
#define Hh 64
#define Ww 64
#define HW 4096

typedef unsigned long long u64;

__device__ __forceinline__ u64 ffma2(u64 a, u64 b, u64 c){
    u64 d; asm("fma.rn.f32x2 %0, %1, %2, %3;" : "=l"(d) : "l"(a), "l"(b), "l"(c)); return d;
}
__device__ __forceinline__ u64 pack2(float lo, float hi){
    u64 d; asm("mov.b64 %0, {%1, %2};" : "=l"(d) : "f"(lo), "f"(hi)); return d;
}
__device__ __forceinline__ float2 unpack2(u64 v){
    float lo, hi; asm("mov.b64 {%0, %1}, %2;" : "=f"(lo), "=f"(hi) : "l"(v));
    return make_float2(lo, hi);
}
__device__ __forceinline__ void mma_bf16(float4& d, const uint32_t a0, const uint32_t a1,
                                         const uint32_t a2, const uint32_t a3,
                                         const uint32_t b0, const uint32_t b1){
    asm volatile(
      "mma.sync.aligned.m16n8k16.row.col.f32.bf16.bf16.f32 "
      "{%0,%1,%2,%3}, {%4,%5,%6,%7}, {%8,%9}, {%0,%1,%2,%3};"
      : "+f"(d.x), "+f"(d.y), "+f"(d.z), "+f"(d.w)
      : "r"(a0), "r"(a1), "r"(a2), "r"(a3), "r"(b0), "r"(b1));
}
__device__ __forceinline__ uint32_t pkbf(__nv_bfloat16 a, __nv_bfloat16 b){
    __nv_bfloat162 t = __halves2bfloat162(a, b);
    return *reinterpret_cast<uint32_t*>(&t);
}

// ---------------- scratch ----------------
__device__ float g_x  [Bn*Cc*HW];
__device__ float g_sum[Bn*Cc*HW];
__device__ float g_t  [Bn*C8*HW];
__device__ float g_attn1[Bn*C8*C8];
__device__ float g_out3[Bn*C8*HW];
__device__ float g_q2n [Bn*HW*C8];
__device__ float g_norm[Bn*HW];
__device__ float g_pgram[Bn*32*C8*C8];
__device__ uint32_t g_wbh[9*128*Cc];   // [tap][ci2][co] bf16-pair hi
__device__ uint32_t g_wbl[9*128*Cc];   // bf16-pair lo

// ================= weight prep: bf16 hi/lo pairs, [tap][ci2][co] =================
__global__ void __launch_bounds__(256) wprep_k(const float* __restrict__ w)
{
    int idx = blockIdx.x * 256 + threadIdx.x;   // 9*128*256 = 294912
    int co  = idx & 255;
    int ci2 = (idx >> 8) & 127;
    int tap = idx >> 15;
    float v0 = w[((size_t)co*Cc + 2*ci2    )*9 + tap];
    float v1 = w[((size_t)co*Cc + 2*ci2 + 1)*9 + tap];
    __nv_bfloat16 h0 = __float2bfloat16_rn(v0), h1 = __float2bfloat16_rn(v1);
    __nv_bfloat16 l0 = __float2bfloat16_rn(v0 - __bfloat162float(h0));
    __nv_bfloat16 l1 = __float2bfloat16_rn(v1 - __bfloat162float(h1));
    g_wbh[idx] = pkbf(h0, h1);
    g_wbl[idx] = pkbf(l0, l1);
}

// ================= 3x3 conv via bf16 m16n8k16 MMA, all-taps W staging =================
// grid (32 pb, 2 cog, 4 b), block 256 (8 warps). CTA tile: 128 co x 128 px.
#define SXB 264            // u32 stride per ci2 for X strip (4 rows x 66)
#define SWB 136            // u32 stride per ci2 for W tile (128 co, padded)
#define SWT (8*SWB)        // per-tap W block (1088)
#define SXB_ELEMS (8*SXB)  // 2112
#define SW_ALL (9*SWT)     // 9792

__global__ void __launch_bounds__(256, 2) convmma_k(
    const float* __restrict__ x, const float* __restrict__ bias)
{
    extern __shared__ uint32_t smu[];
    uint32_t* sXh = smu;
    uint32_t* sXl = sXh + SXB_ELEMS;
    uint32_t* sWh = sXl + SXB_ELEMS;
    uint32_t* sWl = sWh + SW_ALL;

    const int pb = blockIdx.x, cog = blockIdx.y, b = blockIdx.z;
    const int tid  = threadIdx.x;
    const int wid  = tid >> 5, lane = tid & 31;
    const int wm   = wid >> 1, wn = wid & 1;
    const int gid  = lane >> 2, tig = lane & 3;
    const int h0   = pb * 2;

    float4 acc[2][8];
#pragma unroll
    for (int mt = 0; mt < 2; mt++)
#pragma unroll
        for (int nt = 0; nt < 8; nt++) acc[mt][nt] = make_float4(0.f,0.f,0.f,0.f);

    for (int cib = 0; cib < Cc/16; cib++) {
        __syncthreads();
        // ---- stage X strip: 8 ci-pairs x 4 rows x 66 cols, bf16 hi/lo pairs
        for (int e = tid; e < 8*264; e += 256) {
            int ci2 = e / 264;
            int rem = e - ci2*264;
            int r = rem / 66;
            int c = rem - r*66;
            int gh = h0 - 1 + r, gw = c - 1;
            float v0 = 0.f, v1 = 0.f;
            if (gh >= 0 && gh < Hh && gw >= 0 && gw < Ww) {
                const float* p = x + ((size_t)(b*Cc + cib*16 + 2*ci2))*HW + gh*Ww + gw;
                v0 = __ldg(p);
                v1 = __ldg(p + HW);
            }
            __nv_bfloat16 h0b = __float2bfloat16_rn(v0), h1b = __float2bfloat16_rn(v1);
            __nv_bfloat16 l0b = __float2bfloat16_rn(v0 - __bfloat162float(h0b));
            __nv_bfloat16 l1b = __float2bfloat16_rn(v1 - __bfloat162float(h1b));
            sXh[e] = pkbf(h0b, h1b);
            sXl[e] = pkbf(l0b, l1b);
        }
        // ---- stage W: ALL 9 taps for this cib
        {
            const size_t base = (size_t)(cib*8)*256 + cog*128;
#pragma unroll 4
            for (int e = tid; e < 9*1024; e += 256) {
                int tap = e >> 10, rem = e & 1023;
                int ci2 = rem >> 7, col = rem & 127;
                size_t src = (size_t)tap*32768 + base + (size_t)ci2*256 + col;
                int dst = tap*SWT + ci2*SWB + col;
                sWh[dst] = __ldg(g_wbh + src);
                sWl[dst] = __ldg(g_wbl + src);
            }
        }
        __syncthreads();

#pragma unroll
        for (int tap = 0; tap < 9; tap++) {
            const int dh = tap/3 - 1, dw = tap%3 - 1;
            const uint32_t* wh = sWh + tap*SWT;
            const uint32_t* wl = sWl + tap*SWT;

            uint32_t ah[2][4], al[2][4];
#pragma unroll
            for (int mt = 0; mt < 2; mt++) {
                int cb = wm*32 + mt*16 + gid;
                ah[mt][0] = wh[tig*SWB + cb];       ah[mt][1] = wh[tig*SWB + cb + 8];
                ah[mt][2] = wh[(tig+4)*SWB + cb];   ah[mt][3] = wh[(tig+4)*SWB + cb + 8];
                al[mt][0] = wl[tig*SWB + cb];       al[mt][1] = wl[tig*SWB + cb + 8];
                al[mt][2] = wl[(tig+4)*SWB + cb];   al[mt][3] = wl[(tig+4)*SWB + cb + 8];
            }
            const int boff = tig*SXB + (wn + 1 + dh)*66 + 1 + dw + gid;
#pragma unroll
            for (int nt = 0; nt < 8; nt++) {
                uint32_t b0h = sXh[boff + nt*8], b1h = sXh[boff + nt*8 + 4*SXB];
                uint32_t b0l = sXl[boff + nt*8], b1l = sXl[boff + nt*8 + 4*SXB];
#pragma unroll
                for (int mt = 0; mt < 2; mt++) {
                    mma_bf16(acc[mt][nt], ah[mt][0],ah[mt][1],ah[mt][2],ah[mt][3], b0h, b1h);
                    mma_bf16(acc[mt][nt], ah[mt][0],ah[mt][1],ah[mt][2],ah[mt][3], b0l, b1l);
                    mma_bf16(acc[mt][nt], al[mt][0],al[mt][1],al[mt][2],al[mt][3], b0h, b1h);
                }
            }
        }
    }

#pragma unroll
    for (int mt = 0; mt < 2; mt++) {
        int co0 = cog*128 + wm*32 + mt*16 + gid;
        float b0 = __ldg(bias + co0);
        float b1 = __ldg(bias + co0 + 8);
#pragma unroll
        for (int nt = 0; nt < 8; nt++) {
            int px = pb*128 + wn*64 + nt*8 + 2*tig;
            float2* d0 = (float2*)(g_x + ((size_t)(b*Cc + co0))*HW + px);
            float2* d1 = (float2*)(g_x + ((size_t)(b*Cc + co0 + 8))*HW + px);
            float4 a = acc[mt][nt];
            *d0 = make_float2(a.x + b0, a.y + b0);
            *d1 = make_float2(a.z + b1, a.w + b1);
        }
    }
}

// ================= fused depthwise =================
template<int K>
__device__ __forceinline__ void dw_scale(
    const float* xs, float* hb, float out[16],
    const float* __restrict__ wh_c, const float* __restrict__ wv_c,
    float bh, float bv, int w, int h0)
{
    constexpr int P = K/2;
    float whr[K];
#pragma unroll
    for (int k = 0; k < K; k++) whr[k] = __ldg(wh_c + k);
#pragma unroll
    for (int i = 0; i < 16; i++) {
        int h = h0 + i; float s = bh;
#pragma unroll
        for (int k = 0; k < K; k++) {
            int ww = w + k - P;
            if (ww >= 0 && ww < Ww) s += whr[k] * xs[h*Ww + ww];
        }
        hb[h*Ww + w] = s;
    }
    __syncthreads();
    float wvr[K];
#pragma unroll
    for (int k = 0; k < K; k++) wvr[k] = __ldg(wv_c + k);
#pragma unroll
    for (int i = 0; i < 16; i++) {
        int h = h0 + i; float s = bv;
#pragma unroll
        for (int k = 0; k < K; k++) {
            int hh = h + k - P;
            if (hh >= 0 && hh < Hh) s += wvr[k] * hb[hh*Ww + w];
        }
        out[i] += s;
    }
    __syncthreads();
}

__global__ void __launch_bounds__(256) dwfused_k(
    const float* __restrict__ w01, const float* __restrict__ b01,
    const float* __restrict__ w02, const float* __restrict__ b02,
    const float* __restrict__ w11, const float* __restrict__ b11,
    const float* __restrict__ w12, const float* __restrict__ b12,
    const float* __restrict__ w21, const float* __restrict__ b21,
    const float* __restrict__ w22, const float* __restrict__ b22)
{
    __shared__ float xs[HW];
    __shared__ float hb[HW];
    const int plane = blockIdx.x;
    const int c = plane & (Cc-1);
    const int tid = threadIdx.x;
    const float* src = g_x + (size_t)plane*HW;

#pragma unroll
    for (int s = 0; s < 4; s++)
        ((float4*)xs)[tid + s*256] = ((const float4*)src)[tid + s*256];
    __syncthreads();

    const int w  = tid & 63;
    const int h0 = (tid >> 6) * 16;

    float out[16];
#pragma unroll
    for (int i = 0; i < 16; i++) out[i] = xs[(h0+i)*Ww + w];

    dw_scale<7> (xs, hb, out, w01 + c*7,  w02 + c*7,  __ldg(b01+c), __ldg(b02+c), w, h0);
    dw_scale<11>(xs, hb, out, w11 + c*11, w12 + c*11, __ldg(b11+c), __ldg(b12+c), w, h0);
    dw_scale<21>(xs, hb, out, w21 + c*21, w22 + c*21, __ldg(b21+c), __ldg(b22+c), w, h0);

    float* dst = g_sum + (size_t)plane*HW;
#pragma unroll
    for (int i = 0; i < 16; i++) dst[(h0+i)*Ww + w] = out[i];
}

// ================= fused 1x1 proj + transpose + l2norm =================
__global__ void __launch_bounds__(256, 2) projnorm_k(
    const float* __restrict__ w_proj, const float* __restrict__ b_proj)
{
    __shared__ float ws[Cc*C8];
    __shared__ float sred[4*64*33];
    __shared__ float st[64*33];

    const int tid = threadIdx.x;
    for (int idx = tid; idx < Cc*C8; idx += 256) {
        int o = idx >> 8, c = idx & 255;
        ws[c*C8 + o] = w_proj[o*Cc + c];
    }
    __syncthreads();

    const int px = tid & 63, slice = tid >> 6;
    const int g0 = blockIdx.x * 64;
    const int gp = g0 + px;
    const int b = gp >> 12, k = gp & (HW-1);

    u64 acc[16];
    const u64 zero = pack2(0.f, 0.f);
#pragma unroll
    for (int d = 0; d < 16; d++) acc[d] = zero;

    const float* src = g_sum + (size_t)b*Cc*HW + (size_t)slice*64*HW + k;
    const float* wsl = ws + slice*64*C8;
#pragma unroll 4
    for (int c = 0; c < 64; c++) {
        float v = __ldg(src + (size_t)c*HW);
        u64 vp = pack2(v, v);
        const u64* wrow = (const u64*)(wsl + c*C8);
#pragma unroll
        for (int d = 0; d < 16; d++) acc[d] = ffma2(vp, wrow[d], acc[d]);
    }
    float* srow = sred + (slice*64 + px)*33;
#pragma unroll
    for (int d = 0; d < 16; d++) {
        float2 v = unpack2(acc[d]);
        srow[2*d] = v.x; srow[2*d+1] = v.y;
    }
    __syncthreads();

    for (int e = tid; e < 64*C8; e += 256) {
        int p = e >> 5, o = e & 31;
        float v = __ldg(b_proj + o)
                + sred[(0*64+p)*33 + o] + sred[(1*64+p)*33 + o]
                + sred[(2*64+p)*33 + o] + sred[(3*64+p)*33 + o];
        st[p*33 + o] = v;
    }
    __syncthreads();

    if (tid < 64) {
        int p = tid;
        int gpp = g0 + p;
        int bb = gpp >> 12, kk = gpp & (HW-1);
        float v[C8]; float ss = 0.f;
#pragma unroll
        for (int c = 0; c < C8; c++) { v[c] = st[p*33 + c]; ss += v[c]*v[c]; }
        float n = sqrtf(ss);
        float inv = 1.f / fmaxf(n, 1e-12f);
        g_norm[gpp] = n;
        float4* qp = (float4*)(g_q2n + (size_t)gpp*C8);
#pragma unroll
        for (int d = 0; d < 8; d++)
            qp[d] = make_float4(v[d*4+0]*inv, v[d*4+1]*inv, v[d*4+2]*inv, v[d*4+3]*inv);
        float* tb = g_t + (size_t)bb*C8*HW + kk;
#pragma unroll
        for (int c = 0; c < C8; c++) tb[(size_t)c*HW] = v[c];
    }
}

// ================= gram partials =================
__global__ void __launch_bounds__(256) gram_k()
{
    __shared__ float st[32*129];
    const int slab = blockIdx.x, b = blockIdx.y;
    const int tid = threadIdx.x;
    const float* tb = g_t + (size_t)b*C8*HW + slab*128;
    for (int idx = tid; idx < 32*128; idx += 256) {
        int c = idx >> 7, x = idx & 127;
        st[c*129 + x] = tb[(size_t)c*HW + x];
    }
    __syncthreads();

    const int i  = tid >> 3;
    const int j0 = (tid & 7) * 4;
    const float* ri = st + i*129;
    const float* r0 = st + (j0+0)*129;
    const float* r1 = st + (j0+1)*129;
    const float* r2 = st + (j0+2)*129;
    const float* r3 = st + (j0+3)*129;
    float s0=0.f, s1=0.f, s2=0.f, s3=0.f;
#pragma unroll 8
    for (int x = 0; x < 128; x++) {
        float a = ri[x];
        s0 += a*r0[x]; s1 += a*r1[x]; s2 += a*r2[x]; s3 += a*r3[x];
    }
    float* dst = g_pgram + (((size_t)b*32 + slab) << 10) + i*32 + j0;
    dst[0]=s0; dst[1]=s1; dst[2]=s2; dst[3]=s3;
}

// ================= reduce gram + softmax =================
__global__ void __launch_bounds__(1024) chsoft_k()
{
    const int b = blockIdx.x;
    const int tid = threadIdx.x;
    __shared__ float G[1024];
    __shared__ float ninv[32];

    float g = 0.f;
#pragma unroll
    for (int s = 0; s < 32; s++)
        g += g_pgram[(((size_t)b*32 + s) << 10) + tid];
    G[tid] = g;
    if ((tid >> 5) == (tid & 31)) ninv[tid & 31] = 1.f / fmaxf(sqrtf(g), 1e-12f);
    __syncthreads();

    if (tid < 32) {
        int r = tid;
        float ir = ninv[r];
        float row[32]; float s = 0.f;
#pragma unroll
        for (int jj = 0; jj < 32; jj++) {
            float a = G[r*32 + jj] * ir * ninv[jj];
            float p = expf(a - 1.f);
            row[jj] = p; s += p;
        }
        float is = 1.f / s;
        float* dst = g_attn1 + b*C8*C8 + r*32;
#pragma unroll
        for (int jj = 0; jj < 32; jj++) dst[jj] = row[jj] * is;
    }
}

// ================= flash spatial attention, bf16 tensor cores =================
// grid (32 q-tiles of 128, 4 b), block 256 (8 warps x 16 q-rows)
#define SPN 20    // u32 stride per key, [key][dimpair]
#define SPD 68    // u32 stride per dim, [dim][keypair]
#define SPP 68    // u32 stride per P row

__global__ void __launch_bounds__(256, 1) spflash_k()
{
    extern __shared__ uint32_t su[];
    uint32_t* sKnh = su;                     // 128*20
    uint32_t* sKnl = sKnh + 128*SPN;
    uint32_t* sKdh = sKnl + 128*SPN;         // 32*68
    uint32_t* sKdl = sKdh + 32*SPD;
    uint32_t* sP   = sKdl + 32*SPD;          // 8*16*68
    float*    sN   = (float*)(sP + 8*16*SPP);// 128

    const int tid = threadIdx.x;
    const int w = tid >> 5, lane = tid & 31;
    const int gid = lane >> 2, tig = lane & 3;
    const int b = blockIdx.y;
    const int qb = blockIdx.x*128 + w*16;

    // Q A-fragments (bf16 hi/lo), 2 k-chunks of 16 dims
    uint32_t qh[2][4], ql[2][4];
    {
        const float* Q = g_q2n + ((size_t)b*HW + qb)*C8;
#pragma unroll
        for (int ks = 0; ks < 2; ks++)
#pragma unroll
        for (int i = 0; i < 4; i++) {
            int row = gid + (i & 1)*8;
            int dim = ks*16 + 2*tig + ((i & 2) ? 8 : 0);
            float f0 = Q[(size_t)row*32 + dim];
            float f1 = Q[(size_t)row*32 + dim + 1];
            __nv_bfloat16 h0 = __float2bfloat16_rn(f0), h1 = __float2bfloat16_rn(f1);
            __nv_bfloat16 l0 = __float2bfloat16_rn(f0 - __bfloat162float(h0));
            __nv_bfloat16 l1 = __float2bfloat16_rn(f1 - __bfloat162float(h1));
            qh[ks][i] = pkbf(h0, h1);
            ql[ks][i] = pkbf(l0, l1);
        }
    }

    float4 acc_o[4];
#pragma unroll
    for (int n = 0; n < 4; n++) acc_o[n] = make_float4(0.f,0.f,0.f,0.f);
    float l0 = 0.f, l1 = 0.f;
    uint32_t* sPw = sP + w*16*SPP;

    for (int kt = 0; kt < 32; kt++) {
        __syncthreads();
        // ---- stage K tile: bf16 hi/lo in [key][dimpair] and [dim][keypair]
        {
            int key = tid & 127, dh = tid >> 7;
            const float4* src = (const float4*)(g_q2n + ((size_t)b*HW + kt*128 + key)*C8 + dh*16);
            __nv_bfloat16* knh = (__nv_bfloat16*)sKnh;
            __nv_bfloat16* knl = (__nv_bfloat16*)sKnl;
            __nv_bfloat16* kdh = (__nv_bfloat16*)sKdh;
            __nv_bfloat16* kdl = (__nv_bfloat16*)sKdl;
#pragma unroll
            for (int q4 = 0; q4 < 4; q4++) {
                float4 v = src[q4];
                int dim = dh*16 + q4*4;
                float fs[4] = {v.x, v.y, v.z, v.w};
#pragma unroll
                for (int j = 0; j < 4; j++) {
                    __nv_bfloat16 h = __float2bfloat16_rn(fs[j]);
                    __nv_bfloat16 l = __float2bfloat16_rn(fs[j] - __bfloat162float(h));
                    knh[key*(2*SPN) + dim + j] = h;
                    knl[key*(2*SPN) + dim + j] = l;
                    kdh[(dim+j)*(2*SPD) + key] = h;
                    kdl[(dim+j)*(2*SPD) + key] = l;
                }
            }
            if (tid < 128) sN[tid] = g_norm[(size_t)b*HW + kt*128 + tid];
        }
        __syncthreads();

        // ---- S = Q @ K^T (bf16 2-way split), exp, fold norm, pack P (bf16)
#pragma unroll 4
        for (int nt = 0; nt < 16; nt++) {
            float4 s = make_float4(0.f,0.f,0.f,0.f);
            const int key = nt*8 + gid;
#pragma unroll
            for (int ks = 0; ks < 2; ks++) {
                uint32_t bh0 = sKnh[key*SPN + ks*8 + tig];
                uint32_t bh1 = sKnh[key*SPN + ks*8 + tig + 4];
                uint32_t bl0 = sKnl[key*SPN + ks*8 + tig];
                uint32_t bl1 = sKnl[key*SPN + ks*8 + tig + 4];
                mma_bf16(s, qh[ks][0],qh[ks][1],qh[ks][2],qh[ks][3], bh0, bh1);
                mma_bf16(s, qh[ks][0],qh[ks][1],qh[ks][2],qh[ks][3], bl0, bl1);
                mma_bf16(s, ql[ks][0],ql[ks][1],ql[ks][2],ql[ks][3], bh0, bh1);
            }
            float n0 = sN[nt*8 + 2*tig], n1 = sN[nt*8 + 2*tig + 1];
            float e0 = __expf(s.x - 1.f), e1 = __expf(s.y - 1.f);
            float e2 = __expf(s.z - 1.f), e3 = __expf(s.w - 1.f);
            l0 += e0 + e1;
            l1 += e2 + e3;
            sPw[(size_t)gid*SPP     + nt*4 + tig] =
                pkbf(__float2bfloat16_rn(e0*n0), __float2bfloat16_rn(e1*n1));
            sPw[(size_t)(gid+8)*SPP + nt*4 + tig] =
                pkbf(__float2bfloat16_rn(e2*n0), __float2bfloat16_rn(e3*n1));
        }
        __syncwarp();

        // ---- O += P @ V  (V = diag(n)K folded into P; V hi+lo)
#pragma unroll
        for (int ks2 = 0; ks2 < 8; ks2++) {
            uint32_t a0 = sPw[(size_t)gid*SPP     + ks2*8 + tig];
            uint32_t a1 = sPw[(size_t)(gid+8)*SPP + ks2*8 + tig];
            uint32_t a2 = sPw[(size_t)gid*SPP     + ks2*8 + tig + 4];
            uint32_t a3 = sPw[(size_t)(gid+8)*SPP + ks2*8 + tig + 4];
#pragma unroll
            for (int nt2 = 0; nt2 < 4; nt2++) {
                int dimc = nt2*8 + gid;
                uint32_t vh0 = sKdh[dimc*SPD + ks2*8 + tig];
                uint32_t vh1 = sKdh[dimc*SPD + ks2*8 + tig + 4];
                uint32_t vl0 = sKdl[dimc*SPD + ks2*8 + tig];
                uint32_t vl1 = sKdl[dimc*SPD + ks2*8 + tig + 4];
                mma_bf16(acc_o[nt2], a0,a1,a2,a3, vh0, vh1);
                mma_bf16(acc_o[nt2], a0,a1,a2,a3, vl0, vl1);
            }
        }
    }

    l0 += __shfl_xor_sync(0xffffffffu, l0, 1);
    l0 += __shfl_xor_sync(0xffffffffu, l0, 2);
    l1 += __shfl_xor_sync(0xffffffffu, l1, 1);
    l1 += __shfl_xor_sync(0xffffffffu, l1, 2);
    float i0 = 1.f / l0, i1 = 1.f / l1;

    int q0 = qb + gid, q1 = qb + gid + 8;
#pragma unroll
    for (int nt2 = 0; nt2 < 4; nt2++) {
        int d0 = nt2*8 + 2*tig, d1 = d0 + 1;
        g_out3[((size_t)b*C8 + d0)*HW + q0] = acc_o[nt2].x * i0;
        g_out3[((size_t)b*C8 + d1)*HW + q0] = acc_o[nt2].y * i0;
        g_out3[((size_t)b*C8 + d0)*HW + q1] = acc_o[nt2].z * i1;
        g_out3[((size_t)b*C8 + d1)*HW + q1] = acc_o[nt2].w * i1;
    }
}

// ================= final: fused chout + 1x1s =================
__global__ void __launch_bounds__(256, 2) final_k(
    const float* __restrict__ w3, const float* __restrict__ b3,
    const float* __restrict__ w4, const float* __restrict__ b4,
    float* __restrict__ out)
{
    __shared__ float sw3[64*32];
    __shared__ float sw4[Cc*C8];
    __shared__ float sb4[Cc];
    __shared__ float sA[C8*C8];
    __shared__ float so3[64*33];

    const int tid = threadIdx.x;
    const int px = tid & 63, coh = tid >> 6;
    const int g0 = blockIdx.x * 64;
    const int gp = g0 + px;
    const int b = gp >> 12, k = gp & (HW-1);

    for (int idx = tid; idx < 64*32; idx += 256) {
        int j = idx >> 5, o = idx & 31;
        sw3[j*32 + o] = w3[o*64 + j];
    }
    for (int idx = tid; idx < Cc*C8; idx += 256) sw4[idx] = w4[idx];
    if (tid < Cc) sb4[tid] = b4[tid];
    for (int idx = tid; idx < C8*C8; idx += 256) sA[idx] = g_attn1[b*C8*C8 + idx];

    if (coh == 0) {
        const float* o3 = g_out3 + (size_t)b*C8*HW + k;
#pragma unroll
        for (int c = 0; c < C8; c++) so3[px*33 + c] = __ldg(o3 + (size_t)c*HW);
    }
    __syncthreads();

    float tv[C8];
    {
        const float* tb = g_t + (size_t)b*C8*HW + k;
#pragma unroll
        for (int c = 0; c < C8; c++) tv[c] = tb[(size_t)c*HW];
    }
    u64 tvp[16];
#pragma unroll
    for (int d = 0; d < 16; d++) tvp[d] = pack2(tv[2*d], tv[2*d+1]);

    float out2[C8];
#pragma unroll
    for (int i = 0; i < C8; i++) {
        const u64* ar = (const u64*)(sA + i*32);
        u64 s2 = pack2(0.f, 0.f);
#pragma unroll
        for (int d = 0; d < 16; d++) s2 = ffma2(ar[d], tvp[d], s2);
        float2 f = unpack2(s2);
        out2[i] = f.x + f.y;
    }

    u64 o5[16];
#pragma unroll
    for (int d = 0; d < 16; d++)
        o5[d] = pack2(__ldg(b3 + 2*d) + tv[2*d], __ldg(b3 + 2*d+1) + tv[2*d+1]);

#pragma unroll 4
    for (int j = 0; j < 32; j++) {
        u64 vp = pack2(out2[j], out2[j]);
        const u64* wr = (const u64*)(sw3 + j*32);
#pragma unroll
        for (int d = 0; d < 16; d++) o5[d] = ffma2(vp, wr[d], o5[d]);
    }
#pragma unroll 4
    for (int j = 0; j < 32; j++) {
        float v = so3[px*33 + j];
        u64 vp = pack2(v, v);
        const u64* wr = (const u64*)(sw3 + (32+j)*32);
#pragma unroll
        for (int d = 0; d < 16; d++) o5[d] = ffma2(vp, wr[d], o5[d]);
    }

    const int co0 = coh * 64;
    float* dst = out + (size_t)b*Cc*HW + (size_t)co0*HW + k;
#pragma unroll 2
    for (int cc = 0; cc < 64; cc += 2) {
        const u64* w0 = (const u64*)(sw4 + (co0+cc)*C8);
        const u64* w1 = (const u64*)(sw4 + (co0+cc+1)*C8);
        u64 s0 = pack2(0.f, 0.f), s1 = pack2(0.f, 0.f);
#pragma unroll
        for (int d = 0; d < 16; d++) {
            s0 = ffma2(w0[d], o5[d], s0);
            s1 = ffma2(w1[d], o5[d], s1);
        }
        float2 f0 = unpack2(s0), f1 = unpack2(s1);
        dst[(size_t)cc*HW]     = f0.x + f0.y + sb4[co0+cc];
        dst[(size_t)(cc+1)*HW] = f1.x + f1.y + sb4[co0+cc+1];
    }
}

// ================= launch =================
extern "C" void kernel_launch(void* const* d_in, const int* in_sizes, int n_in,
                              void* d_out, int out_size)
{
    const float* x      = (const float*)d_in[0];
    const float* w_conv = (const float*)d_in[1];
    const float* b_conv = (const float*)d_in[2];
    const float* w01 = (const float*)d_in[3];
    const float* b01 = (const float*)d_in[4];
    const float* w02 = (const float*)d_in[5];
    const float* b02 = (const float*)d_in[6];
    const float* w11 = (const float*)d_in[7];
    const float* b11 = (const float*)d_in[8];
    const float* w12 = (const float*)d_in[9];
    const float* b12 = (const float*)d_in[10];
    const float* w21 = (const float*)d_in[11];
    const float* b21 = (const float*)d_in[12];
    const float* w22 = (const float*)d_in[13];
    const float* b22 = (const float*)d_in[14];
    const float* w_proj = (const float*)d_in[15];
    const float* b_proj = (const float*)d_in[16];
    const float* w3 = (const float*)d_in[17];
    const float* b3 = (const float*)d_in[18];
    const float* w4 = (const float*)d_in[19];
    const float* b4 = (const float*)d_in[20];
    float* out = (float*)d_out;

    const int convSmem = (2*SXB_ELEMS + 2*SW_ALL) * (int)sizeof(uint32_t);
    const int spSmem   = (2*128*SPN + 2*32*SPD + 8*16*SPP) * (int)sizeof(uint32_t)
                       + 128 * (int)sizeof(float);
    static bool attrSet = false;
    if (!attrSet) {
        cudaFuncSetAttribute(convmma_k, cudaFuncAttributeMaxDynamicSharedMemorySize, convSmem);
        cudaFuncSetAttribute(spflash_k, cudaFuncAttributeMaxDynamicSharedMemorySize, spSmem);
        attrSet = true;
    }

    wprep_k   <<<9*128*Cc/256, 256>>>(w_conv);
    convmma_k <<<dim3(32, 2, 4), 256, convSmem>>>(x, b_conv);
    dwfused_k <<<Bn*Cc, 256>>>(w01, b01, w02, b02, w11, b11, w12, b12, w21, b21, w22, b22);
    projnorm_k<<<256, 256>>>(w_proj, b_proj);
    gram_k    <<<dim3(32, 4), 256>>>();
    chsoft_k  <<<4, 1024>>>();
    spflash_k <<<dim3(32, 4), 256, spSmem>>>();
    final_k   <<<256, 256>>>(w3, b3, w4, b4, out);
}